// round 3
// baseline (speedup 1.0000x reference)
#include <cuda_runtime.h>
#include <cstdint>

// Problem constants
#define BB     8
#define LL     1024
#define HEADS  4
#define KD     128
#define EMB    512
#define NREL   63

// Scratch (device globals: no allocations allowed)
__device__ float g_q  [BB*LL*EMB];
__device__ float g_k  [BB*LL*EMB];
__device__ float g_v  [BB*LL*EMB];
__device__ float g_ao [BB*LL*EMB];
__device__ float g_rw [BB*HEADS*LL*NREL];
__device__ float g_rh [BB*HEADS*LL*NREL];
__device__ float g_wqt[EMB*EMB];
__device__ float g_wkt[EMB*EMB];
__device__ float g_wvt[EMB*EMB];
__device__ float g_wot[EMB*EMB];

// ---------------------------------------------------------------------------
// Helpers
// ---------------------------------------------------------------------------
__device__ __forceinline__ float tf32_rna(float x) {
    uint32_t h;
    asm("cvt.rna.tf32.f32 %0, %1;" : "=r"(h) : "f"(x));
    return __uint_as_float(h);
}
__device__ __forceinline__ void split2(float x, float& hi, float& lo) {
    hi = tf32_rna(x);
    lo = tf32_rna(x - hi);
}
__device__ __forceinline__ void mma_tf32_16n8k8(float* d, const float4& a, float b0, float b1) {
    asm volatile(
        "mma.sync.aligned.m16n8k8.row.col.f32.tf32.tf32.f32 "
        "{%0,%1,%2,%3}, {%4,%5,%6,%7}, {%8,%9}, {%0,%1,%2,%3};"
        : "+f"(d[0]), "+f"(d[1]), "+f"(d[2]), "+f"(d[3])
        : "r"(__float_as_uint(a.x)), "r"(__float_as_uint(a.y)),
          "r"(__float_as_uint(a.z)), "r"(__float_as_uint(a.w)),
          "r"(__float_as_uint(b0)),  "r"(__float_as_uint(b1)));
}

// ---------------------------------------------------------------------------
// Weight transpose: Wt[n*512+k] = W[k*512+n]
// ---------------------------------------------------------------------------
__global__ void transpose512(const float* __restrict__ W, float* __restrict__ Wt) {
    __shared__ float t[32][33];
    int x = blockIdx.x * 32 + threadIdx.x;
    int y = blockIdx.y * 32 + threadIdx.y;
#pragma unroll
    for (int j = 0; j < 32; j += 8)
        t[threadIdx.y + j][threadIdx.x] = W[(size_t)(y + j) * 512 + x];
    __syncthreads();
    int x2 = blockIdx.y * 32 + threadIdx.x;
    int y2 = blockIdx.x * 32 + threadIdx.y;
#pragma unroll
    for (int j = 0; j < 32; j += 8)
        Wt[(size_t)(y2 + j) * 512 + x2] = t[threadIdx.x][threadIdx.y + j];
}

// ---------------------------------------------------------------------------
// 3xTF32 mma.sync GEMM: C[8192,512] = A[8192,512] @ Wt^T * scale
// (Wt is [N,K] row-major, i.e. the transposed weight.)
// CTA: BM=128, BN=256, BK=32, 512 threads (16 warps, each 32m x 64n).
// Double-buffered smem in FRAGMENT-ORDERED layout:
//   A block (mtile 0..7, ktile 0..3): 256 floats; thread t: hi float4 at
//   blk+t*4 = (a0,a1,a2,a3), lo at blk+128+t*4.
//   B block (ntile 0..31, ktile 0..3): 128 floats; thread t: float4 at
//   blk+t*4 = (b0hi,b1hi,b0lo,b1lo).
// ---------------------------------------------------------------------------
#define ASZ  8192                 // floats per buffer (A)
#define BSZ  16384                // floats per buffer (B)
#define BUFF (ASZ + BSZ)          // 24576 floats
#define GEMM_SMEM (2 * BUFF * 4)  // 196608 bytes

__global__ __launch_bounds__(512) void gemm_mma(const float* __restrict__ A,
                                                const float* __restrict__ Wt,
                                                float* __restrict__ C,
                                                float scale)
{
    extern __shared__ float sm[];
    const int tid  = threadIdx.x;
    const int lane = tid & 31;
    const int wid  = tid >> 5;
    const int wm   = wid & 3;     // 4 m-groups of 32 rows
    const int wn   = wid >> 2;    // 4 n-groups of 64 cols
    const int m0   = blockIdx.y * 128;
    const int n0   = blockIdx.x * 256;

    float4 pa[2], pb[4];

    // ---- load + scatter chunk 0 ----
    {
        const int k0 = 0;
#pragma unroll
        for (int i = 0; i < 2; i++) {
            int idx = tid + i * 512;
            pa[i] = *(const float4*)&A[(size_t)(m0 + (idx >> 3)) * 512 + k0 + (idx & 7) * 4];
        }
#pragma unroll
        for (int i = 0; i < 4; i++) {
            int idx = tid + i * 512;
            pb[i] = *(const float4*)&Wt[(size_t)(n0 + (idx >> 3)) * 512 + k0 + (idx & 7) * 4];
        }
        float* Ab = sm;
        float* Bb = sm + ASZ;
#pragma unroll
        for (int i = 0; i < 2; i++) {
            int idx = tid + i * 512;
            int row = idx >> 3, kq = idx & 7;
            int mt = row >> 4, r16 = row & 15;
            int s = ((r16 >> 3) & 1) | ((kq & 1) << 1);
            int t4 = (r16 & 7) * 4;
            float* base = Ab + (((mt << 2) + (kq >> 1)) << 8) + s;
            float h, l;
            split2(pa[i].x, h, l); base[(t4+0)*4] = h; base[128 + (t4+0)*4] = l;
            split2(pa[i].y, h, l); base[(t4+1)*4] = h; base[128 + (t4+1)*4] = l;
            split2(pa[i].z, h, l); base[(t4+2)*4] = h; base[128 + (t4+2)*4] = l;
            split2(pa[i].w, h, l); base[(t4+3)*4] = h; base[128 + (t4+3)*4] = l;
        }
#pragma unroll
        for (int i = 0; i < 4; i++) {
            int idx = tid + i * 512;
            int n = idx >> 3, kq = idx & 7;
            int slot = kq & 1;
            int t4 = (n & 7) * 4;
            float* base = Bb + ((((n >> 3) << 2) + (kq >> 1)) << 7) + slot;
            float h, l;
            split2(pb[i].x, h, l); base[(t4+0)*4] = h; base[(t4+0)*4 + 2] = l;
            split2(pb[i].y, h, l); base[(t4+1)*4] = h; base[(t4+1)*4 + 2] = l;
            split2(pb[i].z, h, l); base[(t4+2)*4] = h; base[(t4+2)*4 + 2] = l;
            split2(pb[i].w, h, l); base[(t4+3)*4] = h; base[(t4+3)*4 + 2] = l;
        }
    }
    __syncthreads();

    float acc[2][8][4];
#pragma unroll
    for (int mt = 0; mt < 2; mt++)
#pragma unroll
        for (int nt = 0; nt < 8; nt++)
#pragma unroll
            for (int c = 0; c < 4; c++) acc[mt][nt][c] = 0.f;

    for (int c = 0; c < 16; c++) {
        const int p = c & 1;
        float* Ab = sm + p * BUFF;
        float* Bb = Ab + ASZ;

        // prefetch next chunk into registers
        if (c < 15) {
            const int k0 = (c + 1) * 32;
#pragma unroll
            for (int i = 0; i < 2; i++) {
                int idx = tid + i * 512;
                pa[i] = *(const float4*)&A[(size_t)(m0 + (idx >> 3)) * 512 + k0 + (idx & 7) * 4];
            }
#pragma unroll
            for (int i = 0; i < 4; i++) {
                int idx = tid + i * 512;
                pb[i] = *(const float4*)&Wt[(size_t)(n0 + (idx >> 3)) * 512 + k0 + (idx & 7) * 4];
            }
        }

        // MMA over the 4 k8 slices of this chunk
#pragma unroll
        for (int kt = 0; kt < 4; kt++) {
            float4 ahi[2], alo[2];
#pragma unroll
            for (int mt = 0; mt < 2; mt++) {
                int blk = ((((wm * 2 + mt) << 2) + kt) << 8);
                ahi[mt] = *(float4*)&Ab[blk + lane * 4];
                alo[mt] = *(float4*)&Ab[blk + 128 + lane * 4];
            }
#pragma unroll
            for (int nt = 0; nt < 8; nt++) {
                int blk = ((((wn * 8 + nt) << 2) + kt) << 7);
                float4 bv = *(float4*)&Bb[blk + lane * 4];
#pragma unroll
                for (int mt = 0; mt < 2; mt++) {
                    mma_tf32_16n8k8(acc[mt][nt], ahi[mt], bv.x, bv.y);
                    mma_tf32_16n8k8(acc[mt][nt], alo[mt], bv.x, bv.y);
                    mma_tf32_16n8k8(acc[mt][nt], ahi[mt], bv.z, bv.w);
                }
            }
        }

        // scatter prefetched chunk into the other buffer
        if (c < 15) {
            float* Ab2 = sm + (p ^ 1) * BUFF;
            float* Bb2 = Ab2 + ASZ;
#pragma unroll
            for (int i = 0; i < 2; i++) {
                int idx = tid + i * 512;
                int row = idx >> 3, kq = idx & 7;
                int mt = row >> 4, r16 = row & 15;
                int s = ((r16 >> 3) & 1) | ((kq & 1) << 1);
                int t4 = (r16 & 7) * 4;
                float* base = Ab2 + (((mt << 2) + (kq >> 1)) << 8) + s;
                float h, l;
                split2(pa[i].x, h, l); base[(t4+0)*4] = h; base[128 + (t4+0)*4] = l;
                split2(pa[i].y, h, l); base[(t4+1)*4] = h; base[128 + (t4+1)*4] = l;
                split2(pa[i].z, h, l); base[(t4+2)*4] = h; base[128 + (t4+2)*4] = l;
                split2(pa[i].w, h, l); base[(t4+3)*4] = h; base[128 + (t4+3)*4] = l;
            }
#pragma unroll
            for (int i = 0; i < 4; i++) {
                int idx = tid + i * 512;
                int n = idx >> 3, kq = idx & 7;
                int slot = kq & 1;
                int t4 = (n & 7) * 4;
                float* base = Bb2 + ((((n >> 3) << 2) + (kq >> 1)) << 7) + slot;
                float h, l;
                split2(pb[i].x, h, l); base[(t4+0)*4] = h; base[(t4+0)*4 + 2] = l;
                split2(pb[i].y, h, l); base[(t4+1)*4] = h; base[(t4+1)*4 + 2] = l;
                split2(pb[i].z, h, l); base[(t4+2)*4] = h; base[(t4+2)*4 + 2] = l;
                split2(pb[i].w, h, l); base[(t4+3)*4] = h; base[(t4+3)*4 + 2] = l;
            }
        }
        __syncthreads();
    }

    // epilogue
#pragma unroll
    for (int mt = 0; mt < 2; mt++) {
        int row = m0 + wm * 32 + mt * 16 + (lane >> 2);
#pragma unroll
        for (int nt = 0; nt < 8; nt++) {
            int col = n0 + wn * 64 + nt * 8 + (lane & 3) * 2;
            float2 o0 = make_float2(acc[mt][nt][0] * scale, acc[mt][nt][1] * scale);
            float2 o1 = make_float2(acc[mt][nt][2] * scale, acc[mt][nt][3] * scale);
            *(float2*)&C[(size_t)row * 512 + col]       = o0;
            *(float2*)&C[(size_t)(row + 8) * 512 + col] = o1;
        }
    }
}

// ---------------------------------------------------------------------------
// Relative-position logits (unchanged from R1)
// ---------------------------------------------------------------------------
#define RELPOS_SMEM ((8192 + 8192 + 64 * 132) * 4)

__global__ __launch_bounds__(256) void relpos(const float* __restrict__ q,
                                              const float* __restrict__ pew,
                                              const float* __restrict__ peh,
                                              float* __restrict__ rw,
                                              float* __restrict__ rh)
{
    extern __shared__ float smf[];
    float* pw = smf;
    float* ph = smf + 8192;
    float* qs = smf + 16384;

    const int tid = threadIdx.x;
    const int tx  = tid & 15;
    const int ty  = tid >> 4;

    for (int i = tid; i < 8192; i += 256) {
        int d = i >> 6, r = i & 63;
        float vw = 0.f, vh = 0.f;
        if (r < NREL) { vw = pew[d * NREL + r]; vh = peh[d * NREL + r]; }
        pw[i] = vw;
        ph[i] = vh;
    }

    const int gr0 = blockIdx.x * 64;
    for (int idx = tid; idx < 2048; idx += 256) {
        int i = idx >> 5, d4 = idx & 31;
        int gr = gr0 + i;
        int b = gr >> 12, h = (gr >> 10) & 3, l = gr & 1023;
        ((float4*)qs)[i * 33 + d4] =
            *(const float4*)&q[(size_t)((b << 10) + l) * 512 + (h << 7) + (d4 << 2)];
    }
    __syncthreads();

    float aw[4][4], ah[4][4];
#pragma unroll
    for (int i = 0; i < 4; i++)
#pragma unroll
        for (int j = 0; j < 4; j++) { aw[i][j] = 0.f; ah[i][j] = 0.f; }

#pragma unroll 4
    for (int d = 0; d < 128; d++) {
        float bw[4], bh[4], a[4];
        *(float4*)bw = *(const float4*)&pw[(d << 6) + tx * 4];
        *(float4*)bh = *(const float4*)&ph[(d << 6) + tx * 4];
#pragma unroll
        for (int i = 0; i < 4; i++) a[i] = qs[(ty * 4 + i) * 132 + d];
#pragma unroll
        for (int i = 0; i < 4; i++)
#pragma unroll
            for (int c = 0; c < 4; c++) {
                aw[i][c] += a[i] * bw[c];
                ah[i][c] += a[i] * bh[c];
            }
    }

#pragma unroll
    for (int i = 0; i < 4; i++) {
        int gr = gr0 + ty * 4 + i;
#pragma unroll
        for (int c = 0; c < 4; c++) {
            int r = tx * 4 + c;
            if (r < NREL) {
                rw[(size_t)gr * NREL + r] = aw[i][c];
                rh[(size_t)gr * NREL + r] = ah[i][c];
            }
        }
    }
}

// ---------------------------------------------------------------------------
// Flash attention (unchanged from R1)
// ---------------------------------------------------------------------------
#define Q_OFF   0
#define K_OFF   8448
#define V_OFF   16896
#define S_OFF   25344
#define RW_OFF  29504
#define RH_OFF  33536
#define ATTN_SMEM ((33536 + 4032) * 4)

__global__ __launch_bounds__(256) void attn(const float* __restrict__ q,
                                            const float* __restrict__ k,
                                            const float* __restrict__ v,
                                            const float* __restrict__ rw,
                                            const float* __restrict__ rh,
                                            float* __restrict__ aout)
{
    extern __shared__ float smf[];
    float* Qs  = smf + Q_OFF;
    float* Ks  = smf + K_OFF;
    float* Vs  = smf + V_OFF;
    float* Ss  = smf + S_OFF;
    float* RWs = smf + RW_OFF;
    float* RHs = smf + RH_OFF;

    const int tid = threadIdx.x;
    const int tx  = tid & 15;
    const int ty  = tid >> 4;
    const int qt  = blockIdx.x;
    const int h   = blockIdx.y;
    const int b   = blockIdx.z;
    const int qbase = qt * 64;

    const float* qg = q + (size_t)((b << 10) + qbase) * 512 + (h << 7);
    for (int idx = tid; idx < 2048; idx += 256) {
        int i = idx >> 5, d4 = idx & 31;
        ((float4*)Qs)[i * 33 + d4] = *(const float4*)&qg[(size_t)i * 512 + (d4 << 2)];
    }
    const float* RWg = rw + (size_t)(((b << 2) + h) * 1024 + qbase) * NREL;
    const float* RHg = rh + (size_t)(((b << 2) + h) * 1024 + qbase) * NREL;
    for (int i = tid; i < 64 * NREL; i += 256) { RWs[i] = RWg[i]; RHs[i] = RHg[i]; }

    float m_i[4], l_i[4], O[4][8];
    int yq[4], xq[4];
#pragma unroll
    for (int ii = 0; ii < 4; ii++) {
        m_i[ii] = -1e30f;
        l_i[ii] = 0.f;
        int lq = qbase + ty * 4 + ii;
        yq[ii] = lq >> 5;
        xq[ii] = lq & 31;
#pragma unroll
        for (int c = 0; c < 8; c++) O[ii][c] = 0.f;
    }

    for (int kt = 0; kt < 16; kt++) {
        const int kbase = kt * 64;
        __syncthreads();
        const float* kg = k + (size_t)((b << 10) + kbase) * 512 + (h << 7);
        const float* vg = v + (size_t)((b << 10) + kbase) * 512 + (h << 7);
        for (int idx = tid; idx < 2048; idx += 256) {
            int i = idx >> 5, d4 = idx & 31;
            ((float4*)Ks)[i * 33 + d4] = *(const float4*)&kg[(size_t)i * 512 + (d4 << 2)];
            ((float4*)Vs)[i * 33 + d4] = *(const float4*)&vg[(size_t)i * 512 + (d4 << 2)];
        }
        __syncthreads();

        float s[4][4];
#pragma unroll
        for (int i = 0; i < 4; i++)
#pragma unroll
            for (int j = 0; j < 4; j++) s[i][j] = 0.f;

        const float4* Q4 = (const float4*)Qs;
        const float4* K4 = (const float4*)Ks;
#pragma unroll 4
        for (int d4 = 0; d4 < 32; d4++) {
            float a[4][4], bb[4][4];
#pragma unroll
            for (int i = 0; i < 4; i++)
                *(float4*)a[i] = Q4[(ty * 4 + i) * 33 + d4];
#pragma unroll
            for (int j = 0; j < 4; j++)
                *(float4*)bb[j] = K4[(tx + (j << 4)) * 33 + d4];
#pragma unroll
            for (int i = 0; i < 4; i++)
#pragma unroll
                for (int j = 0; j < 4; j++)
#pragma unroll
                    for (int c = 0; c < 4; c++) s[i][j] += a[i][c] * bb[j][c];
        }

#pragma unroll
        for (int ii = 0; ii < 4; ii++) {
            const float* rwrow = &RWs[(ty * 4 + ii) * NREL];
            const float* rhrow = &RHs[(ty * 4 + ii) * NREL];
            float mx = -1e30f;
#pragma unroll
            for (int jj = 0; jj < 4; jj++) {
                int lk = kbase + tx + (jj << 4);
                int yk = lk >> 5, xk = lk & 31;
                s[ii][jj] += rwrow[xk - xq[ii] + 31] + rhrow[yk - yq[ii] + 31];
                mx = fmaxf(mx, s[ii][jj]);
            }
            mx = fmaxf(mx, __shfl_xor_sync(0xffffffffu, mx, 8));
            mx = fmaxf(mx, __shfl_xor_sync(0xffffffffu, mx, 4));
            mx = fmaxf(mx, __shfl_xor_sync(0xffffffffu, mx, 2));
            mx = fmaxf(mx, __shfl_xor_sync(0xffffffffu, mx, 1));
            float mnew  = fmaxf(m_i[ii], mx);
            float alpha = __expf(m_i[ii] - mnew);
            float ps = 0.f;
#pragma unroll
            for (int jj = 0; jj < 4; jj++) {
                float p = __expf(s[ii][jj] - mnew);
                Ss[(ty * 4 + ii) * 65 + tx + (jj << 4)] = p;
                ps += p;
            }
            ps += __shfl_xor_sync(0xffffffffu, ps, 8);
            ps += __shfl_xor_sync(0xffffffffu, ps, 4);
            ps += __shfl_xor_sync(0xffffffffu, ps, 2);
            ps += __shfl_xor_sync(0xffffffffu, ps, 1);
            l_i[ii] = l_i[ii] * alpha + ps;
            m_i[ii] = mnew;
#pragma unroll
            for (int c = 0; c < 8; c++) O[ii][c] *= alpha;
        }
        __syncthreads();

        const float4* V4 = (const float4*)Vs;
#pragma unroll 2
        for (int j = 0; j < 64; j++) {
            float vv[8];
            *(float4*)&vv[0] = V4[j * 33 + (tx << 1)];
            *(float4*)&vv[4] = V4[j * 33 + (tx << 1) + 1];
            float pp[4];
#pragma unroll
            for (int ii = 0; ii < 4; ii++) pp[ii] = Ss[(ty * 4 + ii) * 65 + j];
#pragma unroll
            for (int ii = 0; ii < 4; ii++)
#pragma unroll
                for (int c = 0; c < 8; c++) O[ii][c] += pp[ii] * vv[c];
        }
    }

    float* og = aout + (size_t)((b << 10) + qbase) * 512 + (h << 7);
#pragma unroll
    for (int ii = 0; ii < 4; ii++) {
        float inv = 1.0f / l_i[ii];
        float4 o0 = make_float4(O[ii][0]*inv, O[ii][1]*inv, O[ii][2]*inv, O[ii][3]*inv);
        float4 o1 = make_float4(O[ii][4]*inv, O[ii][5]*inv, O[ii][6]*inv, O[ii][7]*inv);
        size_t base = (size_t)(ty * 4 + ii) * 512 + (tx << 3);
        *(float4*)&og[base]     = o0;
        *(float4*)&og[base + 4] = o1;
    }
}

// ---------------------------------------------------------------------------
extern "C" void kernel_launch(void* const* d_in, const int* in_sizes, int n_in,
                              void* d_out, int out_size)
{
    const float* x   = (const float*)d_in[0];
    const float* Wq  = (const float*)d_in[1];
    const float* Wk  = (const float*)d_in[2];
    const float* Wv  = (const float*)d_in[3];
    const float* Wo  = (const float*)d_in[4];
    const float* pew = (const float*)d_in[5];
    const float* peh = (const float*)d_in[6];
    float* out = (float*)d_out;

    float *qp, *kp, *vp, *aop, *rwp, *rhp, *wqt, *wkt, *wvt, *wot;
    cudaGetSymbolAddress((void**)&qp,  g_q);
    cudaGetSymbolAddress((void**)&kp,  g_k);
    cudaGetSymbolAddress((void**)&vp,  g_v);
    cudaGetSymbolAddress((void**)&aop, g_ao);
    cudaGetSymbolAddress((void**)&rwp, g_rw);
    cudaGetSymbolAddress((void**)&rhp, g_rh);
    cudaGetSymbolAddress((void**)&wqt, g_wqt);
    cudaGetSymbolAddress((void**)&wkt, g_wkt);
    cudaGetSymbolAddress((void**)&wvt, g_wvt);
    cudaGetSymbolAddress((void**)&wot, g_wot);

    cudaFuncSetAttribute(gemm_mma, cudaFuncAttributeMaxDynamicSharedMemorySize, GEMM_SMEM);
    cudaFuncSetAttribute(relpos,   cudaFuncAttributeMaxDynamicSharedMemorySize, RELPOS_SMEM);
    cudaFuncSetAttribute(attn,     cudaFuncAttributeMaxDynamicSharedMemorySize, ATTN_SMEM);

    dim3 tg(16, 16), tb(32, 8);
    transpose512<<<tg, tb>>>(Wq, wqt);
    transpose512<<<tg, tb>>>(Wk, wkt);
    transpose512<<<tg, tb>>>(Wv, wvt);
    transpose512<<<tg, tb>>>(Wo, wot);

    const float scale = 0.08838834764831845f;   // 1/sqrt(128)
    dim3 gg(2, 64);
    gemm_mma<<<gg, 512, GEMM_SMEM>>>(x, wqt, qp, scale);
    gemm_mma<<<gg, 512, GEMM_SMEM>>>(x, wkt, kp, 1.0f);
    gemm_mma<<<gg, 512, GEMM_SMEM>>>(x, wvt, vp, 1.0f);
    relpos<<<512, 256, RELPOS_SMEM>>>(qp, pew, peh, rwp, rhp);
    attn<<<dim3(16, 4, 8), 256, ATTN_SMEM>>>(qp, kp, vp, rwp, rhp, aop);
    gemm_mma<<<gg, 512, GEMM_SMEM>>>(aop, wot, out, 1.0f);
}

// round 4
// speedup vs baseline: 2.2711x; 2.2711x over previous
#include <cuda_runtime.h>
#include <cuda_bf16.h>
#include <cstdint>

// Problem constants
#define BB     8
#define LL     1024
#define HEADS  4
#define KD     128
#define EMB    512
#define NREL   63

// ---------------------------------------------------------------------------
// Device-global scratch (no allocations allowed)
// ---------------------------------------------------------------------------
__device__ float          g_q  [BB*LL*EMB];          // fp32 q (relpos input)
__device__ float          g_v  [BB*LL*EMB];          // fp32 v (transpose input)
__device__ float          g_S  [32*1024*1024];       // scores
__device__ float          g_rw [BB*HEADS*LL*NREL];
__device__ float          g_rh [BB*HEADS*LL*NREL];
__device__ __nv_bfloat16  g_xh [BB*LL*EMB], g_xl [BB*LL*EMB];
__device__ __nv_bfloat16  g_qh [BB*LL*EMB], g_ql [BB*LL*EMB];
__device__ __nv_bfloat16  g_kh [BB*LL*EMB], g_kl [BB*LL*EMB];
__device__ __nv_bfloat16  g_vth[32*128*1024], g_vtl[32*128*1024];
__device__ __nv_bfloat16  g_ph [32*1024*1024], g_pl [32*1024*1024];
__device__ __nv_bfloat16  g_aoh[BB*LL*EMB], g_aol[BB*LL*EMB];
__device__ __nv_bfloat16  g_wqh[EMB*EMB], g_wql[EMB*EMB];
__device__ __nv_bfloat16  g_wkh[EMB*EMB], g_wkl[EMB*EMB];
__device__ __nv_bfloat16  g_wvh[EMB*EMB], g_wvl[EMB*EMB];
__device__ __nv_bfloat16  g_woh[EMB*EMB], g_wol[EMB*EMB];

// ---------------------------------------------------------------------------
// PTX helpers
// ---------------------------------------------------------------------------
__device__ __forceinline__ uint32_t smem_u32(const void* p) {
    uint32_t a;
    asm("{ .reg .u64 t; cvta.to.shared.u64 t, %1; cvt.u32.u64 %0, t; }" : "=r"(a) : "l"(p));
    return a;
}
__device__ __forceinline__ void ldsm4(uint32_t addr, uint32_t* r) {
    asm volatile("ldmatrix.sync.aligned.m8n8.x4.shared.b16 {%0,%1,%2,%3}, [%4];"
                 : "=r"(r[0]), "=r"(r[1]), "=r"(r[2]), "=r"(r[3]) : "r"(addr));
}
__device__ __forceinline__ void mma_bf16(float* d, const uint32_t* a, uint32_t b0, uint32_t b1) {
    asm volatile("mma.sync.aligned.m16n8k16.row.col.f32.bf16.bf16.f32 "
                 "{%0,%1,%2,%3}, {%4,%5,%6,%7}, {%8,%9}, {%0,%1,%2,%3};"
                 : "+f"(d[0]), "+f"(d[1]), "+f"(d[2]), "+f"(d[3])
                 : "r"(a[0]), "r"(a[1]), "r"(a[2]), "r"(a[3]), "r"(b0), "r"(b1));
}
#define CP_ASYNC(dst, src) asm volatile("cp.async.ca.shared.global [%0], [%1], 16;" :: "r"(dst), "l"(src))
#define CP_COMMIT()        asm volatile("cp.async.commit_group;" ::: "memory")
#define CP_WAIT1()         asm volatile("cp.async.wait_group 1;" ::: "memory")

__device__ __forceinline__ void bsplit(float x, __nv_bfloat16& h, __nv_bfloat16& l) {
    h = __float2bfloat16_rn(x);
    l = __float2bfloat16_rn(x - __bfloat162float(h));
}

// ---------------------------------------------------------------------------
// bf16-split pipelined mma GEMM:  C = (Ahi+Alo) @ (Bhi+Blo)^T * scale [+bias]
// A: [rows, K] K-contiguous (lda), B: [cols, K] K-contiguous (ldb).
// CTA: 128x128 tile, BK=32, 256 threads (8 warps: wm=wid>>1 [4], wn=wid&1 [2];
// warp tile 32m x 64n). 3-stage cp.async pipeline.
// smem stage = 4 tiles (Ahi,Alo,Bhi,Blo) of 128 rows x 80B pitch (32 bf16 + pad).
// Batch offsets: off = (z>>2)*str1 + (z&3)*str2 for A, B, C.
// ---------------------------------------------------------------------------
#define STG_BYTES 40960
#define TILE_P    10240
#define GEMM_SMEM (3 * STG_BYTES)

template<bool BIAS, bool SPLIT, bool WF32>
__global__ __launch_bounds__(256) void gemm_bs(
    const __nv_bfloat16* __restrict__ Ahi, const __nv_bfloat16* __restrict__ Alo,
    int lda, long long strA1, long long strA2,
    const __nv_bfloat16* __restrict__ Bhi, const __nv_bfloat16* __restrict__ Blo,
    int ldb, long long strB1, long long strB2,
    float* __restrict__ Cf, __nv_bfloat16* __restrict__ Chi, __nv_bfloat16* __restrict__ Clo,
    int ldc, long long strC1, long long strC2,
    const float* __restrict__ rw, const float* __restrict__ rh,
    int kIters, float scale)
{
    extern __shared__ char smem[];
    const uint32_t sb0 = smem_u32(smem);
    const int tid  = threadIdx.x;
    const int lane = tid & 31;
    const int wid  = tid >> 5;
    const int wm   = wid >> 1;
    const int wn   = wid & 1;
    const int n0   = blockIdx.x * 128;
    const int m0   = blockIdx.y * 128;
    const int z    = blockIdx.z;

    const size_t offA = (size_t)(z >> 2) * strA1 + (size_t)(z & 3) * strA2;
    const size_t offB = (size_t)(z >> 2) * strB1 + (size_t)(z & 3) * strB2;
    const size_t offC = (size_t)(z >> 2) * strC1 + (size_t)(z & 3) * strC2;

    const __nv_bfloat16* aH = Ahi + offA + (size_t)m0 * lda;
    const __nv_bfloat16* aL = Alo + offA + (size_t)m0 * lda;
    const __nv_bfloat16* bH = Bhi + offB + (size_t)n0 * ldb;
    const __nv_bfloat16* bL = Blo + offB + (size_t)n0 * ldb;

    // cp.async issue for chunk c into stage stg
    const int r0i = (tid * 2) >> 2;        // two ops per tile per thread
    const int c0i = (tid * 2) & 3;
    auto issue = [&](int c, int stg) {
        const uint32_t sb = sb0 + stg * STG_BYTES;
        const int k0 = c * 32;
#pragma unroll
        for (int i = 0; i < 2; i++) {
            int o  = tid + i * 256;        // 0..511
            int r  = o >> 2;
            int ch = o & 3;
            uint32_t d = sb + r * 80 + ch * 16;
            const __nv_bfloat16* s;
            s = aH + (size_t)r * lda + k0 + ch * 8; CP_ASYNC(d,              s);
            s = aL + (size_t)r * lda + k0 + ch * 8; CP_ASYNC(d + TILE_P,     s);
            s = bH + (size_t)r * ldb + k0 + ch * 8; CP_ASYNC(d + 2*TILE_P,   s);
            s = bL + (size_t)r * ldb + k0 + ch * 8; CP_ASYNC(d + 3*TILE_P,   s);
        }
        CP_COMMIT();
    };
    (void)r0i; (void)c0i;

    issue(0, 0);
    issue(1, 1);

    float acc[2][8][4];
#pragma unroll
    for (int mt = 0; mt < 2; mt++)
#pragma unroll
        for (int nt = 0; nt < 8; nt++)
#pragma unroll
            for (int e = 0; e < 4; e++) acc[mt][nt][e] = 0.f;

    for (int c = 0; c < kIters; c++) {
        CP_WAIT1();
        __syncthreads();
        if (c + 2 < kIters) issue(c + 2, (c + 2) % 3);

        const uint32_t sb = sb0 + (c % 3) * STG_BYTES;
#pragma unroll
        for (int s = 0; s < 2; s++) {
            uint32_t ahf[2][4], alf[2][4];
#pragma unroll
            for (int mt = 0; mt < 2; mt++) {
                uint32_t addr = sb + (uint32_t)((wm * 32 + mt * 16 + (lane & 15)) * 80)
                                   + (uint32_t)((s * 2 + (lane >> 4)) << 4);
                ldsm4(addr,          ahf[mt]);
                ldsm4(addr + TILE_P, alf[mt]);
            }
            uint32_t bhf[4][4], blf[4][4];
#pragma unroll
            for (int ng = 0; ng < 4; ng++) {
                int row = wn * 64 + ng * 16 + ((lane >> 4) << 3) + (lane & 7);
                uint32_t addr = sb + 2 * TILE_P + (uint32_t)(row * 80)
                                   + (uint32_t)((s * 2 + ((lane >> 3) & 1)) << 4);
                ldsm4(addr,          bhf[ng]);
                ldsm4(addr + TILE_P, blf[ng]);
            }
#pragma unroll
            for (int mt = 0; mt < 2; mt++)
#pragma unroll
                for (int nt = 0; nt < 8; nt++) {
                    int ng = nt >> 1, o = (nt & 1) * 2;
                    mma_bf16(acc[mt][nt], ahf[mt], bhf[ng][o], bhf[ng][o + 1]);
                    mma_bf16(acc[mt][nt], ahf[mt], blf[ng][o], blf[ng][o + 1]);
                    mma_bf16(acc[mt][nt], alf[mt], bhf[ng][o], bhf[ng][o + 1]);
                }
        }
    }

    // ---- epilogue ----
    const int rr  = lane >> 2;
    const int cp2 = (lane & 3) * 2;
    float*         Cfb = WF32  ? (Cf  + offC) : nullptr;
    __nv_bfloat16* Chb = SPLIT ? (Chi + offC) : nullptr;
    __nv_bfloat16* Clb = SPLIT ? (Clo + offC) : nullptr;
    const float* rwb = BIAS ? (rw + (size_t)z * (1024 * NREL)) : nullptr;
    const float* rhb = BIAS ? (rh + (size_t)z * (1024 * NREL)) : nullptr;

#pragma unroll
    for (int mt = 0; mt < 2; mt++) {
        int row0 = m0 + wm * 32 + mt * 16 + rr;
        int row1 = row0 + 8;
#pragma unroll
        for (int nt = 0; nt < 8; nt++) {
            int col = n0 + wn * 64 + nt * 8 + cp2;
            float v0 = acc[mt][nt][0] * scale;
            float v1 = acc[mt][nt][1] * scale;
            float v2 = acc[mt][nt][2] * scale;
            float v3 = acc[mt][nt][3] * scale;
            if (BIAS) {
                int x0a = row0 & 31, y0a = row0 >> 5;
                int x0b = row1 & 31, y0b = row1 >> 5;
                int xk0 = col & 31,  yk0 = col >> 5;
                int xk1 = (col + 1) & 31, yk1 = (col + 1) >> 5;
                v0 += rwb[row0 * NREL + xk0 - x0a + 31] + rhb[row0 * NREL + yk0 - y0a + 31];
                v1 += rwb[row0 * NREL + xk1 - x0a + 31] + rhb[row0 * NREL + yk1 - y0a + 31];
                v2 += rwb[row1 * NREL + xk0 - x0b + 31] + rhb[row1 * NREL + yk0 - y0b + 31];
                v3 += rwb[row1 * NREL + xk1 - x0b + 31] + rhb[row1 * NREL + yk1 - y0b + 31];
            }
            if (WF32) {
                *(float2*)&Cfb[(size_t)row0 * ldc + col] = make_float2(v0, v1);
                *(float2*)&Cfb[(size_t)row1 * ldc + col] = make_float2(v2, v3);
            }
            if (SPLIT) {
                __nv_bfloat16 h0, l0, h1, l1;
                bsplit(v0, h0, l0); bsplit(v1, h1, l1);
                *(__nv_bfloat162*)&Chb[(size_t)row0 * ldc + col] = __nv_bfloat162(h0, h1);
                *(__nv_bfloat162*)&Clb[(size_t)row0 * ldc + col] = __nv_bfloat162(l0, l1);
                bsplit(v2, h0, l0); bsplit(v3, h1, l1);
                *(__nv_bfloat162*)&Chb[(size_t)row1 * ldc + col] = __nv_bfloat162(h0, h1);
                *(__nv_bfloat162*)&Clb[(size_t)row1 * ldc + col] = __nv_bfloat162(l0, l1);
            }
        }
    }
}

// ---------------------------------------------------------------------------
// x -> bf16 hi/lo split (elementwise)
// ---------------------------------------------------------------------------
__global__ __launch_bounds__(256) void splitx(const float* __restrict__ x,
                                              __nv_bfloat16* __restrict__ xh,
                                              __nv_bfloat16* __restrict__ xl, int n4)
{
    for (int i = blockIdx.x * 256 + threadIdx.x; i < n4; i += gridDim.x * 256) {
        float4 v = ((const float4*)x)[i];
        __nv_bfloat16 h0,l0,h1,l1,h2,l2,h3,l3;
        bsplit(v.x,h0,l0); bsplit(v.y,h1,l1); bsplit(v.z,h2,l2); bsplit(v.w,h3,l3);
        ((__nv_bfloat162*)xh)[i*2]   = __nv_bfloat162(h0,h1);
        ((__nv_bfloat162*)xh)[i*2+1] = __nv_bfloat162(h2,h3);
        ((__nv_bfloat162*)xl)[i*2]   = __nv_bfloat162(l0,l1);
        ((__nv_bfloat162*)xl)[i*2+1] = __nv_bfloat162(l2,l3);
    }
}

// ---------------------------------------------------------------------------
// Weight transpose + split: Wt[n*512+k] = split(W[k*512+n])
// ---------------------------------------------------------------------------
__global__ void tsplit(const float* __restrict__ W,
                       __nv_bfloat16* __restrict__ th, __nv_bfloat16* __restrict__ tl)
{
    __shared__ float t[32][33];
    int x = blockIdx.x * 32 + threadIdx.x;
    int y = blockIdx.y * 32 + threadIdx.y;
#pragma unroll
    for (int j = 0; j < 32; j += 8)
        t[threadIdx.y + j][threadIdx.x] = W[(size_t)(y + j) * 512 + x];
    __syncthreads();
    int x2 = blockIdx.y * 32 + threadIdx.x;
    int y2 = blockIdx.x * 32 + threadIdx.y;
#pragma unroll
    for (int j = 0; j < 32; j += 8) {
        float val = t[threadIdx.x][threadIdx.y + j];
        __nv_bfloat16 h, l;
        bsplit(val, h, l);
        size_t o = (size_t)(y2 + j) * 512 + x2;
        th[o] = h; tl[o] = l;
    }
}

// ---------------------------------------------------------------------------
// V transpose + split: v[b, l, h*128+d] -> vt[(b*4+h), d, l] hi/lo
// ---------------------------------------------------------------------------
__global__ void vtrans(const float* __restrict__ v,
                       __nv_bfloat16* __restrict__ vth, __nv_bfloat16* __restrict__ vtl)
{
    __shared__ float t[32][33];
    int z = blockIdx.z, b = z >> 2, h = z & 3;
    int l0 = blockIdx.x * 32, d0 = blockIdx.y * 32;
#pragma unroll
    for (int j = 0; j < 32; j += 8)
        t[threadIdx.y + j][threadIdx.x] =
            v[(size_t)(b * 1024 + l0 + threadIdx.y + j) * 512 + h * 128 + d0 + threadIdx.x];
    __syncthreads();
#pragma unroll
    for (int j = 0; j < 32; j += 8) {
        int d = d0 + threadIdx.y + j;
        float val = t[threadIdx.x][threadIdx.y + j];
        __nv_bfloat16 hh, ll;
        bsplit(val, hh, ll);
        size_t o = (size_t)z * 131072 + (size_t)d * 1024 + l0 + threadIdx.x;
        vth[o] = hh; vtl[o] = ll;
    }
}

// ---------------------------------------------------------------------------
// Row softmax: S[32768,1024] fp32 -> normalized P as bf16 hi/lo. 1 warp/row.
// ---------------------------------------------------------------------------
__global__ __launch_bounds__(256) void softmax_rows(const float* __restrict__ S,
                                                    __nv_bfloat16* __restrict__ ph,
                                                    __nv_bfloat16* __restrict__ pl)
{
    int row  = blockIdx.x * 8 + (threadIdx.x >> 5);
    int lane = threadIdx.x & 31;
    const float* sr = S + (size_t)row * 1024;

    float v[32];
    float mx = -1e30f;
#pragma unroll
    for (int i = 0; i < 8; i++) {
        float4 t = ((const float4*)sr)[i * 32 + lane];
        v[i*4+0] = t.x; v[i*4+1] = t.y; v[i*4+2] = t.z; v[i*4+3] = t.w;
        mx = fmaxf(mx, fmaxf(fmaxf(t.x, t.y), fmaxf(t.z, t.w)));
    }
#pragma unroll
    for (int s = 16; s > 0; s >>= 1) mx = fmaxf(mx, __shfl_xor_sync(0xffffffffu, mx, s));
    float sum = 0.f;
#pragma unroll
    for (int i = 0; i < 32; i++) { v[i] = __expf(v[i] - mx); sum += v[i]; }
#pragma unroll
    for (int s = 16; s > 0; s >>= 1) sum += __shfl_xor_sync(0xffffffffu, sum, s);
    float inv = 1.0f / sum;
#pragma unroll
    for (int i = 0; i < 8; i++) {
        __nv_bfloat16 h0,l0,h1,l1,h2,l2,h3,l3;
        bsplit(v[i*4+0]*inv, h0,l0); bsplit(v[i*4+1]*inv, h1,l1);
        bsplit(v[i*4+2]*inv, h2,l2); bsplit(v[i*4+3]*inv, h3,l3);
        size_t o = (size_t)row * 1024 + (size_t)(i * 32 + lane) * 4;
        *(__nv_bfloat162*)&ph[o]   = __nv_bfloat162(h0,h1);
        *(__nv_bfloat162*)&ph[o+2] = __nv_bfloat162(h2,h3);
        *(__nv_bfloat162*)&pl[o]   = __nv_bfloat162(l0,l1);
        *(__nv_bfloat162*)&pl[o+2] = __nv_bfloat162(l2,l3);
    }
}

// ---------------------------------------------------------------------------
// Relative-position logits (FFMA, unchanged)
// ---------------------------------------------------------------------------
#define RELPOS_SMEM ((8192 + 8192 + 64 * 132) * 4)

__global__ __launch_bounds__(256) void relpos(const float* __restrict__ q,
                                              const float* __restrict__ pew,
                                              const float* __restrict__ peh,
                                              float* __restrict__ rw,
                                              float* __restrict__ rh)
{
    extern __shared__ float smf[];
    float* pw = smf;
    float* ph = smf + 8192;
    float* qs = smf + 16384;

    const int tid = threadIdx.x;
    const int tx  = tid & 15;
    const int ty  = tid >> 4;

    for (int i = tid; i < 8192; i += 256) {
        int d = i >> 6, r = i & 63;
        float vw = 0.f, vh = 0.f;
        if (r < NREL) { vw = pew[d * NREL + r]; vh = peh[d * NREL + r]; }
        pw[i] = vw;
        ph[i] = vh;
    }

    const int gr0 = blockIdx.x * 64;
    for (int idx = tid; idx < 2048; idx += 256) {
        int i = idx >> 5, d4 = idx & 31;
        int gr = gr0 + i;
        int b = gr >> 12, h = (gr >> 10) & 3, l = gr & 1023;
        ((float4*)qs)[i * 33 + d4] =
            *(const float4*)&q[(size_t)((b << 10) + l) * 512 + (h << 7) + (d4 << 2)];
    }
    __syncthreads();

    float aw[4][4], ah[4][4];
#pragma unroll
    for (int i = 0; i < 4; i++)
#pragma unroll
        for (int j = 0; j < 4; j++) { aw[i][j] = 0.f; ah[i][j] = 0.f; }

#pragma unroll 4
    for (int d = 0; d < 128; d++) {
        float bw[4], bh[4], a[4];
        *(float4*)bw = *(const float4*)&pw[(d << 6) + tx * 4];
        *(float4*)bh = *(const float4*)&ph[(d << 6) + tx * 4];
#pragma unroll
        for (int i = 0; i < 4; i++) a[i] = qs[(ty * 4 + i) * 132 + d];
#pragma unroll
        for (int i = 0; i < 4; i++)
#pragma unroll
            for (int c = 0; c < 4; c++) {
                aw[i][c] += a[i] * bw[c];
                ah[i][c] += a[i] * bh[c];
            }
    }

#pragma unroll
    for (int i = 0; i < 4; i++) {
        int gr = gr0 + ty * 4 + i;
#pragma unroll
        for (int c = 0; c < 4; c++) {
            int r = tx * 4 + c;
            if (r < NREL) {
                rw[(size_t)gr * NREL + r] = aw[i][c];
                rh[(size_t)gr * NREL + r] = ah[i][c];
            }
        }
    }
}

// ---------------------------------------------------------------------------
extern "C" void kernel_launch(void* const* d_in, const int* in_sizes, int n_in,
                              void* d_out, int out_size)
{
    const float* x   = (const float*)d_in[0];
    const float* Wq  = (const float*)d_in[1];
    const float* Wk  = (const float*)d_in[2];
    const float* Wv  = (const float*)d_in[3];
    const float* Wo  = (const float*)d_in[4];
    const float* pew = (const float*)d_in[5];
    const float* peh = (const float*)d_in[6];
    float* out = (float*)d_out;

    float *qp, *vp, *Sp, *rwp, *rhp;
    __nv_bfloat16 *xh,*xl,*qh,*ql,*kh,*kl,*vth,*vtl,*ph2,*pl2,*aoh,*aol;
    __nv_bfloat16 *wqh,*wql,*wkh,*wkl,*wvh,*wvl,*woh,*wol;
    cudaGetSymbolAddress((void**)&qp,  g_q);
    cudaGetSymbolAddress((void**)&vp,  g_v);
    cudaGetSymbolAddress((void**)&Sp,  g_S);
    cudaGetSymbolAddress((void**)&rwp, g_rw);
    cudaGetSymbolAddress((void**)&rhp, g_rh);
    cudaGetSymbolAddress((void**)&xh,  g_xh);  cudaGetSymbolAddress((void**)&xl,  g_xl);
    cudaGetSymbolAddress((void**)&qh,  g_qh);  cudaGetSymbolAddress((void**)&ql,  g_ql);
    cudaGetSymbolAddress((void**)&kh,  g_kh);  cudaGetSymbolAddress((void**)&kl,  g_kl);
    cudaGetSymbolAddress((void**)&vth, g_vth); cudaGetSymbolAddress((void**)&vtl, g_vtl);
    cudaGetSymbolAddress((void**)&ph2, g_ph);  cudaGetSymbolAddress((void**)&pl2, g_pl);
    cudaGetSymbolAddress((void**)&aoh, g_aoh); cudaGetSymbolAddress((void**)&aol, g_aol);
    cudaGetSymbolAddress((void**)&wqh, g_wqh); cudaGetSymbolAddress((void**)&wql, g_wql);
    cudaGetSymbolAddress((void**)&wkh, g_wkh); cudaGetSymbolAddress((void**)&wkl, g_wkl);
    cudaGetSymbolAddress((void**)&wvh, g_wvh); cudaGetSymbolAddress((void**)&wvl, g_wvl);
    cudaGetSymbolAddress((void**)&woh, g_woh); cudaGetSymbolAddress((void**)&wol, g_wol);

    cudaFuncSetAttribute(gemm_bs<false,true ,true >, cudaFuncAttributeMaxDynamicSharedMemorySize, GEMM_SMEM);
    cudaFuncSetAttribute(gemm_bs<false,true ,false>, cudaFuncAttributeMaxDynamicSharedMemorySize, GEMM_SMEM);
    cudaFuncSetAttribute(gemm_bs<false,false,true >, cudaFuncAttributeMaxDynamicSharedMemorySize, GEMM_SMEM);
    cudaFuncSetAttribute(gemm_bs<true ,false,true >, cudaFuncAttributeMaxDynamicSharedMemorySize, GEMM_SMEM);
    cudaFuncSetAttribute(relpos, cudaFuncAttributeMaxDynamicSharedMemorySize, RELPOS_SMEM);

    const float scale = 0.08838834764831845f;   // 1/sqrt(128)

    // 1. split x
    splitx<<<1024, 256>>>(x, xh, xl, 8192*512/4);
    // 2. transpose+split weights
    dim3 tg(16, 16), tb(32, 8);
    tsplit<<<tg, tb>>>(Wq, wqh, wql);
    tsplit<<<tg, tb>>>(Wk, wkh, wkl);
    tsplit<<<tg, tb>>>(Wv, wvh, wvl);
    tsplit<<<tg, tb>>>(Wo, woh, wol);
    // 3. projections
    dim3 pg(4, 64, 1);
    gemm_bs<false,true ,true ><<<pg, 256, GEMM_SMEM>>>(xh, xl, 512, 0, 0, wqh, wql, 512, 0, 0,
        qp, qh, ql, 512, 0, 0, nullptr, nullptr, 16, scale);
    gemm_bs<false,true ,false><<<pg, 256, GEMM_SMEM>>>(xh, xl, 512, 0, 0, wkh, wkl, 512, 0, 0,
        nullptr, kh, kl, 512, 0, 0, nullptr, nullptr, 16, 1.0f);
    gemm_bs<false,false,true ><<<pg, 256, GEMM_SMEM>>>(xh, xl, 512, 0, 0, wvh, wvl, 512, 0, 0,
        vp, nullptr, nullptr, 512, 0, 0, nullptr, nullptr, 16, 1.0f);
    // 4. V transpose+split
    vtrans<<<dim3(32, 4, 32), dim3(32, 8)>>>(vp, vth, vtl);
    // 5. relative-position tables
    relpos<<<512, 256, RELPOS_SMEM>>>(qp, pew, peh, rwp, rhp);
    // 6. S = QK^T + bias   (batched over z = b*4+h)
    gemm_bs<true ,false,true ><<<dim3(8, 8, 32), 256, GEMM_SMEM>>>(
        qh, ql, 512, 524288LL, 128LL,
        kh, kl, 512, 524288LL, 128LL,
        Sp, nullptr, nullptr, 1024, 4194304LL, 1048576LL,
        rwp, rhp, 4, 1.0f);
    // 7. softmax rows -> P hi/lo
    softmax_rows<<<4096, 256>>>(Sp, ph2, pl2);
    // 8. O = P @ V^T  (batched)
    gemm_bs<false,true ,false><<<dim3(1, 8, 32), 256, GEMM_SMEM>>>(
        ph2, pl2, 1024, 4194304LL, 1048576LL,
        vth, vtl, 1024, 524288LL, 131072LL,
        nullptr, aoh, aol, 512, 524288LL, 128LL,
        nullptr, nullptr, 32, 1.0f);
    // 9. final projection
    gemm_bs<false,false,true ><<<pg, 256, GEMM_SMEM>>>(aoh, aol, 512, 0, 0, woh, wol, 512, 0, 0,
        out, nullptr, nullptr, 512, 0, 0, nullptr, nullptr, 16, 1.0f);
}

// round 5
// speedup vs baseline: 2.6430x; 1.1638x over previous
#include <cuda_runtime.h>
#include <cuda_bf16.h>
#include <cstdint>

// Problem constants
#define BB     8
#define LL     1024
#define HEADS  4
#define KD     128
#define EMB    512
#define NREL   63

// ---------------------------------------------------------------------------
// Device-global scratch (no allocations allowed)
// ---------------------------------------------------------------------------
__device__ float          g_q  [BB*LL*EMB];          // fp32 q (relpos input)
__device__ float          g_v  [BB*LL*EMB];          // fp32 v (transpose input)
__device__ float          g_rw [BB*HEADS*LL*NREL];
__device__ float          g_rh [BB*HEADS*LL*NREL];
__device__ __nv_bfloat16  g_xh [BB*LL*EMB], g_xl [BB*LL*EMB];
__device__ __nv_bfloat16  g_qh [BB*LL*EMB], g_ql [BB*LL*EMB];
__device__ __nv_bfloat16  g_kh [BB*LL*EMB], g_kl [BB*LL*EMB];
__device__ __nv_bfloat16  g_vth[32*128*1024], g_vtl[32*128*1024];
__device__ __nv_bfloat16  g_aoh[BB*LL*EMB], g_aol[BB*LL*EMB];
__device__ __nv_bfloat16  g_wqh[EMB*EMB], g_wql[EMB*EMB];
__device__ __nv_bfloat16  g_wkh[EMB*EMB], g_wkl[EMB*EMB];
__device__ __nv_bfloat16  g_wvh[EMB*EMB], g_wvl[EMB*EMB];
__device__ __nv_bfloat16  g_woh[EMB*EMB], g_wol[EMB*EMB];

// ---------------------------------------------------------------------------
// PTX helpers
// ---------------------------------------------------------------------------
__device__ __forceinline__ uint32_t smem_u32(const void* p) {
    uint32_t a;
    asm("{ .reg .u64 t; cvta.to.shared.u64 t, %1; cvt.u32.u64 %0, t; }" : "=r"(a) : "l"(p));
    return a;
}
__device__ __forceinline__ void ldsm4(uint32_t addr, uint32_t* r) {
    asm volatile("ldmatrix.sync.aligned.m8n8.x4.shared.b16 {%0,%1,%2,%3}, [%4];"
                 : "=r"(r[0]), "=r"(r[1]), "=r"(r[2]), "=r"(r[3]) : "r"(addr));
}
__device__ __forceinline__ void mma_bf16(float* d, const uint32_t* a, uint32_t b0, uint32_t b1) {
    asm volatile("mma.sync.aligned.m16n8k16.row.col.f32.bf16.bf16.f32 "
                 "{%0,%1,%2,%3}, {%4,%5,%6,%7}, {%8,%9}, {%0,%1,%2,%3};"
                 : "+f"(d[0]), "+f"(d[1]), "+f"(d[2]), "+f"(d[3])
                 : "r"(a[0]), "r"(a[1]), "r"(a[2]), "r"(a[3]), "r"(b0), "r"(b1));
}
#define CP_ASYNC(dst, src) asm volatile("cp.async.ca.shared.global [%0], [%1], 16;" :: "r"(dst), "l"(src))
#define CP_COMMIT()        asm volatile("cp.async.commit_group;" ::: "memory")
#define CP_WAIT1()         asm volatile("cp.async.wait_group 1;" ::: "memory")
#define CP_WAIT0()         asm volatile("cp.async.wait_group 0;" ::: "memory")

__device__ __forceinline__ void bsplit(float x, __nv_bfloat16& h, __nv_bfloat16& l) {
    h = __float2bfloat16_rn(x);
    l = __float2bfloat16_rn(x - __bfloat162float(h));
}
__device__ __forceinline__ uint32_t packbf(__nv_bfloat16 a, __nv_bfloat16 b) {
    __nv_bfloat162 t(a, b);
    return *(uint32_t*)&t;
}

// ---------------------------------------------------------------------------
// bf16-split pipelined mma GEMM (projections): C = (Ahi+Alo)@(Bhi+Blo)^T*scale
// ---------------------------------------------------------------------------
#define STG_BYTES 40960
#define TILE_P    10240
#define GEMM_SMEM (3 * STG_BYTES)

template<bool SPLIT, bool WF32>
__global__ __launch_bounds__(256) void gemm_bs(
    const __nv_bfloat16* __restrict__ Ahi, const __nv_bfloat16* __restrict__ Alo,
    const __nv_bfloat16* __restrict__ Bhi, const __nv_bfloat16* __restrict__ Blo,
    float* __restrict__ Cf, __nv_bfloat16* __restrict__ Chi, __nv_bfloat16* __restrict__ Clo,
    int kIters, float scale)
{
    extern __shared__ char smem[];
    const uint32_t sb0 = smem_u32(smem);
    const int tid  = threadIdx.x;
    const int lane = tid & 31;
    const int wid  = tid >> 5;
    const int wm   = wid >> 1;
    const int wn   = wid & 1;
    const int n0   = blockIdx.x * 128;
    const int m0   = blockIdx.y * 128;
    const int lda = 512, ldb = 512, ldc = 512;

    const __nv_bfloat16* aH = Ahi + (size_t)m0 * lda;
    const __nv_bfloat16* aL = Alo + (size_t)m0 * lda;
    const __nv_bfloat16* bH = Bhi + (size_t)n0 * ldb;
    const __nv_bfloat16* bL = Blo + (size_t)n0 * ldb;

    auto issue = [&](int c, int stg) {
        const uint32_t sb = sb0 + stg * STG_BYTES;
        const int k0 = c * 32;
#pragma unroll
        for (int i = 0; i < 2; i++) {
            int o  = tid + i * 256;
            int r  = o >> 2;
            int ch = o & 3;
            uint32_t d = sb + r * 80 + ch * 16;
            const __nv_bfloat16* s;
            s = aH + (size_t)r * lda + k0 + ch * 8; CP_ASYNC(d,            s);
            s = aL + (size_t)r * lda + k0 + ch * 8; CP_ASYNC(d + TILE_P,   s);
            s = bH + (size_t)r * ldb + k0 + ch * 8; CP_ASYNC(d + 2*TILE_P, s);
            s = bL + (size_t)r * ldb + k0 + ch * 8; CP_ASYNC(d + 3*TILE_P, s);
        }
        CP_COMMIT();
    };

    issue(0, 0);
    issue(1, 1);

    float acc[2][8][4];
#pragma unroll
    for (int mt = 0; mt < 2; mt++)
#pragma unroll
        for (int nt = 0; nt < 8; nt++)
#pragma unroll
            for (int e = 0; e < 4; e++) acc[mt][nt][e] = 0.f;

    for (int c = 0; c < kIters; c++) {
        CP_WAIT1();
        __syncthreads();
        if (c + 2 < kIters) issue(c + 2, (c + 2) % 3);

        const uint32_t sb = sb0 + (c % 3) * STG_BYTES;
#pragma unroll
        for (int s = 0; s < 2; s++) {
            uint32_t ahf[2][4], alf[2][4];
#pragma unroll
            for (int mt = 0; mt < 2; mt++) {
                uint32_t addr = sb + (uint32_t)((wm * 32 + mt * 16 + (lane & 15)) * 80)
                                   + (uint32_t)((s * 2 + (lane >> 4)) << 4);
                ldsm4(addr,          ahf[mt]);
                ldsm4(addr + TILE_P, alf[mt]);
            }
            uint32_t bhf[4][4], blf[4][4];
#pragma unroll
            for (int ng = 0; ng < 4; ng++) {
                int row = wn * 64 + ng * 16 + ((lane >> 4) << 3) + (lane & 7);
                uint32_t addr = sb + 2 * TILE_P + (uint32_t)(row * 80)
                                   + (uint32_t)((s * 2 + ((lane >> 3) & 1)) << 4);
                ldsm4(addr,          bhf[ng]);
                ldsm4(addr + TILE_P, blf[ng]);
            }
#pragma unroll
            for (int mt = 0; mt < 2; mt++)
#pragma unroll
                for (int nt = 0; nt < 8; nt++) {
                    int ng = nt >> 1, o = (nt & 1) * 2;
                    mma_bf16(acc[mt][nt], ahf[mt], bhf[ng][o], bhf[ng][o + 1]);
                    mma_bf16(acc[mt][nt], ahf[mt], blf[ng][o], blf[ng][o + 1]);
                    mma_bf16(acc[mt][nt], alf[mt], bhf[ng][o], bhf[ng][o + 1]);
                }
        }
    }

    const int rr  = lane >> 2;
    const int cp2 = (lane & 3) * 2;
#pragma unroll
    for (int mt = 0; mt < 2; mt++) {
        int row0 = m0 + wm * 32 + mt * 16 + rr;
        int row1 = row0 + 8;
#pragma unroll
        for (int nt = 0; nt < 8; nt++) {
            int col = n0 + wn * 64 + nt * 8 + cp2;
            float v0 = acc[mt][nt][0] * scale;
            float v1 = acc[mt][nt][1] * scale;
            float v2 = acc[mt][nt][2] * scale;
            float v3 = acc[mt][nt][3] * scale;
            if (WF32) {
                *(float2*)&Cf[(size_t)row0 * ldc + col] = make_float2(v0, v1);
                *(float2*)&Cf[(size_t)row1 * ldc + col] = make_float2(v2, v3);
            }
            if (SPLIT) {
                __nv_bfloat16 h0, l0, h1, l1;
                bsplit(v0, h0, l0); bsplit(v1, h1, l1);
                *(__nv_bfloat162*)&Chi[(size_t)row0 * ldc + col] = __nv_bfloat162(h0, h1);
                *(__nv_bfloat162*)&Clo[(size_t)row0 * ldc + col] = __nv_bfloat162(l0, l1);
                bsplit(v2, h0, l0); bsplit(v3, h1, l1);
                *(__nv_bfloat162*)&Chi[(size_t)row1 * ldc + col] = __nv_bfloat162(h0, h1);
                *(__nv_bfloat162*)&Clo[(size_t)row1 * ldc + col] = __nv_bfloat162(l0, l1);
            }
        }
    }
}

// ---------------------------------------------------------------------------
// Fused flash attention with decomposed relative-position bias.
// CTA = (qtile 0..7, z = b*4+h). 128 q-rows x 64-key window x 16 iters.
// 8 warps x 16 q-rows. bf16-split mma for QK^T and PV; fp32 online softmax.
// ---------------------------------------------------------------------------
#define FL_QH 0
#define FL_QL 34816
#define FL_KH 69632
#define FL_KL 87040
#define FL_VH 104448
#define FL_VL 122880
#define FL_RW 141312                      // float[128][65]
#define FL_RH (141312 + 33280)
#define FLASH_SMEM (141312 + 2 * 33280)   // 207872

__global__ __launch_bounds__(256) void flash(
    const __nv_bfloat16* __restrict__ qh, const __nv_bfloat16* __restrict__ ql,
    const __nv_bfloat16* __restrict__ kh, const __nv_bfloat16* __restrict__ kl,
    const __nv_bfloat16* __restrict__ vth, const __nv_bfloat16* __restrict__ vtl,
    const float* __restrict__ rw, const float* __restrict__ rh,
    __nv_bfloat16* __restrict__ aoh, __nv_bfloat16* __restrict__ aol)
{
    extern __shared__ char smem[];
    const uint32_t sb = smem_u32(smem);
    float* rwS = (float*)(smem + FL_RW);
    float* rhS = (float*)(smem + FL_RH);

    const int tid  = threadIdx.x;
    const int lane = tid & 31;
    const int w    = tid >> 5;
    const int z    = blockIdx.z;
    const int b    = z >> 2;
    const int hh   = z & 3;
    const int qbase = blockIdx.x * 128;

    // ---- Q tiles (hi/lo) via cp.async ----
#pragma unroll
    for (int t = 0; t < 8; t++) {
        int idx = tid + t * 256;
        int r = idx >> 4, c = idx & 15;
        size_t g = (size_t)((b << 10) + qbase + r) * 512 + hh * 128 + c * 8;
        CP_ASYNC(sb + FL_QH + r * 272 + c * 16, qh + g);
        CP_ASYNC(sb + FL_QL + r * 272 + c * 16, ql + g);
    }
    CP_COMMIT();

    // ---- bias tables ----
    for (int i = tid; i < 128 * 64; i += 256) {
        int r = i >> 6, c = i & 63;
        float vw = 0.f, vb = 0.f;
        if (c < NREL) {
            size_t g = ((size_t)z * 1024 + qbase + r) * NREL + c;
            vw = rw[g]; vb = rh[g];
        }
        rwS[r * 65 + c] = vw;
        rhS[r * 65 + c] = vb;
    }

    const int r0 = w * 16 + (lane >> 2);
    const int r1 = r0 + 8;
    const int lq0 = qbase + r0, lq1 = qbase + r1;
    const int xq0 = lq0 & 31, yq0 = lq0 >> 5;
    const int xq1 = lq1 & 31, yq1 = lq1 >> 5;
    const float L2E = 1.4426950408889634f;

    float m0 = -1e30f, m1 = -1e30f, l0 = 0.f, l1 = 0.f;
    float O[16][4];
#pragma unroll
    for (int d = 0; d < 16; d++)
#pragma unroll
        for (int e = 0; e < 4; e++) O[d][e] = 0.f;

    for (int it = 0; it < 16; it++) {
        const int kb = it * 64;
        if (it > 0) __syncthreads();     // previous iter done with K/V smem

        // K tile: 64 rows x 128 d (hi/lo)
#pragma unroll
        for (int t = 0; t < 4; t++) {
            int idx = tid + t * 256;
            int r = idx >> 4, c = idx & 15;
            size_t g = (size_t)((b << 10) + kb + r) * 512 + hh * 128 + c * 8;
            CP_ASYNC(sb + FL_KH + r * 272 + c * 16, kh + g);
            CP_ASYNC(sb + FL_KL + r * 272 + c * 16, kl + g);
        }
        // V^T tile: 128 d-rows x 64 l (hi/lo)
#pragma unroll
        for (int t = 0; t < 4; t++) {
            int idx = tid + t * 256;
            int d = idx >> 3, c = idx & 7;
            size_t g = (size_t)z * 131072 + (size_t)d * 1024 + kb + c * 8;
            CP_ASYNC(sb + FL_VH + d * 144 + c * 16, vth + g);
            CP_ASYNC(sb + FL_VL + d * 144 + c * 16, vtl + g);
        }
        CP_COMMIT();
        CP_WAIT0();
        __syncthreads();

        // ---- S = Q K^T  (16 rows x 64 cols per warp) ----
        float s[8][4];
#pragma unroll
        for (int nt = 0; nt < 8; nt++)
#pragma unroll
            for (int e = 0; e < 4; e++) s[nt][e] = 0.f;

#pragma unroll
        for (int ks = 0; ks < 8; ks++) {
            uint32_t qhf[4], qlf[4];
            uint32_t addrA = sb + FL_QH + (uint32_t)((w * 16 + (lane & 15)) * 272)
                               + (uint32_t)(ks * 32 + (lane >> 4) * 16);
            ldsm4(addrA,                 qhf);
            ldsm4(addrA + (FL_QL - FL_QH), qlf);
            uint32_t bhf[4][4], blf[4][4];
#pragma unroll
            for (int ng = 0; ng < 4; ng++) {
                int row = ng * 16 + ((lane >> 4) << 3) + (lane & 7);
                uint32_t addrB = sb + FL_KH + (uint32_t)(row * 272)
                                   + (uint32_t)(ks * 32 + ((lane >> 3) & 1) * 16);
                ldsm4(addrB,                 bhf[ng]);
                ldsm4(addrB + (FL_KL - FL_KH), blf[ng]);
            }
#pragma unroll
            for (int nt = 0; nt < 8; nt++) {
                int ng = nt >> 1, o = (nt & 1) * 2;
                mma_bf16(s[nt], qhf, bhf[ng][o], bhf[ng][o + 1]);
                mma_bf16(s[nt], qhf, blf[ng][o], blf[ng][o + 1]);
                mma_bf16(s[nt], qlf, bhf[ng][o], bhf[ng][o + 1]);
            }
        }

        // ---- bias + online softmax ----
        float mx0 = m0, mx1 = m1;
#pragma unroll
        for (int nt = 0; nt < 8; nt++) {
            int c0 = kb + nt * 8 + (lane & 3) * 2;
            int c1 = c0 + 1;
            int xk0 = c0 & 31, yk0 = (c0 >> 5) & 31;
            int xk1 = c1 & 31, yk1 = (c1 >> 5) & 31;
            s[nt][0] += rwS[r0 * 65 + xk0 - xq0 + 31] + rhS[r0 * 65 + yk0 - yq0 + 31];
            s[nt][1] += rwS[r0 * 65 + xk1 - xq0 + 31] + rhS[r0 * 65 + yk1 - yq0 + 31];
            s[nt][2] += rwS[r1 * 65 + xk0 - xq1 + 31] + rhS[r1 * 65 + yk0 - yq1 + 31];
            s[nt][3] += rwS[r1 * 65 + xk1 - xq1 + 31] + rhS[r1 * 65 + yk1 - yq1 + 31];
            mx0 = fmaxf(mx0, fmaxf(s[nt][0], s[nt][1]));
            mx1 = fmaxf(mx1, fmaxf(s[nt][2], s[nt][3]));
        }
        mx0 = fmaxf(mx0, __shfl_xor_sync(0xffffffffu, mx0, 1));
        mx0 = fmaxf(mx0, __shfl_xor_sync(0xffffffffu, mx0, 2));
        mx1 = fmaxf(mx1, __shfl_xor_sync(0xffffffffu, mx1, 1));
        mx1 = fmaxf(mx1, __shfl_xor_sync(0xffffffffu, mx1, 2));

        float a0 = exp2f((m0 - mx0) * L2E);
        float a1 = exp2f((m1 - mx1) * L2E);
        m0 = mx0; m1 = mx1;

        float s0 = 0.f, s1 = 0.f;
#pragma unroll
        for (int nt = 0; nt < 8; nt++) {
            s[nt][0] = exp2f((s[nt][0] - m0) * L2E);
            s[nt][1] = exp2f((s[nt][1] - m0) * L2E);
            s[nt][2] = exp2f((s[nt][2] - m1) * L2E);
            s[nt][3] = exp2f((s[nt][3] - m1) * L2E);
            s0 += s[nt][0] + s[nt][1];
            s1 += s[nt][2] + s[nt][3];
        }
        s0 += __shfl_xor_sync(0xffffffffu, s0, 1);
        s0 += __shfl_xor_sync(0xffffffffu, s0, 2);
        s1 += __shfl_xor_sync(0xffffffffu, s1, 1);
        s1 += __shfl_xor_sync(0xffffffffu, s1, 2);
        l0 = l0 * a0 + s0;
        l1 = l1 * a1 + s1;

#pragma unroll
        for (int d = 0; d < 16; d++) {
            O[d][0] *= a0; O[d][1] *= a0;
            O[d][2] *= a1; O[d][3] *= a1;
        }

        // ---- O += P V^T ----
#pragma unroll
        for (int ks = 0; ks < 4; ks++) {
            // pack P fragments (C-layout -> A-layout), hi and lo
            uint32_t pah[4], pal[4];
            {
                __nv_bfloat16 h00,l00,h01,l01,h02,l02,h03,l03;
                __nv_bfloat16 h10,l10,h11,l11,h12,l12,h13,l13;
                bsplit(s[2*ks][0],   h00, l00); bsplit(s[2*ks][1],   h01, l01);
                bsplit(s[2*ks][2],   h02, l02); bsplit(s[2*ks][3],   h03, l03);
                bsplit(s[2*ks+1][0], h10, l10); bsplit(s[2*ks+1][1], h11, l11);
                bsplit(s[2*ks+1][2], h12, l12); bsplit(s[2*ks+1][3], h13, l13);
                pah[0] = packbf(h00, h01); pah[1] = packbf(h02, h03);
                pah[2] = packbf(h10, h11); pah[3] = packbf(h12, h13);
                pal[0] = packbf(l00, l01); pal[1] = packbf(l02, l03);
                pal[2] = packbf(l10, l11); pal[3] = packbf(l12, l13);
            }
#pragma unroll
            for (int dg = 0; dg < 8; dg++) {
                int row = dg * 16 + ((lane >> 4) << 3) + (lane & 7);
                uint32_t addrV = sb + FL_VH + (uint32_t)(row * 144)
                                   + (uint32_t)(ks * 32 + ((lane >> 3) & 1) * 16);
                uint32_t vhf[4], vlf[4];
                ldsm4(addrV,                 vhf);
                ldsm4(addrV + (FL_VL - FL_VH), vlf);
#pragma unroll
                for (int hf = 0; hf < 2; hf++) {
                    int dnt = dg * 2 + hf, o = hf * 2;
                    mma_bf16(O[dnt], pah, vhf[o], vhf[o + 1]);
                    mma_bf16(O[dnt], pah, vlf[o], vlf[o + 1]);
                    mma_bf16(O[dnt], pal, vhf[o], vhf[o + 1]);
                }
            }
        }
    }

    // ---- normalize + store split bf16 ----
    float inv0 = 1.0f / l0, inv1 = 1.0f / l1;
    size_t row0g = (size_t)((b << 10) + lq0) * 512 + hh * 128;
    size_t row1g = (size_t)((b << 10) + lq1) * 512 + hh * 128;
#pragma unroll
    for (int d = 0; d < 16; d++) {
        int col = d * 8 + (lane & 3) * 2;
        __nv_bfloat16 h0, lo0, h1, lo1;
        bsplit(O[d][0] * inv0, h0, lo0); bsplit(O[d][1] * inv0, h1, lo1);
        *(__nv_bfloat162*)&aoh[row0g + col] = __nv_bfloat162(h0, h1);
        *(__nv_bfloat162*)&aol[row0g + col] = __nv_bfloat162(lo0, lo1);
        bsplit(O[d][2] * inv1, h0, lo0); bsplit(O[d][3] * inv1, h1, lo1);
        *(__nv_bfloat162*)&aoh[row1g + col] = __nv_bfloat162(h0, h1);
        *(__nv_bfloat162*)&aol[row1g + col] = __nv_bfloat162(lo0, lo1);
    }
}

// ---------------------------------------------------------------------------
// x -> bf16 hi/lo split
// ---------------------------------------------------------------------------
__global__ __launch_bounds__(256) void splitx(const float* __restrict__ x,
                                              __nv_bfloat16* __restrict__ xh,
                                              __nv_bfloat16* __restrict__ xl, int n4)
{
    for (int i = blockIdx.x * 256 + threadIdx.x; i < n4; i += gridDim.x * 256) {
        float4 v = ((const float4*)x)[i];
        __nv_bfloat16 h0,l0,h1,l1,h2,l2,h3,l3;
        bsplit(v.x,h0,l0); bsplit(v.y,h1,l1); bsplit(v.z,h2,l2); bsplit(v.w,h3,l3);
        ((__nv_bfloat162*)xh)[i*2]   = __nv_bfloat162(h0,h1);
        ((__nv_bfloat162*)xh)[i*2+1] = __nv_bfloat162(h2,h3);
        ((__nv_bfloat162*)xl)[i*2]   = __nv_bfloat162(l0,l1);
        ((__nv_bfloat162*)xl)[i*2+1] = __nv_bfloat162(l2,l3);
    }
}

// ---------------------------------------------------------------------------
// Weight transpose + split
// ---------------------------------------------------------------------------
__global__ void tsplit(const float* __restrict__ W,
                       __nv_bfloat16* __restrict__ th, __nv_bfloat16* __restrict__ tl)
{
    __shared__ float t[32][33];
    int x = blockIdx.x * 32 + threadIdx.x;
    int y = blockIdx.y * 32 + threadIdx.y;
#pragma unroll
    for (int j = 0; j < 32; j += 8)
        t[threadIdx.y + j][threadIdx.x] = W[(size_t)(y + j) * 512 + x];
    __syncthreads();
    int x2 = blockIdx.y * 32 + threadIdx.x;
    int y2 = blockIdx.x * 32 + threadIdx.y;
#pragma unroll
    for (int j = 0; j < 32; j += 8) {
        float val = t[threadIdx.x][threadIdx.y + j];
        __nv_bfloat16 h, l;
        bsplit(val, h, l);
        size_t o = (size_t)(y2 + j) * 512 + x2;
        th[o] = h; tl[o] = l;
    }
}

// ---------------------------------------------------------------------------
// V transpose + split: v[b,l,h*128+d] -> vt[(b*4+h), d, l] hi/lo
// ---------------------------------------------------------------------------
__global__ void vtrans(const float* __restrict__ v,
                       __nv_bfloat16* __restrict__ vth, __nv_bfloat16* __restrict__ vtl)
{
    __shared__ float t[32][33];
    int z = blockIdx.z, b = z >> 2, h = z & 3;
    int l0 = blockIdx.x * 32, d0 = blockIdx.y * 32;
#pragma unroll
    for (int j = 0; j < 32; j += 8)
        t[threadIdx.y + j][threadIdx.x] =
            v[(size_t)(b * 1024 + l0 + threadIdx.y + j) * 512 + h * 128 + d0 + threadIdx.x];
    __syncthreads();
#pragma unroll
    for (int j = 0; j < 32; j += 8) {
        int d = d0 + threadIdx.y + j;
        float val = t[threadIdx.x][threadIdx.y + j];
        __nv_bfloat16 hh, ll;
        bsplit(val, hh, ll);
        size_t o = (size_t)z * 131072 + (size_t)d * 1024 + l0 + threadIdx.x;
        vth[o] = hh; vtl[o] = ll;
    }
}

// ---------------------------------------------------------------------------
// Relative-position logits (FFMA)
// ---------------------------------------------------------------------------
#define RELPOS_SMEM ((8192 + 8192 + 64 * 132) * 4)

__global__ __launch_bounds__(256) void relpos(const float* __restrict__ q,
                                              const float* __restrict__ pew,
                                              const float* __restrict__ peh,
                                              float* __restrict__ rw,
                                              float* __restrict__ rh)
{
    extern __shared__ float smf[];
    float* pw = smf;
    float* ph = smf + 8192;
    float* qs = smf + 16384;

    const int tid = threadIdx.x;
    const int tx  = tid & 15;
    const int ty  = tid >> 4;

    for (int i = tid; i < 8192; i += 256) {
        int d = i >> 6, r = i & 63;
        float vw = 0.f, vh = 0.f;
        if (r < NREL) { vw = pew[d * NREL + r]; vh = peh[d * NREL + r]; }
        pw[i] = vw;
        ph[i] = vh;
    }

    const int gr0 = blockIdx.x * 64;
    for (int idx = tid; idx < 2048; idx += 256) {
        int i = idx >> 5, d4 = idx & 31;
        int gr = gr0 + i;
        int b = gr >> 12, h = (gr >> 10) & 3, l = gr & 1023;
        ((float4*)qs)[i * 33 + d4] =
            *(const float4*)&q[(size_t)((b << 10) + l) * 512 + (h << 7) + (d4 << 2)];
    }
    __syncthreads();

    float aw[4][4], ah[4][4];
#pragma unroll
    for (int i = 0; i < 4; i++)
#pragma unroll
        for (int j = 0; j < 4; j++) { aw[i][j] = 0.f; ah[i][j] = 0.f; }

#pragma unroll 4
    for (int d = 0; d < 128; d++) {
        float bw[4], bh[4], a[4];
        *(float4*)bw = *(const float4*)&pw[(d << 6) + tx * 4];
        *(float4*)bh = *(const float4*)&ph[(d << 6) + tx * 4];
#pragma unroll
        for (int i = 0; i < 4; i++) a[i] = qs[(ty * 4 + i) * 132 + d];
#pragma unroll
        for (int i = 0; i < 4; i++)
#pragma unroll
            for (int c = 0; c < 4; c++) {
                aw[i][c] += a[i] * bw[c];
                ah[i][c] += a[i] * bh[c];
            }
    }

#pragma unroll
    for (int i = 0; i < 4; i++) {
        int gr = gr0 + ty * 4 + i;
#pragma unroll
        for (int c = 0; c < 4; c++) {
            int r = tx * 4 + c;
            if (r < NREL) {
                rw[(size_t)gr * NREL + r] = aw[i][c];
                rh[(size_t)gr * NREL + r] = ah[i][c];
            }
        }
    }
}

// ---------------------------------------------------------------------------
extern "C" void kernel_launch(void* const* d_in, const int* in_sizes, int n_in,
                              void* d_out, int out_size)
{
    const float* x   = (const float*)d_in[0];
    const float* Wq  = (const float*)d_in[1];
    const float* Wk  = (const float*)d_in[2];
    const float* Wv  = (const float*)d_in[3];
    const float* Wo  = (const float*)d_in[4];
    const float* pew = (const float*)d_in[5];
    const float* peh = (const float*)d_in[6];
    float* out = (float*)d_out;

    float *qp, *vp, *rwp, *rhp;
    __nv_bfloat16 *xh,*xl,*qh,*ql,*kh,*kl,*vth,*vtl,*aoh,*aol;
    __nv_bfloat16 *wqh,*wql,*wkh,*wkl,*wvh,*wvl,*woh,*wol;
    cudaGetSymbolAddress((void**)&qp,  g_q);
    cudaGetSymbolAddress((void**)&vp,  g_v);
    cudaGetSymbolAddress((void**)&rwp, g_rw);
    cudaGetSymbolAddress((void**)&rhp, g_rh);
    cudaGetSymbolAddress((void**)&xh,  g_xh);  cudaGetSymbolAddress((void**)&xl,  g_xl);
    cudaGetSymbolAddress((void**)&qh,  g_qh);  cudaGetSymbolAddress((void**)&ql,  g_ql);
    cudaGetSymbolAddress((void**)&kh,  g_kh);  cudaGetSymbolAddress((void**)&kl,  g_kl);
    cudaGetSymbolAddress((void**)&vth, g_vth); cudaGetSymbolAddress((void**)&vtl, g_vtl);
    cudaGetSymbolAddress((void**)&aoh, g_aoh); cudaGetSymbolAddress((void**)&aol, g_aol);
    cudaGetSymbolAddress((void**)&wqh, g_wqh); cudaGetSymbolAddress((void**)&wql, g_wql);
    cudaGetSymbolAddress((void**)&wkh, g_wkh); cudaGetSymbolAddress((void**)&wkl, g_wkl);
    cudaGetSymbolAddress((void**)&wvh, g_wvh); cudaGetSymbolAddress((void**)&wvl, g_wvl);
    cudaGetSymbolAddress((void**)&woh, g_woh); cudaGetSymbolAddress((void**)&wol, g_wol);

    cudaFuncSetAttribute(gemm_bs<true ,true >, cudaFuncAttributeMaxDynamicSharedMemorySize, GEMM_SMEM);
    cudaFuncSetAttribute(gemm_bs<true ,false>, cudaFuncAttributeMaxDynamicSharedMemorySize, GEMM_SMEM);
    cudaFuncSetAttribute(gemm_bs<false,true >, cudaFuncAttributeMaxDynamicSharedMemorySize, GEMM_SMEM);
    cudaFuncSetAttribute(flash,  cudaFuncAttributeMaxDynamicSharedMemorySize, FLASH_SMEM);
    cudaFuncSetAttribute(relpos, cudaFuncAttributeMaxDynamicSharedMemorySize, RELPOS_SMEM);

    const float scale = 0.08838834764831845f;   // 1/sqrt(128)

    splitx<<<1024, 256>>>(x, xh, xl, 8192*512/4);
    dim3 tg(16, 16), tb(32, 8);
    tsplit<<<tg, tb>>>(Wq, wqh, wql);
    tsplit<<<tg, tb>>>(Wk, wkh, wkl);
    tsplit<<<tg, tb>>>(Wv, wvh, wvl);
    tsplit<<<tg, tb>>>(Wo, woh, wol);

    dim3 pg(4, 64);
    gemm_bs<true ,true ><<<pg, 256, GEMM_SMEM>>>(xh, xl, wqh, wql, qp, qh, ql, 16, scale);
    gemm_bs<true ,false><<<pg, 256, GEMM_SMEM>>>(xh, xl, wkh, wkl, nullptr, kh, kl, 16, 1.0f);
    gemm_bs<false,true ><<<pg, 256, GEMM_SMEM>>>(xh, xl, wvh, wvl, vp, nullptr, nullptr, 16, 1.0f);

    vtrans<<<dim3(32, 4, 32), dim3(32, 8)>>>(vp, vth, vtl);
    relpos<<<512, 256, RELPOS_SMEM>>>(qp, pew, peh, rwp, rhp);

    flash<<<dim3(8, 1, 32), 256, FLASH_SMEM>>>(qh, ql, kh, kl, vth, vtl, rwp, rhp, aoh, aol);

    gemm_bs<false,true ><<<pg, 256, GEMM_SMEM>>>(aoh, aol, woh, wol, out, nullptr, nullptr, 16, 1.0f);
}

// round 7
// speedup vs baseline: 2.8769x; 1.0885x over previous
#include <cuda_runtime.h>
#include <cuda_bf16.h>
#include <cstdint>

// Problem constants
#define BB     8
#define LL     1024
#define HEADS  4
#define KD     128
#define EMB    512
#define NREL   63

// ---------------------------------------------------------------------------
// Device-global scratch (no allocations allowed)
// ---------------------------------------------------------------------------
__device__ float          g_v  [BB*LL*EMB];          // fp32 v (transpose input)
__device__ float          g_rwh[32*1024*128];        // fused RW|RH bias, pitch 128
__device__ __nv_bfloat16  g_xh [BB*LL*EMB], g_xl [BB*LL*EMB];
__device__ __nv_bfloat16  g_qh [BB*LL*EMB], g_ql [BB*LL*EMB];
__device__ __nv_bfloat16  g_kh [BB*LL*EMB], g_kl [BB*LL*EMB];
__device__ __nv_bfloat16  g_vth[32*128*1024], g_vtl[32*128*1024];
__device__ __nv_bfloat16  g_aoh[BB*LL*EMB], g_aol[BB*LL*EMB];
__device__ __nv_bfloat16  g_wqh[EMB*EMB], g_wql[EMB*EMB];
__device__ __nv_bfloat16  g_wkh[EMB*EMB], g_wkl[EMB*EMB];
__device__ __nv_bfloat16  g_wvh[EMB*EMB], g_wvl[EMB*EMB];
__device__ __nv_bfloat16  g_woh[EMB*EMB], g_wol[EMB*EMB];
__device__ __nv_bfloat16  g_pbh[128*128], g_pbl[128*128];   // padded [posW|posH]^T

// ---------------------------------------------------------------------------
// PTX helpers
// ---------------------------------------------------------------------------
__device__ __forceinline__ uint32_t smem_u32(const void* p) {
    uint32_t a;
    asm("{ .reg .u64 t; cvta.to.shared.u64 t, %1; cvt.u32.u64 %0, t; }" : "=r"(a) : "l"(p));
    return a;
}
__device__ __forceinline__ void ldsm4(uint32_t addr, uint32_t* r) {
    asm volatile("ldmatrix.sync.aligned.m8n8.x4.shared.b16 {%0,%1,%2,%3}, [%4];"
                 : "=r"(r[0]), "=r"(r[1]), "=r"(r[2]), "=r"(r[3]) : "r"(addr));
}
__device__ __forceinline__ void mma_bf16(float* d, const uint32_t* a, uint32_t b0, uint32_t b1) {
    asm volatile("mma.sync.aligned.m16n8k16.row.col.f32.bf16.bf16.f32 "
                 "{%0,%1,%2,%3}, {%4,%5,%6,%7}, {%8,%9}, {%0,%1,%2,%3};"
                 : "+f"(d[0]), "+f"(d[1]), "+f"(d[2]), "+f"(d[3])
                 : "r"(a[0]), "r"(a[1]), "r"(a[2]), "r"(a[3]), "r"(b0), "r"(b1));
}
#define CP_ASYNC(dst, src) asm volatile("cp.async.ca.shared.global [%0], [%1], 16;" :: "r"(dst), "l"(src))
#define CP_COMMIT()        asm volatile("cp.async.commit_group;" ::: "memory")
#define CP_WAIT1()         asm volatile("cp.async.wait_group 1;" ::: "memory")
#define CP_WAIT0()         asm volatile("cp.async.wait_group 0;" ::: "memory")

__device__ __forceinline__ void bsplit(float x, __nv_bfloat16& h, __nv_bfloat16& l) {
    h = __float2bfloat16_rn(x);
    l = __float2bfloat16_rn(x - __bfloat162float(h));
}
__device__ __forceinline__ uint32_t packbf(__nv_bfloat16 a, __nv_bfloat16 b) {
    __nv_bfloat162 t(a, b);
    return *(uint32_t*)&t;
}

// ---------------------------------------------------------------------------
// bf16-split pipelined mma GEMM: C = (Ahi+Alo)@(Bhi+Blo)^T * scale
// Batched: off = (z>>2)*str1 + (z&3)*str2 per operand.
// ---------------------------------------------------------------------------
#define STG_BYTES 40960
#define TILE_P    10240
#define GEMM_SMEM (3 * STG_BYTES)

template<bool SPLIT, bool WF32>
__global__ __launch_bounds__(256) void gemm_bs(
    const __nv_bfloat16* __restrict__ Ahi, const __nv_bfloat16* __restrict__ Alo,
    int lda, long long strA1, long long strA2,
    const __nv_bfloat16* __restrict__ Bhi, const __nv_bfloat16* __restrict__ Blo,
    int ldb, long long strB1, long long strB2,
    float* __restrict__ Cf, __nv_bfloat16* __restrict__ Chi, __nv_bfloat16* __restrict__ Clo,
    int ldc, long long strC1, long long strC2,
    int kIters, float scale)
{
    extern __shared__ char smem[];
    const uint32_t sb0 = smem_u32(smem);
    const int tid  = threadIdx.x;
    const int lane = tid & 31;
    const int wid  = tid >> 5;
    const int wm   = wid >> 1;
    const int wn   = wid & 1;
    const int n0   = blockIdx.x * 128;
    const int m0   = blockIdx.y * 128;
    const int z    = blockIdx.z;

    const size_t offA = (size_t)(z >> 2) * strA1 + (size_t)(z & 3) * strA2;
    const size_t offB = (size_t)(z >> 2) * strB1 + (size_t)(z & 3) * strB2;
    const size_t offC = (size_t)(z >> 2) * strC1 + (size_t)(z & 3) * strC2;

    const __nv_bfloat16* aH = Ahi + offA + (size_t)m0 * lda;
    const __nv_bfloat16* aL = Alo + offA + (size_t)m0 * lda;
    const __nv_bfloat16* bH = Bhi + offB + (size_t)n0 * ldb;
    const __nv_bfloat16* bL = Blo + offB + (size_t)n0 * ldb;

    auto issue = [&](int c, int stg) {
        const uint32_t sb = sb0 + stg * STG_BYTES;
        const int k0 = c * 32;
#pragma unroll
        for (int i = 0; i < 2; i++) {
            int o  = tid + i * 256;
            int r  = o >> 2;
            int ch = o & 3;
            uint32_t d = sb + r * 80 + ch * 16;
            const __nv_bfloat16* s;
            s = aH + (size_t)r * lda + k0 + ch * 8; CP_ASYNC(d,            s);
            s = aL + (size_t)r * lda + k0 + ch * 8; CP_ASYNC(d + TILE_P,   s);
            s = bH + (size_t)r * ldb + k0 + ch * 8; CP_ASYNC(d + 2*TILE_P, s);
            s = bL + (size_t)r * ldb + k0 + ch * 8; CP_ASYNC(d + 3*TILE_P, s);
        }
        CP_COMMIT();
    };

    issue(0, 0);
    issue(1, 1);

    float acc[2][8][4];
#pragma unroll
    for (int mt = 0; mt < 2; mt++)
#pragma unroll
        for (int nt = 0; nt < 8; nt++)
#pragma unroll
            for (int e = 0; e < 4; e++) acc[mt][nt][e] = 0.f;

    for (int c = 0; c < kIters; c++) {
        CP_WAIT1();
        __syncthreads();
        if (c + 2 < kIters) issue(c + 2, (c + 2) % 3);

        const uint32_t sb = sb0 + (c % 3) * STG_BYTES;
#pragma unroll
        for (int s = 0; s < 2; s++) {
            uint32_t ahf[2][4], alf[2][4];
#pragma unroll
            for (int mt = 0; mt < 2; mt++) {
                uint32_t addr = sb + (uint32_t)((wm * 32 + mt * 16 + (lane & 15)) * 80)
                                   + (uint32_t)((s * 2 + (lane >> 4)) << 4);
                ldsm4(addr,          ahf[mt]);
                ldsm4(addr + TILE_P, alf[mt]);
            }
            uint32_t bhf[4][4], blf[4][4];
#pragma unroll
            for (int ng = 0; ng < 4; ng++) {
                int row = wn * 64 + ng * 16 + ((lane >> 4) << 3) + (lane & 7);
                uint32_t addr = sb + 2 * TILE_P + (uint32_t)(row * 80)
                                   + (uint32_t)((s * 2 + ((lane >> 3) & 1)) << 4);
                ldsm4(addr,          bhf[ng]);
                ldsm4(addr + TILE_P, blf[ng]);
            }
#pragma unroll
            for (int mt = 0; mt < 2; mt++)
#pragma unroll
                for (int nt = 0; nt < 8; nt++) {
                    int ng = nt >> 1, o = (nt & 1) * 2;
                    mma_bf16(acc[mt][nt], ahf[mt], bhf[ng][o], bhf[ng][o + 1]);
                    mma_bf16(acc[mt][nt], ahf[mt], blf[ng][o], blf[ng][o + 1]);
                    mma_bf16(acc[mt][nt], alf[mt], bhf[ng][o], bhf[ng][o + 1]);
                }
        }
    }

    const int rr  = lane >> 2;
    const int cp2 = (lane & 3) * 2;
    float*         Cfb = WF32  ? (Cf  + offC) : nullptr;
    __nv_bfloat16* Chb = SPLIT ? (Chi + offC) : nullptr;
    __nv_bfloat16* Clb = SPLIT ? (Clo + offC) : nullptr;
#pragma unroll
    for (int mt = 0; mt < 2; mt++) {
        int row0 = m0 + wm * 32 + mt * 16 + rr;
        int row1 = row0 + 8;
#pragma unroll
        for (int nt = 0; nt < 8; nt++) {
            int col = n0 + wn * 64 + nt * 8 + cp2;
            float v0 = acc[mt][nt][0] * scale;
            float v1 = acc[mt][nt][1] * scale;
            float v2 = acc[mt][nt][2] * scale;
            float v3 = acc[mt][nt][3] * scale;
            if (WF32) {
                *(float2*)&Cfb[(size_t)row0 * ldc + col] = make_float2(v0, v1);
                *(float2*)&Cfb[(size_t)row1 * ldc + col] = make_float2(v2, v3);
            }
            if (SPLIT) {
                __nv_bfloat16 h0, l0, h1, l1;
                bsplit(v0, h0, l0); bsplit(v1, h1, l1);
                *(__nv_bfloat162*)&Chb[(size_t)row0 * ldc + col] = __nv_bfloat162(h0, h1);
                *(__nv_bfloat162*)&Clb[(size_t)row0 * ldc + col] = __nv_bfloat162(l0, l1);
                bsplit(v2, h0, l0); bsplit(v3, h1, l1);
                *(__nv_bfloat162*)&Chb[(size_t)row1 * ldc + col] = __nv_bfloat162(h0, h1);
                *(__nv_bfloat162*)&Clb[(size_t)row1 * ldc + col] = __nv_bfloat162(l0, l1);
            }
        }
    }
}

// ---------------------------------------------------------------------------
// Fused flash attention, pipelined loads.
// CTA = (qtile 0..7, z=b*4+h), 128 q-rows, 64-key window x 16 iters, 8 warps.
// ---------------------------------------------------------------------------
#define FL_QH 0
#define FL_QL 34816
#define FL_KH 69632
#define FL_KL 87040
#define FL_VH 104448
#define FL_VL 122880
#define FL_RW 141312                      // float[128][68]
#define FL_RH (141312 + 34816)
#define FLASH_SMEM (141312 + 2 * 34816)   // 210944

__global__ __launch_bounds__(256) void flash(
    const __nv_bfloat16* __restrict__ qh, const __nv_bfloat16* __restrict__ ql,
    const __nv_bfloat16* __restrict__ kh, const __nv_bfloat16* __restrict__ kl,
    const __nv_bfloat16* __restrict__ vth, const __nv_bfloat16* __restrict__ vtl,
    const float* __restrict__ rwh,
    __nv_bfloat16* __restrict__ aoh, __nv_bfloat16* __restrict__ aol)
{
    extern __shared__ char smem[];
    const uint32_t sb = smem_u32(smem);
    float* rwS = (float*)(smem + FL_RW);
    float* rhS = (float*)(smem + FL_RH);

    const int tid  = threadIdx.x;
    const int lane = tid & 31;
    const int w    = tid >> 5;
    const int z    = blockIdx.z;
    const int b    = z >> 2;
    const int hh   = z & 3;
    const int qbase = blockIdx.x * 128;

    auto loadK = [&](int it) {
        const int kb = it * 64;
#pragma unroll
        for (int t = 0; t < 4; t++) {
            int idx = tid + t * 256;
            int r = idx >> 4, c = idx & 15;
            size_t g = (size_t)((b << 10) + kb + r) * 512 + hh * 128 + c * 8;
            CP_ASYNC(sb + FL_KH + r * 272 + c * 16, kh + g);
            CP_ASYNC(sb + FL_KL + r * 272 + c * 16, kl + g);
        }
        CP_COMMIT();
    };
    auto loadV = [&](int it) {
        const int kb = it * 64;
#pragma unroll
        for (int t = 0; t < 4; t++) {
            int idx = tid + t * 256;
            int d = idx >> 3, c = idx & 7;
            size_t g = (size_t)z * 131072 + (size_t)d * 1024 + kb + c * 8;
            CP_ASYNC(sb + FL_VH + d * 144 + c * 16, vth + g);
            CP_ASYNC(sb + FL_VL + d * 144 + c * 16, vtl + g);
        }
        CP_COMMIT();
    };

    // Q group
#pragma unroll
    for (int t = 0; t < 8; t++) {
        int idx = tid + t * 256;
        int r = idx >> 4, c = idx & 15;
        size_t g = (size_t)((b << 10) + qbase + r) * 512 + hh * 128 + c * 8;
        CP_ASYNC(sb + FL_QH + r * 272 + c * 16, qh + g);
        CP_ASYNC(sb + FL_QL + r * 272 + c * 16, ql + g);
    }
    CP_COMMIT();
    loadK(0);
    loadV(0);

    // bias tables: fused rwh [row][128] -> rwS/rhS pitch 68
    {
        const float4* bsrc = (const float4*)(rwh + ((size_t)z * 1024 + qbase) * 128);
        for (int i = tid; i < 128 * 32; i += 256) {
            int r = i >> 5, c = i & 31;
            float4 v = bsrc[r * 32 + c];
            if (c < 16) *(float4*)&rwS[r * 68 + c * 4]        = v;
            else        *(float4*)&rhS[r * 68 + (c - 16) * 4] = v;
        }
    }

    const int r0 = w * 16 + (lane >> 2);
    const int r1 = r0 + 8;
    const int lq0 = qbase + r0, lq1 = qbase + r1;
    const int xq0 = lq0 & 31, yq0 = lq0 >> 5;
    const int xq1 = lq1 & 31, yq1 = lq1 >> 5;
    const float L2E = 1.4426950408889634f;

    float m0 = -1e30f, m1 = -1e30f, l0 = 0.f, l1 = 0.f;
    float O[16][4];
#pragma unroll
    for (int d = 0; d < 16; d++)
#pragma unroll
        for (int e = 0; e < 4; e++) O[d][e] = 0.f;

    for (int it = 0; it < 16; it++) {
        const int kb = it * 64;

        CP_WAIT1();                     // Q + K(it) ready (V(it) may be in flight)
        __syncthreads();

        // ---- S = Q K^T ----
        float s[8][4];
#pragma unroll
        for (int nt = 0; nt < 8; nt++)
#pragma unroll
            for (int e = 0; e < 4; e++) s[nt][e] = 0.f;

#pragma unroll
        for (int ks = 0; ks < 8; ks++) {
            uint32_t qhf[4], qlf[4];
            uint32_t addrA = sb + FL_QH + (uint32_t)((w * 16 + (lane & 15)) * 272)
                               + (uint32_t)(ks * 32 + (lane >> 4) * 16);
            ldsm4(addrA,                   qhf);
            ldsm4(addrA + (FL_QL - FL_QH), qlf);
            uint32_t bhf[4][4], blf[4][4];
#pragma unroll
            for (int ng = 0; ng < 4; ng++) {
                int row = ng * 16 + ((lane >> 4) << 3) + (lane & 7);
                uint32_t addrB = sb + FL_KH + (uint32_t)(row * 272)
                                   + (uint32_t)(ks * 32 + ((lane >> 3) & 1) * 16);
                ldsm4(addrB,                   bhf[ng]);
                ldsm4(addrB + (FL_KL - FL_KH), blf[ng]);
            }
#pragma unroll
            for (int nt = 0; nt < 8; nt++) {
                int ng = nt >> 1, o = (nt & 1) * 2;
                mma_bf16(s[nt], qhf, bhf[ng][o], bhf[ng][o + 1]);
                mma_bf16(s[nt], qhf, blf[ng][o], blf[ng][o + 1]);
                mma_bf16(s[nt], qlf, bhf[ng][o], bhf[ng][o + 1]);
            }
        }
        __syncthreads();                // all warps done reading K
        if (it < 15) loadK(it + 1);     // overlap with softmax + PV

        // ---- bias + online softmax ----
        float mx0 = m0, mx1 = m1;
#pragma unroll
        for (int nt = 0; nt < 8; nt++) {
            int c0 = kb + nt * 8 + (lane & 3) * 2;
            int c1 = c0 + 1;
            int xk0 = c0 & 31, yk0 = (c0 >> 5) & 31;
            int xk1 = c1 & 31, yk1 = (c1 >> 5) & 31;
            s[nt][0] += rwS[r0 * 68 + xk0 - xq0 + 31] + rhS[r0 * 68 + yk0 - yq0 + 31];
            s[nt][1] += rwS[r0 * 68 + xk1 - xq0 + 31] + rhS[r0 * 68 + yk1 - yq0 + 31];
            s[nt][2] += rwS[r1 * 68 + xk0 - xq1 + 31] + rhS[r1 * 68 + yk0 - yq1 + 31];
            s[nt][3] += rwS[r1 * 68 + xk1 - xq1 + 31] + rhS[r1 * 68 + yk1 - yq1 + 31];
            mx0 = fmaxf(mx0, fmaxf(s[nt][0], s[nt][1]));
            mx1 = fmaxf(mx1, fmaxf(s[nt][2], s[nt][3]));
        }
        mx0 = fmaxf(mx0, __shfl_xor_sync(0xffffffffu, mx0, 1));
        mx0 = fmaxf(mx0, __shfl_xor_sync(0xffffffffu, mx0, 2));
        mx1 = fmaxf(mx1, __shfl_xor_sync(0xffffffffu, mx1, 1));
        mx1 = fmaxf(mx1, __shfl_xor_sync(0xffffffffu, mx1, 2));

        float a0 = exp2f((m0 - mx0) * L2E);
        float a1 = exp2f((m1 - mx1) * L2E);
        m0 = mx0; m1 = mx1;

        float s0 = 0.f, s1 = 0.f;
#pragma unroll
        for (int nt = 0; nt < 8; nt++) {
            s[nt][0] = exp2f((s[nt][0] - m0) * L2E);
            s[nt][1] = exp2f((s[nt][1] - m0) * L2E);
            s[nt][2] = exp2f((s[nt][2] - m1) * L2E);
            s[nt][3] = exp2f((s[nt][3] - m1) * L2E);
            s0 += s[nt][0] + s[nt][1];
            s1 += s[nt][2] + s[nt][3];
        }
        s0 += __shfl_xor_sync(0xffffffffu, s0, 1);
        s0 += __shfl_xor_sync(0xffffffffu, s0, 2);
        s1 += __shfl_xor_sync(0xffffffffu, s1, 1);
        s1 += __shfl_xor_sync(0xffffffffu, s1, 2);
        l0 = l0 * a0 + s0;
        l1 = l1 * a1 + s1;

#pragma unroll
        for (int d = 0; d < 16; d++) {
            O[d][0] *= a0; O[d][1] *= a0;
            O[d][2] *= a1; O[d][3] *= a1;
        }

        if (it < 15) { CP_WAIT1(); } else { CP_WAIT0(); }   // V(it) ready
        __syncthreads();

        // ---- O += P V^T ----
#pragma unroll
        for (int ks = 0; ks < 4; ks++) {
            uint32_t pah[4], pal[4];
            {
                __nv_bfloat16 h00,l00,h01,l01,h02,l02,h03,l03;
                __nv_bfloat16 h10,l10,h11,l11,h12,l12,h13,l13;
                bsplit(s[2*ks][0],   h00, l00); bsplit(s[2*ks][1],   h01, l01);
                bsplit(s[2*ks][2],   h02, l02); bsplit(s[2*ks][3],   h03, l03);
                bsplit(s[2*ks+1][0], h10, l10); bsplit(s[2*ks+1][1], h11, l11);
                bsplit(s[2*ks+1][2], h12, l12); bsplit(s[2*ks+1][3], h13, l13);
                pah[0] = packbf(h00, h01); pah[1] = packbf(h02, h03);
                pah[2] = packbf(h10, h11); pah[3] = packbf(h12, h13);
                pal[0] = packbf(l00, l01); pal[1] = packbf(l02, l03);
                pal[2] = packbf(l10, l11); pal[3] = packbf(l12, l13);
            }
#pragma unroll
            for (int dg = 0; dg < 8; dg++) {
                int row = dg * 16 + ((lane >> 4) << 3) + (lane & 7);
                uint32_t addrV = sb + FL_VH + (uint32_t)(row * 144)
                                   + (uint32_t)(ks * 32 + ((lane >> 3) & 1) * 16);
                uint32_t vhf[4], vlf[4];
                ldsm4(addrV,                   vhf);
                ldsm4(addrV + (FL_VL - FL_VH), vlf);
#pragma unroll
                for (int hf = 0; hf < 2; hf++) {
                    int dnt = dg * 2 + hf, o = hf * 2;
                    mma_bf16(O[dnt], pah, vhf[o], vhf[o + 1]);
                    mma_bf16(O[dnt], pah, vlf[o], vlf[o + 1]);
                    mma_bf16(O[dnt], pal, vhf[o], vhf[o + 1]);
                }
            }
        }
        __syncthreads();                // all warps done reading V
        if (it < 15) loadV(it + 1);     // overlap with next iter's QK
    }

    // ---- normalize + store split bf16 ----
    float inv0 = 1.0f / l0, inv1 = 1.0f / l1;
    size_t row0g = (size_t)((b << 10) + lq0) * 512 + hh * 128;
    size_t row1g = (size_t)((b << 10) + lq1) * 512 + hh * 128;
#pragma unroll
    for (int d = 0; d < 16; d++) {
        int col = d * 8 + (lane & 3) * 2;
        __nv_bfloat16 h0, lo0, h1, lo1;
        bsplit(O[d][0] * inv0, h0, lo0); bsplit(O[d][1] * inv0, h1, lo1);
        *(__nv_bfloat162*)&aoh[row0g + col] = __nv_bfloat162(h0, h1);
        *(__nv_bfloat162*)&aol[row0g + col] = __nv_bfloat162(lo0, lo1);
        bsplit(O[d][2] * inv1, h0, lo0); bsplit(O[d][3] * inv1, h1, lo1);
        *(__nv_bfloat162*)&aoh[row1g + col] = __nv_bfloat162(h0, h1);
        *(__nv_bfloat162*)&aol[row1g + col] = __nv_bfloat162(lo0, lo1);
    }
}

// ---------------------------------------------------------------------------
// x -> bf16 hi/lo split
// ---------------------------------------------------------------------------
__global__ __launch_bounds__(256) void splitx(const float* __restrict__ x,
                                              __nv_bfloat16* __restrict__ xh,
                                              __nv_bfloat16* __restrict__ xl, int n4)
{
    for (int i = blockIdx.x * 256 + threadIdx.x; i < n4; i += gridDim.x * 256) {
        float4 v = ((const float4*)x)[i];
        __nv_bfloat16 h0,l0,h1,l1,h2,l2,h3,l3;
        bsplit(v.x,h0,l0); bsplit(v.y,h1,l1); bsplit(v.z,h2,l2); bsplit(v.w,h3,l3);
        ((__nv_bfloat162*)xh)[i*2]   = __nv_bfloat162(h0,h1);
        ((__nv_bfloat162*)xh)[i*2+1] = __nv_bfloat162(h2,h3);
        ((__nv_bfloat162*)xl)[i*2]   = __nv_bfloat162(l0,l1);
        ((__nv_bfloat162*)xl)[i*2+1] = __nv_bfloat162(l2,l3);
    }
}

// ---------------------------------------------------------------------------
// Weight transpose + split
// ---------------------------------------------------------------------------
__global__ void tsplit(const float* __restrict__ W,
                       __nv_bfloat16* __restrict__ th, __nv_bfloat16* __restrict__ tl)
{
    __shared__ float t[32][33];
    int x = blockIdx.x * 32 + threadIdx.x;
    int y = blockIdx.y * 32 + threadIdx.y;
#pragma unroll
    for (int j = 0; j < 32; j += 8)
        t[threadIdx.y + j][threadIdx.x] = W[(size_t)(y + j) * 512 + x];
    __syncthreads();
    int x2 = blockIdx.y * 32 + threadIdx.x;
    int y2 = blockIdx.x * 32 + threadIdx.y;
#pragma unroll
    for (int j = 0; j < 32; j += 8) {
        float val = t[threadIdx.x][threadIdx.y + j];
        __nv_bfloat16 h, l;
        bsplit(val, h, l);
        size_t o = (size_t)(y2 + j) * 512 + x2;
        th[o] = h; tl[o] = l;
    }
}

// ---------------------------------------------------------------------------
// Padded [posW | posH]^T -> bf16 hi/lo. B row n, col k (ldb=128).
// n<63: posW[k][n]; n==63: 0; 64<=n<127: posH[k][n-64]; n==127: 0.
// ---------------------------------------------------------------------------
__global__ void posprep(const float* __restrict__ pew, const float* __restrict__ peh,
                        __nv_bfloat16* __restrict__ pbh, __nv_bfloat16* __restrict__ pbl)
{
    int i = blockIdx.x * 256 + threadIdx.x;
    if (i >= 128 * 128) return;
    int n = i >> 7, k = i & 127;
    float v = 0.f;
    if (n < NREL)                 v = pew[k * NREL + n];
    else if (n >= 64 && n < 127)  v = peh[k * NREL + (n - 64)];
    __nv_bfloat16 h, l;
    bsplit(v, h, l);
    pbh[i] = h; pbl[i] = l;
}

// ---------------------------------------------------------------------------
// V transpose + split: v[b,l,h*128+d] -> vt[(b*4+h), d, l] hi/lo
// ---------------------------------------------------------------------------
__global__ void vtrans(const float* __restrict__ v,
                       __nv_bfloat16* __restrict__ vth, __nv_bfloat16* __restrict__ vtl)
{
    __shared__ float t[32][33];
    int z = blockIdx.z, b = z >> 2, h = z & 3;
    int l0 = blockIdx.x * 32, d0 = blockIdx.y * 32;
#pragma unroll
    for (int j = 0; j < 32; j += 8)
        t[threadIdx.y + j][threadIdx.x] =
            v[(size_t)(b * 1024 + l0 + threadIdx.y + j) * 512 + h * 128 + d0 + threadIdx.x];
    __syncthreads();
#pragma unroll
    for (int j = 0; j < 32; j += 8) {
        int d = d0 + threadIdx.y + j;
        float val = t[threadIdx.x][threadIdx.y + j];
        __nv_bfloat16 hh, ll;
        bsplit(val, hh, ll);
        size_t o = (size_t)z * 131072 + (size_t)d * 1024 + l0 + threadIdx.x;
        vth[o] = hh; vtl[o] = ll;
    }
}

// ---------------------------------------------------------------------------
extern "C" void kernel_launch(void* const* d_in, const int* in_sizes, int n_in,
                              void* d_out, int out_size)
{
    const float* x   = (const float*)d_in[0];
    const float* Wq  = (const float*)d_in[1];
    const float* Wk  = (const float*)d_in[2];
    const float* Wv  = (const float*)d_in[3];
    const float* Wo  = (const float*)d_in[4];
    const float* pew = (const float*)d_in[5];
    const float* peh = (const float*)d_in[6];
    float* out = (float*)d_out;

    float *vp, *rwhp;
    __nv_bfloat16 *xh,*xl,*qh,*ql,*kh,*kl,*vth,*vtl,*aoh,*aol,*pbh,*pbl;
    __nv_bfloat16 *wqh,*wql,*wkh,*wkl,*wvh,*wvl,*woh,*wol;
    cudaGetSymbolAddress((void**)&vp,   g_v);
    cudaGetSymbolAddress((void**)&rwhp, g_rwh);
    cudaGetSymbolAddress((void**)&xh,  g_xh);  cudaGetSymbolAddress((void**)&xl,  g_xl);
    cudaGetSymbolAddress((void**)&qh,  g_qh);  cudaGetSymbolAddress((void**)&ql,  g_ql);
    cudaGetSymbolAddress((void**)&kh,  g_kh);  cudaGetSymbolAddress((void**)&kl,  g_kl);
    cudaGetSymbolAddress((void**)&vth, g_vth); cudaGetSymbolAddress((void**)&vtl, g_vtl);
    cudaGetSymbolAddress((void**)&aoh, g_aoh); cudaGetSymbolAddress((void**)&aol, g_aol);
    cudaGetSymbolAddress((void**)&pbh, g_pbh); cudaGetSymbolAddress((void**)&pbl, g_pbl);
    cudaGetSymbolAddress((void**)&wqh, g_wqh); cudaGetSymbolAddress((void**)&wql, g_wql);
    cudaGetSymbolAddress((void**)&wkh, g_wkh); cudaGetSymbolAddress((void**)&wkl, g_wkl);
    cudaGetSymbolAddress((void**)&wvh, g_wvh); cudaGetSymbolAddress((void**)&wvl, g_wvl);
    cudaGetSymbolAddress((void**)&woh, g_woh); cudaGetSymbolAddress((void**)&wol, g_wol);

    cudaFuncSetAttribute(gemm_bs<true ,false>, cudaFuncAttributeMaxDynamicSharedMemorySize, GEMM_SMEM);
    cudaFuncSetAttribute(gemm_bs<false,true >, cudaFuncAttributeMaxDynamicSharedMemorySize, GEMM_SMEM);
    cudaFuncSetAttribute(flash, cudaFuncAttributeMaxDynamicSharedMemorySize, FLASH_SMEM);

    const float scale = 0.08838834764831845f;   // 1/sqrt(128)

    splitx<<<1024, 256>>>(x, xh, xl, 8192*512/4);
    dim3 tg(16, 16), tb(32, 8);
    tsplit<<<tg, tb>>>(Wq, wqh, wql);
    tsplit<<<tg, tb>>>(Wk, wkh, wkl);
    tsplit<<<tg, tb>>>(Wv, wvh, wvl);
    tsplit<<<tg, tb>>>(Wo, woh, wol);
    posprep<<<64, 256>>>(pew, peh, pbh, pbl);

    // projections
    dim3 pg(4, 64, 1);
    gemm_bs<true ,false><<<pg, 256, GEMM_SMEM>>>(xh, xl, 512, 0, 0, wqh, wql, 512, 0, 0,
        nullptr, qh, ql, 512, 0, 0, 16, scale);
    gemm_bs<true ,false><<<pg, 256, GEMM_SMEM>>>(xh, xl, 512, 0, 0, wkh, wkl, 512, 0, 0,
        nullptr, kh, kl, 512, 0, 0, 16, 1.0f);
    gemm_bs<false,true ><<<pg, 256, GEMM_SMEM>>>(xh, xl, 512, 0, 0, wvh, wvl, 512, 0, 0,
        vp, nullptr, nullptr, 512, 0, 0, 16, 1.0f);

    vtrans<<<dim3(32, 4, 32), dim3(32, 8)>>>(vp, vth, vtl);

    // relpos as batched GEMM: RW|RH [z, l, 128] = q[z,l,:] @ [posW|posH]
    gemm_bs<false,true ><<<dim3(1, 8, 32), 256, GEMM_SMEM>>>(
        qh, ql, 512, 524288LL, 128LL,
        pbh, pbl, 128, 0, 0,
        rwhp, nullptr, nullptr, 128, 524288LL, 131072LL,
        4, 1.0f);

    flash<<<dim3(8, 1, 32), 256, FLASH_SMEM>>>(qh, ql, kh, kl, vth, vtl, rwhp, aoh, aol);

    gemm_bs<false,true ><<<pg, 256, GEMM_SMEM>>>(aoh, aol, 512, 0, 0, woh, wol, 512, 0, 0,
        out, nullptr, nullptr, 512, 0, 0, 16, 1.0f);
}

// round 8
// speedup vs baseline: 2.9636x; 1.0301x over previous
#include <cuda_runtime.h>
#include <cuda_bf16.h>
#include <cstdint>

// Problem constants
#define BB     8
#define LL     1024
#define HEADS  4
#define KD     128
#define EMB    512
#define NREL   63

// ---------------------------------------------------------------------------
// Device-global scratch (no allocations allowed)
// ---------------------------------------------------------------------------
__device__ float          g_rwh[32*1024*128];        // fused RW|RH bias, pitch 128
__device__ __nv_bfloat16  g_xh [BB*LL*EMB], g_xl [BB*LL*EMB];
__device__ __nv_bfloat16  g_qh [BB*LL*EMB], g_ql [BB*LL*EMB];
__device__ __nv_bfloat16  g_kh [BB*LL*EMB], g_kl [BB*LL*EMB];
__device__ __nv_bfloat16  g_vh [BB*LL*EMB], g_vl [BB*LL*EMB];
__device__ __nv_bfloat16  g_aoh[BB*LL*EMB], g_aol[BB*LL*EMB];
__device__ __nv_bfloat16  g_wqh[EMB*EMB], g_wql[EMB*EMB];
__device__ __nv_bfloat16  g_wkh[EMB*EMB], g_wkl[EMB*EMB];
__device__ __nv_bfloat16  g_wvh[EMB*EMB], g_wvl[EMB*EMB];
__device__ __nv_bfloat16  g_woh[EMB*EMB], g_wol[EMB*EMB];
__device__ __nv_bfloat16  g_pbh[128*128], g_pbl[128*128];   // padded [posW|posH]^T

// ---------------------------------------------------------------------------
// PTX helpers
// ---------------------------------------------------------------------------
__device__ __forceinline__ uint32_t smem_u32(const void* p) {
    uint32_t a;
    asm("{ .reg .u64 t; cvta.to.shared.u64 t, %1; cvt.u32.u64 %0, t; }" : "=r"(a) : "l"(p));
    return a;
}
__device__ __forceinline__ void ldsm4(uint32_t addr, uint32_t* r) {
    asm volatile("ldmatrix.sync.aligned.m8n8.x4.shared.b16 {%0,%1,%2,%3}, [%4];"
                 : "=r"(r[0]), "=r"(r[1]), "=r"(r[2]), "=r"(r[3]) : "r"(addr));
}
__device__ __forceinline__ void ldsm4t(uint32_t addr, uint32_t* r) {
    asm volatile("ldmatrix.sync.aligned.m8n8.x4.trans.shared.b16 {%0,%1,%2,%3}, [%4];"
                 : "=r"(r[0]), "=r"(r[1]), "=r"(r[2]), "=r"(r[3]) : "r"(addr));
}
__device__ __forceinline__ void mma_bf16(float* d, const uint32_t* a, uint32_t b0, uint32_t b1) {
    asm volatile("mma.sync.aligned.m16n8k16.row.col.f32.bf16.bf16.f32 "
                 "{%0,%1,%2,%3}, {%4,%5,%6,%7}, {%8,%9}, {%0,%1,%2,%3};"
                 : "+f"(d[0]), "+f"(d[1]), "+f"(d[2]), "+f"(d[3])
                 : "r"(a[0]), "r"(a[1]), "r"(a[2]), "r"(a[3]), "r"(b0), "r"(b1));
}
#define CP_ASYNC(dst, src) asm volatile("cp.async.ca.shared.global [%0], [%1], 16;" :: "r"(dst), "l"(src))
#define CP_COMMIT()        asm volatile("cp.async.commit_group;" ::: "memory")
#define CP_WAIT1()         asm volatile("cp.async.wait_group 1;" ::: "memory")
#define CP_WAIT0()         asm volatile("cp.async.wait_group 0;" ::: "memory")

__device__ __forceinline__ void bsplit(float x, __nv_bfloat16& h, __nv_bfloat16& l) {
    h = __float2bfloat16_rn(x);
    l = __float2bfloat16_rn(x - __bfloat162float(h));
}
__device__ __forceinline__ uint32_t packbf(__nv_bfloat16 a, __nv_bfloat16 b) {
    __nv_bfloat162 t(a, b);
    return *(uint32_t*)&t;
}

// ---------------------------------------------------------------------------
// Shared GEMM machinery constants
// ---------------------------------------------------------------------------
#define STG_BYTES 40960
#define TILE_P    10240
#define GEMM_SMEM (3 * STG_BYTES)

// ---------------------------------------------------------------------------
// bf16-split pipelined mma GEMM (generic, fp32 out): C = (A@B^T)*scale
// Batched: off = (z>>2)*str1 + (z&3)*str2 per operand.
// ---------------------------------------------------------------------------
__global__ __launch_bounds__(256) void gemm_bs(
    const __nv_bfloat16* __restrict__ Ahi, const __nv_bfloat16* __restrict__ Alo,
    int lda, long long strA1, long long strA2,
    const __nv_bfloat16* __restrict__ Bhi, const __nv_bfloat16* __restrict__ Blo,
    int ldb, long long strB1, long long strB2,
    float* __restrict__ Cf,
    int ldc, long long strC1, long long strC2,
    int kIters, float scale)
{
    extern __shared__ char smem[];
    const uint32_t sb0 = smem_u32(smem);
    const int tid  = threadIdx.x;
    const int lane = tid & 31;
    const int wid  = tid >> 5;
    const int wm   = wid >> 1;
    const int wn   = wid & 1;
    const int n0   = blockIdx.x * 128;
    const int m0   = blockIdx.y * 128;
    const int z    = blockIdx.z;

    const size_t offA = (size_t)(z >> 2) * strA1 + (size_t)(z & 3) * strA2;
    const size_t offB = (size_t)(z >> 2) * strB1 + (size_t)(z & 3) * strB2;
    const size_t offC = (size_t)(z >> 2) * strC1 + (size_t)(z & 3) * strC2;

    const __nv_bfloat16* aH = Ahi + offA + (size_t)m0 * lda;
    const __nv_bfloat16* aL = Alo + offA + (size_t)m0 * lda;
    const __nv_bfloat16* bH = Bhi + offB + (size_t)n0 * ldb;
    const __nv_bfloat16* bL = Blo + offB + (size_t)n0 * ldb;

    auto issue = [&](int c, int stg) {
        const uint32_t sb = sb0 + stg * STG_BYTES;
        const int k0 = c * 32;
#pragma unroll
        for (int i = 0; i < 2; i++) {
            int o  = tid + i * 256;
            int r  = o >> 2;
            int ch = o & 3;
            uint32_t d = sb + r * 80 + ch * 16;
            const __nv_bfloat16* s;
            s = aH + (size_t)r * lda + k0 + ch * 8; CP_ASYNC(d,            s);
            s = aL + (size_t)r * lda + k0 + ch * 8; CP_ASYNC(d + TILE_P,   s);
            s = bH + (size_t)r * ldb + k0 + ch * 8; CP_ASYNC(d + 2*TILE_P, s);
            s = bL + (size_t)r * ldb + k0 + ch * 8; CP_ASYNC(d + 3*TILE_P, s);
        }
        CP_COMMIT();
    };

    issue(0, 0);
    issue(1, 1);

    float acc[2][8][4];
#pragma unroll
    for (int mt = 0; mt < 2; mt++)
#pragma unroll
        for (int nt = 0; nt < 8; nt++)
#pragma unroll
            for (int e = 0; e < 4; e++) acc[mt][nt][e] = 0.f;

    for (int c = 0; c < kIters; c++) {
        CP_WAIT1();
        __syncthreads();
        if (c + 2 < kIters) issue(c + 2, (c + 2) % 3);

        const uint32_t sb = sb0 + (c % 3) * STG_BYTES;
#pragma unroll
        for (int s = 0; s < 2; s++) {
            uint32_t ahf[2][4], alf[2][4];
#pragma unroll
            for (int mt = 0; mt < 2; mt++) {
                uint32_t addr = sb + (uint32_t)((wm * 32 + mt * 16 + (lane & 15)) * 80)
                                   + (uint32_t)((s * 2 + (lane >> 4)) << 4);
                ldsm4(addr,          ahf[mt]);
                ldsm4(addr + TILE_P, alf[mt]);
            }
            uint32_t bhf[4][4], blf[4][4];
#pragma unroll
            for (int ng = 0; ng < 4; ng++) {
                int row = wn * 64 + ng * 16 + ((lane >> 4) << 3) + (lane & 7);
                uint32_t addr = sb + 2 * TILE_P + (uint32_t)(row * 80)
                                   + (uint32_t)((s * 2 + ((lane >> 3) & 1)) << 4);
                ldsm4(addr,          bhf[ng]);
                ldsm4(addr + TILE_P, blf[ng]);
            }
#pragma unroll
            for (int mt = 0; mt < 2; mt++)
#pragma unroll
                for (int nt = 0; nt < 8; nt++) {
                    int ng = nt >> 1, o = (nt & 1) * 2;
                    mma_bf16(acc[mt][nt], ahf[mt], bhf[ng][o], bhf[ng][o + 1]);
                    mma_bf16(acc[mt][nt], ahf[mt], blf[ng][o], blf[ng][o + 1]);
                    mma_bf16(acc[mt][nt], alf[mt], bhf[ng][o], bhf[ng][o + 1]);
                }
        }
    }

    const int rr  = lane >> 2;
    const int cp2 = (lane & 3) * 2;
    float* Cfb = Cf + offC;
#pragma unroll
    for (int mt = 0; mt < 2; mt++) {
        int row0 = m0 + wm * 32 + mt * 16 + rr;
        int row1 = row0 + 8;
#pragma unroll
        for (int nt = 0; nt < 8; nt++) {
            int col = n0 + wn * 64 + nt * 8 + cp2;
            *(float2*)&Cfb[(size_t)row0 * ldc + col] =
                make_float2(acc[mt][nt][0] * scale, acc[mt][nt][1] * scale);
            *(float2*)&Cfb[(size_t)row1 * ldc + col] =
                make_float2(acc[mt][nt][2] * scale, acc[mt][nt][3] * scale);
        }
    }
}

// ---------------------------------------------------------------------------
// Fused QKV projection GEMM (split bf16 out). grid (12, 64):
// bx>>2 selects {Q,K,V}; n0 = (bx&3)*128 within the projection.
// ---------------------------------------------------------------------------
__global__ __launch_bounds__(256) void gemm_qkv(
    const __nv_bfloat16* __restrict__ xh, const __nv_bfloat16* __restrict__ xl,
    const __nv_bfloat16* __restrict__ wqh, const __nv_bfloat16* __restrict__ wql,
    const __nv_bfloat16* __restrict__ wkh, const __nv_bfloat16* __restrict__ wkl,
    const __nv_bfloat16* __restrict__ wvh, const __nv_bfloat16* __restrict__ wvl,
    __nv_bfloat16* __restrict__ qh, __nv_bfloat16* __restrict__ ql,
    __nv_bfloat16* __restrict__ kh, __nv_bfloat16* __restrict__ kl,
    __nv_bfloat16* __restrict__ vh, __nv_bfloat16* __restrict__ vl,
    float qscale)
{
    extern __shared__ char smem[];
    const uint32_t sb0 = smem_u32(smem);
    const int tid  = threadIdx.x;
    const int lane = tid & 31;
    const int wid  = tid >> 5;
    const int wm   = wid >> 1;
    const int wn   = wid & 1;
    const int sel  = blockIdx.x >> 2;
    const int n0   = (blockIdx.x & 3) * 128;
    const int m0   = blockIdx.y * 128;

    const __nv_bfloat16* Bhi = sel == 0 ? wqh : sel == 1 ? wkh : wvh;
    const __nv_bfloat16* Blo = sel == 0 ? wql : sel == 1 ? wkl : wvl;
    __nv_bfloat16* Chi = sel == 0 ? qh : sel == 1 ? kh : vh;
    __nv_bfloat16* Clo = sel == 0 ? ql : sel == 1 ? kl : vl;
    const float scale = sel == 0 ? qscale : 1.0f;

    const __nv_bfloat16* aH = xh  + (size_t)m0 * 512;
    const __nv_bfloat16* aL = xl  + (size_t)m0 * 512;
    const __nv_bfloat16* bH = Bhi + (size_t)n0 * 512;
    const __nv_bfloat16* bL = Blo + (size_t)n0 * 512;

    auto issue = [&](int c, int stg) {
        const uint32_t sb = sb0 + stg * STG_BYTES;
        const int k0 = c * 32;
#pragma unroll
        for (int i = 0; i < 2; i++) {
            int o  = tid + i * 256;
            int r  = o >> 2;
            int ch = o & 3;
            uint32_t d = sb + r * 80 + ch * 16;
            const __nv_bfloat16* s;
            s = aH + (size_t)r * 512 + k0 + ch * 8; CP_ASYNC(d,            s);
            s = aL + (size_t)r * 512 + k0 + ch * 8; CP_ASYNC(d + TILE_P,   s);
            s = bH + (size_t)r * 512 + k0 + ch * 8; CP_ASYNC(d + 2*TILE_P, s);
            s = bL + (size_t)r * 512 + k0 + ch * 8; CP_ASYNC(d + 3*TILE_P, s);
        }
        CP_COMMIT();
    };

    issue(0, 0);
    issue(1, 1);

    float acc[2][8][4];
#pragma unroll
    for (int mt = 0; mt < 2; mt++)
#pragma unroll
        for (int nt = 0; nt < 8; nt++)
#pragma unroll
            for (int e = 0; e < 4; e++) acc[mt][nt][e] = 0.f;

    for (int c = 0; c < 16; c++) {
        CP_WAIT1();
        __syncthreads();
        if (c + 2 < 16) issue(c + 2, (c + 2) % 3);

        const uint32_t sb = sb0 + (c % 3) * STG_BYTES;
#pragma unroll
        for (int s = 0; s < 2; s++) {
            uint32_t ahf[2][4], alf[2][4];
#pragma unroll
            for (int mt = 0; mt < 2; mt++) {
                uint32_t addr = sb + (uint32_t)((wm * 32 + mt * 16 + (lane & 15)) * 80)
                                   + (uint32_t)((s * 2 + (lane >> 4)) << 4);
                ldsm4(addr,          ahf[mt]);
                ldsm4(addr + TILE_P, alf[mt]);
            }
            uint32_t bhf[4][4], blf[4][4];
#pragma unroll
            for (int ng = 0; ng < 4; ng++) {
                int row = wn * 64 + ng * 16 + ((lane >> 4) << 3) + (lane & 7);
                uint32_t addr = sb + 2 * TILE_P + (uint32_t)(row * 80)
                                   + (uint32_t)((s * 2 + ((lane >> 3) & 1)) << 4);
                ldsm4(addr,          bhf[ng]);
                ldsm4(addr + TILE_P, blf[ng]);
            }
#pragma unroll
            for (int mt = 0; mt < 2; mt++)
#pragma unroll
                for (int nt = 0; nt < 8; nt++) {
                    int ng = nt >> 1, o = (nt & 1) * 2;
                    mma_bf16(acc[mt][nt], ahf[mt], bhf[ng][o], bhf[ng][o + 1]);
                    mma_bf16(acc[mt][nt], ahf[mt], blf[ng][o], blf[ng][o + 1]);
                    mma_bf16(acc[mt][nt], alf[mt], bhf[ng][o], bhf[ng][o + 1]);
                }
        }
    }

    const int rr  = lane >> 2;
    const int cp2 = (lane & 3) * 2;
#pragma unroll
    for (int mt = 0; mt < 2; mt++) {
        int row0 = m0 + wm * 32 + mt * 16 + rr;
        int row1 = row0 + 8;
#pragma unroll
        for (int nt = 0; nt < 8; nt++) {
            int col = n0 + wn * 64 + nt * 8 + cp2;
            __nv_bfloat16 h0, l0, h1, l1;
            bsplit(acc[mt][nt][0] * scale, h0, l0); bsplit(acc[mt][nt][1] * scale, h1, l1);
            *(__nv_bfloat162*)&Chi[(size_t)row0 * 512 + col] = __nv_bfloat162(h0, h1);
            *(__nv_bfloat162*)&Clo[(size_t)row0 * 512 + col] = __nv_bfloat162(l0, l1);
            bsplit(acc[mt][nt][2] * scale, h0, l0); bsplit(acc[mt][nt][3] * scale, h1, l1);
            *(__nv_bfloat162*)&Chi[(size_t)row1 * 512 + col] = __nv_bfloat162(h0, h1);
            *(__nv_bfloat162*)&Clo[(size_t)row1 * 512 + col] = __nv_bfloat162(l0, l1);
        }
    }
}

// ---------------------------------------------------------------------------
// Fused flash attention, pipelined loads. V consumed ROW-MAJOR via ldsm.trans.
// CTA = (qtile 0..7, z=b*4+h), 128 q-rows, 64-key window x 16 iters, 8 warps.
// ---------------------------------------------------------------------------
#define FL_QH 0
#define FL_QL 34816
#define FL_KH 69632
#define FL_KL 87040
#define FL_VH 104448
#define FL_VL 121856
#define FL_RW 139264                      // float[128][68]
#define FL_RH (139264 + 34816)
#define FLASH_SMEM (139264 + 2 * 34816)   // 208896

__global__ __launch_bounds__(256) void flash(
    const __nv_bfloat16* __restrict__ qh, const __nv_bfloat16* __restrict__ ql,
    const __nv_bfloat16* __restrict__ kh, const __nv_bfloat16* __restrict__ kl,
    const __nv_bfloat16* __restrict__ vh, const __nv_bfloat16* __restrict__ vl,
    const float* __restrict__ rwh,
    __nv_bfloat16* __restrict__ aoh, __nv_bfloat16* __restrict__ aol)
{
    extern __shared__ char smem[];
    const uint32_t sb = smem_u32(smem);
    float* rwS = (float*)(smem + FL_RW);
    float* rhS = (float*)(smem + FL_RH);

    const int tid  = threadIdx.x;
    const int lane = tid & 31;
    const int w    = tid >> 5;
    const int z    = blockIdx.z;
    const int b    = z >> 2;
    const int hh   = z & 3;
    const int qbase = blockIdx.x * 128;

    auto loadK = [&](int it) {
        const int kb = it * 64;
#pragma unroll
        for (int t = 0; t < 4; t++) {
            int idx = tid + t * 256;
            int r = idx >> 4, c = idx & 15;
            size_t g = (size_t)((b << 10) + kb + r) * 512 + hh * 128 + c * 8;
            CP_ASYNC(sb + FL_KH + r * 272 + c * 16, kh + g);
            CP_ASYNC(sb + FL_KL + r * 272 + c * 16, kl + g);
        }
        CP_COMMIT();
    };
    auto loadV = [&](int it) {
        const int kb = it * 64;
#pragma unroll
        for (int t = 0; t < 4; t++) {
            int idx = tid + t * 256;
            int r = idx >> 4, c = idx & 15;
            size_t g = (size_t)((b << 10) + kb + r) * 512 + hh * 128 + c * 8;
            CP_ASYNC(sb + FL_VH + r * 272 + c * 16, vh + g);
            CP_ASYNC(sb + FL_VL + r * 272 + c * 16, vl + g);
        }
        CP_COMMIT();
    };

    // Q group
#pragma unroll
    for (int t = 0; t < 8; t++) {
        int idx = tid + t * 256;
        int r = idx >> 4, c = idx & 15;
        size_t g = (size_t)((b << 10) + qbase + r) * 512 + hh * 128 + c * 8;
        CP_ASYNC(sb + FL_QH + r * 272 + c * 16, qh + g);
        CP_ASYNC(sb + FL_QL + r * 272 + c * 16, ql + g);
    }
    CP_COMMIT();
    loadK(0);
    loadV(0);

    // bias tables: fused rwh [row][128] -> rwS/rhS pitch 68
    {
        const float4* bsrc = (const float4*)(rwh + ((size_t)z * 1024 + qbase) * 128);
        for (int i = tid; i < 128 * 32; i += 256) {
            int r = i >> 5, c = i & 31;
            float4 v = bsrc[r * 32 + c];
            if (c < 16) *(float4*)&rwS[r * 68 + c * 4]        = v;
            else        *(float4*)&rhS[r * 68 + (c - 16) * 4] = v;
        }
    }

    const int r0 = w * 16 + (lane >> 2);
    const int r1 = r0 + 8;
    const int lq0 = qbase + r0, lq1 = qbase + r1;
    const int xq0 = lq0 & 31, yq0 = lq0 >> 5;
    const int xq1 = lq1 & 31, yq1 = lq1 >> 5;
    const float L2E = 1.4426950408889634f;

    float m0 = -1e30f, m1 = -1e30f, l0 = 0.f, l1 = 0.f;
    float O[16][4];
#pragma unroll
    for (int d = 0; d < 16; d++)
#pragma unroll
        for (int e = 0; e < 4; e++) O[d][e] = 0.f;

    for (int it = 0; it < 16; it++) {
        const int kb = it * 64;

        CP_WAIT1();                     // Q + K(it) ready (V(it) may be in flight)
        __syncthreads();

        // ---- S = Q K^T ----
        float s[8][4];
#pragma unroll
        for (int nt = 0; nt < 8; nt++)
#pragma unroll
            for (int e = 0; e < 4; e++) s[nt][e] = 0.f;

#pragma unroll
        for (int ks = 0; ks < 8; ks++) {
            uint32_t qhf[4], qlf[4];
            uint32_t addrA = sb + FL_QH + (uint32_t)((w * 16 + (lane & 15)) * 272)
                               + (uint32_t)(ks * 32 + (lane >> 4) * 16);
            ldsm4(addrA,                   qhf);
            ldsm4(addrA + (FL_QL - FL_QH), qlf);
            uint32_t bhf[4][4], blf[4][4];
#pragma unroll
            for (int ng = 0; ng < 4; ng++) {
                int row = ng * 16 + ((lane >> 4) << 3) + (lane & 7);
                uint32_t addrB = sb + FL_KH + (uint32_t)(row * 272)
                                   + (uint32_t)(ks * 32 + ((lane >> 3) & 1) * 16);
                ldsm4(addrB,                   bhf[ng]);
                ldsm4(addrB + (FL_KL - FL_KH), blf[ng]);
            }
#pragma unroll
            for (int nt = 0; nt < 8; nt++) {
                int ng = nt >> 1, o = (nt & 1) * 2;
                mma_bf16(s[nt], qhf, bhf[ng][o], bhf[ng][o + 1]);
                mma_bf16(s[nt], qhf, blf[ng][o], blf[ng][o + 1]);
                mma_bf16(s[nt], qlf, bhf[ng][o], bhf[ng][o + 1]);
            }
        }
        __syncthreads();                // all warps done reading K
        if (it < 15) loadK(it + 1);     // overlap with softmax + PV

        // ---- bias + online softmax ----
        float mx0 = m0, mx1 = m1;
#pragma unroll
        for (int nt = 0; nt < 8; nt++) {
            int c0 = kb + nt * 8 + (lane & 3) * 2;
            int c1 = c0 + 1;
            int xk0 = c0 & 31, yk0 = (c0 >> 5) & 31;
            int xk1 = c1 & 31, yk1 = (c1 >> 5) & 31;
            s[nt][0] += rwS[r0 * 68 + xk0 - xq0 + 31] + rhS[r0 * 68 + yk0 - yq0 + 31];
            s[nt][1] += rwS[r0 * 68 + xk1 - xq0 + 31] + rhS[r0 * 68 + yk1 - yq0 + 31];
            s[nt][2] += rwS[r1 * 68 + xk0 - xq1 + 31] + rhS[r1 * 68 + yk0 - yq1 + 31];
            s[nt][3] += rwS[r1 * 68 + xk1 - xq1 + 31] + rhS[r1 * 68 + yk1 - yq1 + 31];
            mx0 = fmaxf(mx0, fmaxf(s[nt][0], s[nt][1]));
            mx1 = fmaxf(mx1, fmaxf(s[nt][2], s[nt][3]));
        }
        mx0 = fmaxf(mx0, __shfl_xor_sync(0xffffffffu, mx0, 1));
        mx0 = fmaxf(mx0, __shfl_xor_sync(0xffffffffu, mx0, 2));
        mx1 = fmaxf(mx1, __shfl_xor_sync(0xffffffffu, mx1, 1));
        mx1 = fmaxf(mx1, __shfl_xor_sync(0xffffffffu, mx1, 2));

        float a0 = exp2f((m0 - mx0) * L2E);
        float a1 = exp2f((m1 - mx1) * L2E);
        m0 = mx0; m1 = mx1;

        float s0 = 0.f, s1 = 0.f;
#pragma unroll
        for (int nt = 0; nt < 8; nt++) {
            s[nt][0] = exp2f((s[nt][0] - m0) * L2E);
            s[nt][1] = exp2f((s[nt][1] - m0) * L2E);
            s[nt][2] = exp2f((s[nt][2] - m1) * L2E);
            s[nt][3] = exp2f((s[nt][3] - m1) * L2E);
            s0 += s[nt][0] + s[nt][1];
            s1 += s[nt][2] + s[nt][3];
        }
        s0 += __shfl_xor_sync(0xffffffffu, s0, 1);
        s0 += __shfl_xor_sync(0xffffffffu, s0, 2);
        s1 += __shfl_xor_sync(0xffffffffu, s1, 1);
        s1 += __shfl_xor_sync(0xffffffffu, s1, 2);
        l0 = l0 * a0 + s0;
        l1 = l1 * a1 + s1;

#pragma unroll
        for (int d = 0; d < 16; d++) {
            O[d][0] *= a0; O[d][1] *= a0;
            O[d][2] *= a1; O[d][3] *= a1;
        }

        if (it < 15) { CP_WAIT1(); } else { CP_WAIT0(); }   // V(it) ready
        __syncthreads();

        // ---- O += P V (V row-major [l][d], B fragments via ldmatrix.trans) ----
#pragma unroll
        for (int ks = 0; ks < 4; ks++) {
            uint32_t pah[4], pal[4];
            {
                __nv_bfloat16 h00,l00,h01,l01,h02,l02,h03,l03;
                __nv_bfloat16 h10,l10,h11,l11,h12,l12,h13,l13;
                bsplit(s[2*ks][0],   h00, l00); bsplit(s[2*ks][1],   h01, l01);
                bsplit(s[2*ks][2],   h02, l02); bsplit(s[2*ks][3],   h03, l03);
                bsplit(s[2*ks+1][0], h10, l10); bsplit(s[2*ks+1][1], h11, l11);
                bsplit(s[2*ks+1][2], h12, l12); bsplit(s[2*ks+1][3], h13, l13);
                pah[0] = packbf(h00, h01); pah[1] = packbf(h02, h03);
                pah[2] = packbf(h10, h11); pah[3] = packbf(h12, h13);
                pal[0] = packbf(l00, l01); pal[1] = packbf(l02, l03);
                pal[2] = packbf(l10, l11); pal[3] = packbf(l12, l13);
            }
            // trans tiles: t0 = (l 0-7, d 0-7), t1 = (l 8-15, d 0-7),
            //              t2 = (l 0-7, d 8-15), t3 = (l 8-15, d 8-15)
            uint32_t vrow = (uint32_t)(ks * 16 + (lane & 7) + (((lane >> 3) & 1) << 3));
            uint32_t vcb  = (uint32_t)((lane >> 4) << 4);
#pragma unroll
            for (int dg = 0; dg < 8; dg++) {
                uint32_t addrV = sb + FL_VH + vrow * 272 + (uint32_t)(dg * 32) + vcb;
                uint32_t vhf[4], vlf[4];
                ldsm4t(addrV,                   vhf);
                ldsm4t(addrV + (FL_VL - FL_VH), vlf);
#pragma unroll
                for (int hf = 0; hf < 2; hf++) {
                    int dnt = dg * 2 + hf, o = hf * 2;
                    mma_bf16(O[dnt], pah, vhf[o], vhf[o + 1]);
                    mma_bf16(O[dnt], pah, vlf[o], vlf[o + 1]);
                    mma_bf16(O[dnt], pal, vhf[o], vhf[o + 1]);
                }
            }
        }
        __syncthreads();                // all warps done reading V
        if (it < 15) loadV(it + 1);     // overlap with next iter's QK
    }

    // ---- normalize + store split bf16 ----
    float inv0 = 1.0f / l0, inv1 = 1.0f / l1;
    size_t row0g = (size_t)((b << 10) + lq0) * 512 + hh * 128;
    size_t row1g = (size_t)((b << 10) + lq1) * 512 + hh * 128;
#pragma unroll
    for (int d = 0; d < 16; d++) {
        int col = d * 8 + (lane & 3) * 2;
        __nv_bfloat16 h0, lo0, h1, lo1;
        bsplit(O[d][0] * inv0, h0, lo0); bsplit(O[d][1] * inv0, h1, lo1);
        *(__nv_bfloat162*)&aoh[row0g + col] = __nv_bfloat162(h0, h1);
        *(__nv_bfloat162*)&aol[row0g + col] = __nv_bfloat162(lo0, lo1);
        bsplit(O[d][2] * inv1, h0, lo0); bsplit(O[d][3] * inv1, h1, lo1);
        *(__nv_bfloat162*)&aoh[row1g + col] = __nv_bfloat162(h0, h1);
        *(__nv_bfloat162*)&aol[row1g + col] = __nv_bfloat162(lo0, lo1);
    }
}

// ---------------------------------------------------------------------------
// x -> bf16 hi/lo split
// ---------------------------------------------------------------------------
__global__ __launch_bounds__(256) void splitx(const float* __restrict__ x,
                                              __nv_bfloat16* __restrict__ xh,
                                              __nv_bfloat16* __restrict__ xl, int n4)
{
    for (int i = blockIdx.x * 256 + threadIdx.x; i < n4; i += gridDim.x * 256) {
        float4 v = ((const float4*)x)[i];
        __nv_bfloat16 h0,l0,h1,l1,h2,l2,h3,l3;
        bsplit(v.x,h0,l0); bsplit(v.y,h1,l1); bsplit(v.z,h2,l2); bsplit(v.w,h3,l3);
        ((__nv_bfloat162*)xh)[i*2]   = __nv_bfloat162(h0,h1);
        ((__nv_bfloat162*)xh)[i*2+1] = __nv_bfloat162(h2,h3);
        ((__nv_bfloat162*)xl)[i*2]   = __nv_bfloat162(l0,l1);
        ((__nv_bfloat162*)xl)[i*2+1] = __nv_bfloat162(l2,l3);
    }
}

// ---------------------------------------------------------------------------
// Merged weight prep: z<4 -> transpose+split weight z; z==4 -> pos tables.
// grid (16,16,5), block (32,8).
// ---------------------------------------------------------------------------
__global__ void wprep(const float* __restrict__ Wq, const float* __restrict__ Wk,
                      const float* __restrict__ Wv, const float* __restrict__ Wo,
                      const float* __restrict__ pew, const float* __restrict__ peh,
                      __nv_bfloat16* __restrict__ wqh, __nv_bfloat16* __restrict__ wql,
                      __nv_bfloat16* __restrict__ wkh, __nv_bfloat16* __restrict__ wkl,
                      __nv_bfloat16* __restrict__ wvh, __nv_bfloat16* __restrict__ wvl,
                      __nv_bfloat16* __restrict__ woh, __nv_bfloat16* __restrict__ wol,
                      __nv_bfloat16* __restrict__ pbh, __nv_bfloat16* __restrict__ pbl)
{
    const int zz = blockIdx.z;
    if (zz < 4) {
        const float* W = zz == 0 ? Wq : zz == 1 ? Wk : zz == 2 ? Wv : Wo;
        __nv_bfloat16* th = zz == 0 ? wqh : zz == 1 ? wkh : zz == 2 ? wvh : woh;
        __nv_bfloat16* tl = zz == 0 ? wql : zz == 1 ? wkl : zz == 2 ? wvl : wol;
        __shared__ float t[32][33];
        int x = blockIdx.x * 32 + threadIdx.x;
        int y = blockIdx.y * 32 + threadIdx.y;
#pragma unroll
        for (int j = 0; j < 32; j += 8)
            t[threadIdx.y + j][threadIdx.x] = W[(size_t)(y + j) * 512 + x];
        __syncthreads();
        int x2 = blockIdx.y * 32 + threadIdx.x;
        int y2 = blockIdx.x * 32 + threadIdx.y;
#pragma unroll
        for (int j = 0; j < 32; j += 8) {
            float val = t[threadIdx.x][threadIdx.y + j];
            __nv_bfloat16 h, l;
            bsplit(val, h, l);
            size_t o = (size_t)(y2 + j) * 512 + x2;
            th[o] = h; tl[o] = l;
        }
    } else {
        int blk = blockIdx.y * 16 + blockIdx.x;
        if (blk >= 64) return;
        int i = blk * 256 + threadIdx.y * 32 + threadIdx.x;
        int n = i >> 7, k = i & 127;
        float v = 0.f;
        if (n < NREL)                 v = pew[k * NREL + n];
        else if (n >= 64 && n < 127)  v = peh[k * NREL + (n - 64)];
        __nv_bfloat16 h, l;
        bsplit(v, h, l);
        pbh[i] = h; pbl[i] = l;
    }
}

// ---------------------------------------------------------------------------
extern "C" void kernel_launch(void* const* d_in, const int* in_sizes, int n_in,
                              void* d_out, int out_size)
{
    const float* x   = (const float*)d_in[0];
    const float* Wq  = (const float*)d_in[1];
    const float* Wk  = (const float*)d_in[2];
    const float* Wv  = (const float*)d_in[3];
    const float* Wo  = (const float*)d_in[4];
    const float* pew = (const float*)d_in[5];
    const float* peh = (const float*)d_in[6];
    float* out = (float*)d_out;

    float* rwhp;
    __nv_bfloat16 *xh,*xl,*qh,*ql,*kh,*kl,*vh,*vl,*aoh,*aol,*pbh,*pbl;
    __nv_bfloat16 *wqh,*wql,*wkh,*wkl,*wvh,*wvl,*woh,*wol;
    cudaGetSymbolAddress((void**)&rwhp, g_rwh);
    cudaGetSymbolAddress((void**)&xh,  g_xh);  cudaGetSymbolAddress((void**)&xl,  g_xl);
    cudaGetSymbolAddress((void**)&qh,  g_qh);  cudaGetSymbolAddress((void**)&ql,  g_ql);
    cudaGetSymbolAddress((void**)&kh,  g_kh);  cudaGetSymbolAddress((void**)&kl,  g_kl);
    cudaGetSymbolAddress((void**)&vh,  g_vh);  cudaGetSymbolAddress((void**)&vl,  g_vl);
    cudaGetSymbolAddress((void**)&aoh, g_aoh); cudaGetSymbolAddress((void**)&aol, g_aol);
    cudaGetSymbolAddress((void**)&pbh, g_pbh); cudaGetSymbolAddress((void**)&pbl, g_pbl);
    cudaGetSymbolAddress((void**)&wqh, g_wqh); cudaGetSymbolAddress((void**)&wql, g_wql);
    cudaGetSymbolAddress((void**)&wkh, g_wkh); cudaGetSymbolAddress((void**)&wkl, g_wkl);
    cudaGetSymbolAddress((void**)&wvh, g_wvh); cudaGetSymbolAddress((void**)&wvl, g_wvl);
    cudaGetSymbolAddress((void**)&woh, g_woh); cudaGetSymbolAddress((void**)&wol, g_wol);

    cudaFuncSetAttribute(gemm_bs,  cudaFuncAttributeMaxDynamicSharedMemorySize, GEMM_SMEM);
    cudaFuncSetAttribute(gemm_qkv, cudaFuncAttributeMaxDynamicSharedMemorySize, GEMM_SMEM);
    cudaFuncSetAttribute(flash,    cudaFuncAttributeMaxDynamicSharedMemorySize, FLASH_SMEM);

    const float scale = 0.08838834764831845f;   // 1/sqrt(128)

    // #1: input split
    splitx<<<1024, 256>>>(x, xh, xl, 8192*512/4);
    // #2: all weight prep (4 transposes + pos tables)
    wprep<<<dim3(16, 16, 5), dim3(32, 8)>>>(Wq, Wk, Wv, Wo, pew, peh,
        wqh, wql, wkh, wkl, wvh, wvl, woh, wol, pbh, pbl);
    // #3: fused QKV projections
    gemm_qkv<<<dim3(12, 64), 256, GEMM_SMEM>>>(xh, xl,
        wqh, wql, wkh, wkl, wvh, wvl, qh, ql, kh, kl, vh, vl, scale);
    // #4: relpos as batched GEMM: RW|RH [z, l, 128] = q[z,l,:] @ [posW|posH]
    gemm_bs<<<dim3(1, 8, 32), 256, GEMM_SMEM>>>(
        qh, ql, 512, 524288LL, 128LL,
        pbh, pbl, 128, 0, 0,
        rwhp, 128, 524288LL, 131072LL,
        4, 1.0f);
    // #5: flash attention (profiled launch)
    flash<<<dim3(8, 1, 32), 256, FLASH_SMEM>>>(qh, ql, kh, kl, vh, vl, rwhp, aoh, aol);
    // #6: output projection
    gemm_bs<<<dim3(4, 64, 1), 256, GEMM_SMEM>>>(
        aoh, aol, 512, 0, 0, woh, wol, 512, 0, 0,
        out, 512, 0, 0, 16, 1.0f);
}

// round 9
// speedup vs baseline: 3.1582x; 1.0657x over previous
#include <cuda_runtime.h>
#include <cuda_bf16.h>
#include <cstdint>

// Problem constants
#define BB     8
#define LL     1024
#define HEADS  4
#define KD     128
#define EMB    512
#define NREL   63

// ---------------------------------------------------------------------------
// Device-global scratch (no allocations allowed)
// ---------------------------------------------------------------------------
__device__ float          g_rwh[32*1024*128];        // fused RW|RH bias, pitch 128
__device__ __nv_bfloat16  g_xh [BB*LL*EMB], g_xl [BB*LL*EMB];
__device__ __nv_bfloat16  g_qh [BB*LL*EMB], g_ql [BB*LL*EMB];
__device__ __nv_bfloat16  g_kh [BB*LL*EMB], g_kl [BB*LL*EMB];
__device__ __nv_bfloat16  g_vh [BB*LL*EMB], g_vl [BB*LL*EMB];
__device__ __nv_bfloat16  g_aoh[BB*LL*EMB], g_aol[BB*LL*EMB];
__device__ __nv_bfloat16  g_wqh[EMB*EMB], g_wql[EMB*EMB];
__device__ __nv_bfloat16  g_wkh[EMB*EMB], g_wkl[EMB*EMB];
__device__ __nv_bfloat16  g_wvh[EMB*EMB], g_wvl[EMB*EMB];
__device__ __nv_bfloat16  g_woh[EMB*EMB], g_wol[EMB*EMB];
__device__ __nv_bfloat16  g_pbh[128*128], g_pbl[128*128];   // padded [posW|posH]^T

// ---------------------------------------------------------------------------
// PTX helpers
// ---------------------------------------------------------------------------
__device__ __forceinline__ uint32_t smem_u32(const void* p) {
    uint32_t a;
    asm("{ .reg .u64 t; cvta.to.shared.u64 t, %1; cvt.u32.u64 %0, t; }" : "=r"(a) : "l"(p));
    return a;
}
__device__ __forceinline__ void ldsm4(uint32_t addr, uint32_t* r) {
    asm volatile("ldmatrix.sync.aligned.m8n8.x4.shared.b16 {%0,%1,%2,%3}, [%4];"
                 : "=r"(r[0]), "=r"(r[1]), "=r"(r[2]), "=r"(r[3]) : "r"(addr));
}
__device__ __forceinline__ void ldsm4t(uint32_t addr, uint32_t* r) {
    asm volatile("ldmatrix.sync.aligned.m8n8.x4.trans.shared.b16 {%0,%1,%2,%3}, [%4];"
                 : "=r"(r[0]), "=r"(r[1]), "=r"(r[2]), "=r"(r[3]) : "r"(addr));
}
__device__ __forceinline__ void mma_bf16(float* d, const uint32_t* a, uint32_t b0, uint32_t b1) {
    asm volatile("mma.sync.aligned.m16n8k16.row.col.f32.bf16.bf16.f32 "
                 "{%0,%1,%2,%3}, {%4,%5,%6,%7}, {%8,%9}, {%0,%1,%2,%3};"
                 : "+f"(d[0]), "+f"(d[1]), "+f"(d[2]), "+f"(d[3])
                 : "r"(a[0]), "r"(a[1]), "r"(a[2]), "r"(a[3]), "r"(b0), "r"(b1));
}
#define CP_ASYNC(dst, src) asm volatile("cp.async.ca.shared.global [%0], [%1], 16;" :: "r"(dst), "l"(src))
#define CP_COMMIT()        asm volatile("cp.async.commit_group;" ::: "memory")
#define CP_WAIT1()         asm volatile("cp.async.wait_group 1;" ::: "memory")
#define CP_WAIT0()         asm volatile("cp.async.wait_group 0;" ::: "memory")

__device__ __forceinline__ void bsplit(float x, __nv_bfloat16& h, __nv_bfloat16& l) {
    h = __float2bfloat16_rn(x);
    l = __float2bfloat16_rn(x - __bfloat162float(h));
}
__device__ __forceinline__ uint32_t packbf(__nv_bfloat16 a, __nv_bfloat16 b) {
    __nv_bfloat162 t(a, b);
    return *(uint32_t*)&t;
}

// ---------------------------------------------------------------------------
// Shared GEMM machinery constants (2-stage now: 80 KB -> 2 CTAs/SM)
// ---------------------------------------------------------------------------
#define STG_BYTES 40960
#define TILE_P    10240
#define GEMM_SMEM (2 * STG_BYTES)

// ---------------------------------------------------------------------------
// bf16-split pipelined mma GEMM (generic, fp32 out): C = (A@B^T)*scale
// 128x128 tile, BK=32, 2-stage, 8 warps (wm 0..3 x 32m, wn 0..1 x 64n).
// Batched: off = (z>>2)*str1 + (z&3)*str2 per operand.
// ---------------------------------------------------------------------------
__global__ __launch_bounds__(256, 2) void gemm_bs(
    const __nv_bfloat16* __restrict__ Ahi, const __nv_bfloat16* __restrict__ Alo,
    int lda, long long strA1, long long strA2,
    const __nv_bfloat16* __restrict__ Bhi, const __nv_bfloat16* __restrict__ Blo,
    int ldb, long long strB1, long long strB2,
    float* __restrict__ Cf,
    int ldc, long long strC1, long long strC2,
    int kIters, float scale)
{
    extern __shared__ char smem[];
    const uint32_t sb0 = smem_u32(smem);
    const int tid  = threadIdx.x;
    const int lane = tid & 31;
    const int wid  = tid >> 5;
    const int wm   = wid >> 1;
    const int wn   = wid & 1;
    const int n0   = blockIdx.x * 128;
    const int m0   = blockIdx.y * 128;
    const int z    = blockIdx.z;

    const size_t offA = (size_t)(z >> 2) * strA1 + (size_t)(z & 3) * strA2;
    const size_t offB = (size_t)(z >> 2) * strB1 + (size_t)(z & 3) * strB2;
    const size_t offC = (size_t)(z >> 2) * strC1 + (size_t)(z & 3) * strC2;

    const __nv_bfloat16* aH = Ahi + offA + (size_t)m0 * lda;
    const __nv_bfloat16* aL = Alo + offA + (size_t)m0 * lda;
    const __nv_bfloat16* bH = Bhi + offB + (size_t)n0 * ldb;
    const __nv_bfloat16* bL = Blo + offB + (size_t)n0 * ldb;

    auto issue = [&](int c, int stg) {
        const uint32_t sb = sb0 + stg * STG_BYTES;
        const int k0 = c * 32;
#pragma unroll
        for (int i = 0; i < 2; i++) {
            int o  = tid + i * 256;
            int r  = o >> 2;
            int ch = o & 3;
            uint32_t d = sb + r * 80 + ch * 16;
            const __nv_bfloat16* s;
            s = aH + (size_t)r * lda + k0 + ch * 8; CP_ASYNC(d,            s);
            s = aL + (size_t)r * lda + k0 + ch * 8; CP_ASYNC(d + TILE_P,   s);
            s = bH + (size_t)r * ldb + k0 + ch * 8; CP_ASYNC(d + 2*TILE_P, s);
            s = bL + (size_t)r * ldb + k0 + ch * 8; CP_ASYNC(d + 3*TILE_P, s);
        }
        CP_COMMIT();
    };

    issue(0, 0);
    if (kIters > 1) issue(1, 1);

    float acc[2][8][4];
#pragma unroll
    for (int mt = 0; mt < 2; mt++)
#pragma unroll
        for (int nt = 0; nt < 8; nt++)
#pragma unroll
            for (int e = 0; e < 4; e++) acc[mt][nt][e] = 0.f;

    for (int c = 0; c < kIters; c++) {
        CP_WAIT1();
        __syncthreads();

        const uint32_t sb = sb0 + (c & 1) * STG_BYTES;
#pragma unroll
        for (int s = 0; s < 2; s++) {
            uint32_t ahf[2][4], alf[2][4];
#pragma unroll
            for (int mt = 0; mt < 2; mt++) {
                uint32_t addr = sb + (uint32_t)((wm * 32 + mt * 16 + (lane & 15)) * 80)
                                   + (uint32_t)((s * 2 + (lane >> 4)) << 4);
                ldsm4(addr,          ahf[mt]);
                ldsm4(addr + TILE_P, alf[mt]);
            }
#pragma unroll
            for (int ng = 0; ng < 4; ng++) {
                int row = wn * 64 + ng * 16 + ((lane >> 4) << 3) + (lane & 7);
                uint32_t addr = sb + 2 * TILE_P + (uint32_t)(row * 80)
                                   + (uint32_t)((s * 2 + ((lane >> 3) & 1)) << 4);
                uint32_t bhf[4], blf[4];
                ldsm4(addr,          bhf);
                ldsm4(addr + TILE_P, blf);
#pragma unroll
                for (int hf = 0; hf < 2; hf++) {
                    int nt = ng * 2 + hf, o = hf * 2;
#pragma unroll
                    for (int mt = 0; mt < 2; mt++) {
                        mma_bf16(acc[mt][nt], ahf[mt], bhf[o], bhf[o + 1]);
                        mma_bf16(acc[mt][nt], ahf[mt], blf[o], blf[o + 1]);
                        mma_bf16(acc[mt][nt], alf[mt], bhf[o], bhf[o + 1]);
                    }
                }
            }
        }
        __syncthreads();
        if (c + 2 < kIters) issue(c + 2, c & 1);
    }

    const int rr  = lane >> 2;
    const int cp2 = (lane & 3) * 2;
    float* Cfb = Cf + offC;
#pragma unroll
    for (int mt = 0; mt < 2; mt++) {
        int row0 = m0 + wm * 32 + mt * 16 + rr;
        int row1 = row0 + 8;
#pragma unroll
        for (int nt = 0; nt < 8; nt++) {
            int col = n0 + wn * 64 + nt * 8 + cp2;
            *(float2*)&Cfb[(size_t)row0 * ldc + col] =
                make_float2(acc[mt][nt][0] * scale, acc[mt][nt][1] * scale);
            *(float2*)&Cfb[(size_t)row1 * ldc + col] =
                make_float2(acc[mt][nt][2] * scale, acc[mt][nt][3] * scale);
        }
    }
}

// ---------------------------------------------------------------------------
// Fused QKV projection GEMM (split bf16 out). grid (12, 64):
// bx>>2 selects {Q,K,V}; n0 = (bx&3)*128 within the projection.
// ---------------------------------------------------------------------------
__global__ __launch_bounds__(256, 2) void gemm_qkv(
    const __nv_bfloat16* __restrict__ xh, const __nv_bfloat16* __restrict__ xl,
    const __nv_bfloat16* __restrict__ wqh, const __nv_bfloat16* __restrict__ wql,
    const __nv_bfloat16* __restrict__ wkh, const __nv_bfloat16* __restrict__ wkl,
    const __nv_bfloat16* __restrict__ wvh, const __nv_bfloat16* __restrict__ wvl,
    __nv_bfloat16* __restrict__ qh, __nv_bfloat16* __restrict__ ql,
    __nv_bfloat16* __restrict__ kh, __nv_bfloat16* __restrict__ kl,
    __nv_bfloat16* __restrict__ vh, __nv_bfloat16* __restrict__ vl,
    float qscale)
{
    extern __shared__ char smem[];
    const uint32_t sb0 = smem_u32(smem);
    const int tid  = threadIdx.x;
    const int lane = tid & 31;
    const int wid  = tid >> 5;
    const int wm   = wid >> 1;
    const int wn   = wid & 1;
    const int sel  = blockIdx.x >> 2;
    const int n0   = (blockIdx.x & 3) * 128;
    const int m0   = blockIdx.y * 128;

    const __nv_bfloat16* Bhi = sel == 0 ? wqh : sel == 1 ? wkh : wvh;
    const __nv_bfloat16* Blo = sel == 0 ? wql : sel == 1 ? wkl : wvl;
    __nv_bfloat16* Chi = sel == 0 ? qh : sel == 1 ? kh : vh;
    __nv_bfloat16* Clo = sel == 0 ? ql : sel == 1 ? kl : vl;
    const float scale = sel == 0 ? qscale : 1.0f;

    const __nv_bfloat16* aH = xh  + (size_t)m0 * 512;
    const __nv_bfloat16* aL = xl  + (size_t)m0 * 512;
    const __nv_bfloat16* bH = Bhi + (size_t)n0 * 512;
    const __nv_bfloat16* bL = Blo + (size_t)n0 * 512;

    auto issue = [&](int c, int stg) {
        const uint32_t sb = sb0 + stg * STG_BYTES;
        const int k0 = c * 32;
#pragma unroll
        for (int i = 0; i < 2; i++) {
            int o  = tid + i * 256;
            int r  = o >> 2;
            int ch = o & 3;
            uint32_t d = sb + r * 80 + ch * 16;
            const __nv_bfloat16* s;
            s = aH + (size_t)r * 512 + k0 + ch * 8; CP_ASYNC(d,            s);
            s = aL + (size_t)r * 512 + k0 + ch * 8; CP_ASYNC(d + TILE_P,   s);
            s = bH + (size_t)r * 512 + k0 + ch * 8; CP_ASYNC(d + 2*TILE_P, s);
            s = bL + (size_t)r * 512 + k0 + ch * 8; CP_ASYNC(d + 3*TILE_P, s);
        }
        CP_COMMIT();
    };

    issue(0, 0);
    issue(1, 1);

    float acc[2][8][4];
#pragma unroll
    for (int mt = 0; mt < 2; mt++)
#pragma unroll
        for (int nt = 0; nt < 8; nt++)
#pragma unroll
            for (int e = 0; e < 4; e++) acc[mt][nt][e] = 0.f;

    for (int c = 0; c < 16; c++) {
        CP_WAIT1();
        __syncthreads();

        const uint32_t sb = sb0 + (c & 1) * STG_BYTES;
#pragma unroll
        for (int s = 0; s < 2; s++) {
            uint32_t ahf[2][4], alf[2][4];
#pragma unroll
            for (int mt = 0; mt < 2; mt++) {
                uint32_t addr = sb + (uint32_t)((wm * 32 + mt * 16 + (lane & 15)) * 80)
                                   + (uint32_t)((s * 2 + (lane >> 4)) << 4);
                ldsm4(addr,          ahf[mt]);
                ldsm4(addr + TILE_P, alf[mt]);
            }
#pragma unroll
            for (int ng = 0; ng < 4; ng++) {
                int row = wn * 64 + ng * 16 + ((lane >> 4) << 3) + (lane & 7);
                uint32_t addr = sb + 2 * TILE_P + (uint32_t)(row * 80)
                                   + (uint32_t)((s * 2 + ((lane >> 3) & 1)) << 4);
                uint32_t bhf[4], blf[4];
                ldsm4(addr,          bhf);
                ldsm4(addr + TILE_P, blf);
#pragma unroll
                for (int hf = 0; hf < 2; hf++) {
                    int nt = ng * 2 + hf, o = hf * 2;
#pragma unroll
                    for (int mt = 0; mt < 2; mt++) {
                        mma_bf16(acc[mt][nt], ahf[mt], bhf[o], bhf[o + 1]);
                        mma_bf16(acc[mt][nt], ahf[mt], blf[o], blf[o + 1]);
                        mma_bf16(acc[mt][nt], alf[mt], bhf[o], bhf[o + 1]);
                    }
                }
            }
        }
        __syncthreads();
        if (c + 2 < 16) issue(c + 2, c & 1);
    }

    const int rr  = lane >> 2;
    const int cp2 = (lane & 3) * 2;
#pragma unroll
    for (int mt = 0; mt < 2; mt++) {
        int row0 = m0 + wm * 32 + mt * 16 + rr;
        int row1 = row0 + 8;
#pragma unroll
        for (int nt = 0; nt < 8; nt++) {
            int col = n0 + wn * 64 + nt * 8 + cp2;
            __nv_bfloat16 h0, l0, h1, l1;
            bsplit(acc[mt][nt][0] * scale, h0, l0); bsplit(acc[mt][nt][1] * scale, h1, l1);
            *(__nv_bfloat162*)&Chi[(size_t)row0 * 512 + col] = __nv_bfloat162(h0, h1);
            *(__nv_bfloat162*)&Clo[(size_t)row0 * 512 + col] = __nv_bfloat162(l0, l1);
            bsplit(acc[mt][nt][2] * scale, h0, l0); bsplit(acc[mt][nt][3] * scale, h1, l1);
            *(__nv_bfloat162*)&Chi[(size_t)row1 * 512 + col] = __nv_bfloat162(h0, h1);
            *(__nv_bfloat162*)&Clo[(size_t)row1 * 512 + col] = __nv_bfloat162(l0, l1);
        }
    }
}

// ---------------------------------------------------------------------------
// Fused flash attention, pipelined loads. V consumed ROW-MAJOR via ldsm.trans.
// CTA = (qtile 0..7, z=b*4+h), 128 q-rows, 64-key window x 16 iters, 8 warps.
// ---------------------------------------------------------------------------
#define FL_QH 0
#define FL_QL 34816
#define FL_KH 69632
#define FL_KL 87040
#define FL_VH 104448
#define FL_VL 121856
#define FL_RW 139264                      // float[128][68]
#define FL_RH (139264 + 34816)
#define FLASH_SMEM (139264 + 2 * 34816)   // 208896

__global__ __launch_bounds__(256) void flash(
    const __nv_bfloat16* __restrict__ qh, const __nv_bfloat16* __restrict__ ql,
    const __nv_bfloat16* __restrict__ kh, const __nv_bfloat16* __restrict__ kl,
    const __nv_bfloat16* __restrict__ vh, const __nv_bfloat16* __restrict__ vl,
    const float* __restrict__ rwh,
    __nv_bfloat16* __restrict__ aoh, __nv_bfloat16* __restrict__ aol)
{
    extern __shared__ char smem[];
    const uint32_t sb = smem_u32(smem);
    float* rwS = (float*)(smem + FL_RW);
    float* rhS = (float*)(smem + FL_RH);

    const int tid  = threadIdx.x;
    const int lane = tid & 31;
    const int w    = tid >> 5;
    const int z    = blockIdx.z;
    const int b    = z >> 2;
    const int hh   = z & 3;
    const int qbase = blockIdx.x * 128;

    auto loadK = [&](int it) {
        const int kb = it * 64;
#pragma unroll
        for (int t = 0; t < 4; t++) {
            int idx = tid + t * 256;
            int r = idx >> 4, c = idx & 15;
            size_t g = (size_t)((b << 10) + kb + r) * 512 + hh * 128 + c * 8;
            CP_ASYNC(sb + FL_KH + r * 272 + c * 16, kh + g);
            CP_ASYNC(sb + FL_KL + r * 272 + c * 16, kl + g);
        }
        CP_COMMIT();
    };
    auto loadV = [&](int it) {
        const int kb = it * 64;
#pragma unroll
        for (int t = 0; t < 4; t++) {
            int idx = tid + t * 256;
            int r = idx >> 4, c = idx & 15;
            size_t g = (size_t)((b << 10) + kb + r) * 512 + hh * 128 + c * 8;
            CP_ASYNC(sb + FL_VH + r * 272 + c * 16, vh + g);
            CP_ASYNC(sb + FL_VL + r * 272 + c * 16, vl + g);
        }
        CP_COMMIT();
    };

    // Q group
#pragma unroll
    for (int t = 0; t < 8; t++) {
        int idx = tid + t * 256;
        int r = idx >> 4, c = idx & 15;
        size_t g = (size_t)((b << 10) + qbase + r) * 512 + hh * 128 + c * 8;
        CP_ASYNC(sb + FL_QH + r * 272 + c * 16, qh + g);
        CP_ASYNC(sb + FL_QL + r * 272 + c * 16, ql + g);
    }
    CP_COMMIT();
    loadK(0);
    loadV(0);

    // bias tables: fused rwh [row][128] -> rwS/rhS pitch 68
    {
        const float4* bsrc = (const float4*)(rwh + ((size_t)z * 1024 + qbase) * 128);
        for (int i = tid; i < 128 * 32; i += 256) {
            int r = i >> 5, c = i & 31;
            float4 v = bsrc[r * 32 + c];
            if (c < 16) *(float4*)&rwS[r * 68 + c * 4]        = v;
            else        *(float4*)&rhS[r * 68 + (c - 16) * 4] = v;
        }
    }

    const int r0 = w * 16 + (lane >> 2);
    const int r1 = r0 + 8;
    const int lq0 = qbase + r0, lq1 = qbase + r1;
    const int xq0 = lq0 & 31, yq0 = lq0 >> 5;
    const int xq1 = lq1 & 31, yq1 = lq1 >> 5;
    const float L2E = 1.4426950408889634f;

    float m0 = -1e30f, m1 = -1e30f, l0 = 0.f, l1 = 0.f;
    float O[16][4];
#pragma unroll
    for (int d = 0; d < 16; d++)
#pragma unroll
        for (int e = 0; e < 4; e++) O[d][e] = 0.f;

    for (int it = 0; it < 16; it++) {
        const int kb = it * 64;

        CP_WAIT1();                     // Q + K(it) ready (V(it) may be in flight)
        __syncthreads();

        // ---- S = Q K^T ----
        float s[8][4];
#pragma unroll
        for (int nt = 0; nt < 8; nt++)
#pragma unroll
            for (int e = 0; e < 4; e++) s[nt][e] = 0.f;

#pragma unroll
        for (int ks = 0; ks < 8; ks++) {
            uint32_t qhf[4], qlf[4];
            uint32_t addrA = sb + FL_QH + (uint32_t)((w * 16 + (lane & 15)) * 272)
                               + (uint32_t)(ks * 32 + (lane >> 4) * 16);
            ldsm4(addrA,                   qhf);
            ldsm4(addrA + (FL_QL - FL_QH), qlf);
            uint32_t bhf[4][4], blf[4][4];
#pragma unroll
            for (int ng = 0; ng < 4; ng++) {
                int row = ng * 16 + ((lane >> 4) << 3) + (lane & 7);
                uint32_t addrB = sb + FL_KH + (uint32_t)(row * 272)
                                   + (uint32_t)(ks * 32 + ((lane >> 3) & 1) * 16);
                ldsm4(addrB,                   bhf[ng]);
                ldsm4(addrB + (FL_KL - FL_KH), blf[ng]);
            }
#pragma unroll
            for (int nt = 0; nt < 8; nt++) {
                int ng = nt >> 1, o = (nt & 1) * 2;
                mma_bf16(s[nt], qhf, bhf[ng][o], bhf[ng][o + 1]);
                mma_bf16(s[nt], qhf, blf[ng][o], blf[ng][o + 1]);
                mma_bf16(s[nt], qlf, bhf[ng][o], bhf[ng][o + 1]);
            }
        }
        __syncthreads();                // all warps done reading K
        if (it < 15) loadK(it + 1);     // overlap with softmax + PV

        // ---- bias + online softmax ----
        float mx0 = m0, mx1 = m1;
#pragma unroll
        for (int nt = 0; nt < 8; nt++) {
            int c0 = kb + nt * 8 + (lane & 3) * 2;
            int c1 = c0 + 1;
            int xk0 = c0 & 31, yk0 = (c0 >> 5) & 31;
            int xk1 = c1 & 31, yk1 = (c1 >> 5) & 31;
            s[nt][0] += rwS[r0 * 68 + xk0 - xq0 + 31] + rhS[r0 * 68 + yk0 - yq0 + 31];
            s[nt][1] += rwS[r0 * 68 + xk1 - xq0 + 31] + rhS[r0 * 68 + yk1 - yq0 + 31];
            s[nt][2] += rwS[r1 * 68 + xk0 - xq1 + 31] + rhS[r1 * 68 + yk0 - yq1 + 31];
            s[nt][3] += rwS[r1 * 68 + xk1 - xq1 + 31] + rhS[r1 * 68 + yk1 - yq1 + 31];
            mx0 = fmaxf(mx0, fmaxf(s[nt][0], s[nt][1]));
            mx1 = fmaxf(mx1, fmaxf(s[nt][2], s[nt][3]));
        }
        mx0 = fmaxf(mx0, __shfl_xor_sync(0xffffffffu, mx0, 1));
        mx0 = fmaxf(mx0, __shfl_xor_sync(0xffffffffu, mx0, 2));
        mx1 = fmaxf(mx1, __shfl_xor_sync(0xffffffffu, mx1, 1));
        mx1 = fmaxf(mx1, __shfl_xor_sync(0xffffffffu, mx1, 2));

        float a0 = exp2f((m0 - mx0) * L2E);
        float a1 = exp2f((m1 - mx1) * L2E);
        m0 = mx0; m1 = mx1;

        float s0 = 0.f, s1 = 0.f;
#pragma unroll
        for (int nt = 0; nt < 8; nt++) {
            s[nt][0] = exp2f((s[nt][0] - m0) * L2E);
            s[nt][1] = exp2f((s[nt][1] - m0) * L2E);
            s[nt][2] = exp2f((s[nt][2] - m1) * L2E);
            s[nt][3] = exp2f((s[nt][3] - m1) * L2E);
            s0 += s[nt][0] + s[nt][1];
            s1 += s[nt][2] + s[nt][3];
        }
        s0 += __shfl_xor_sync(0xffffffffu, s0, 1);
        s0 += __shfl_xor_sync(0xffffffffu, s0, 2);
        s1 += __shfl_xor_sync(0xffffffffu, s1, 1);
        s1 += __shfl_xor_sync(0xffffffffu, s1, 2);
        l0 = l0 * a0 + s0;
        l1 = l1 * a1 + s1;

#pragma unroll
        for (int d = 0; d < 16; d++) {
            O[d][0] *= a0; O[d][1] *= a0;
            O[d][2] *= a1; O[d][3] *= a1;
        }

        if (it < 15) { CP_WAIT1(); } else { CP_WAIT0(); }   // V(it) ready
        __syncthreads();

        // ---- O += P V (V row-major [l][d], B fragments via ldmatrix.trans) ----
#pragma unroll
        for (int ks = 0; ks < 4; ks++) {
            uint32_t pah[4], pal[4];
            {
                __nv_bfloat16 h00,l00,h01,l01,h02,l02,h03,l03;
                __nv_bfloat16 h10,l10,h11,l11,h12,l12,h13,l13;
                bsplit(s[2*ks][0],   h00, l00); bsplit(s[2*ks][1],   h01, l01);
                bsplit(s[2*ks][2],   h02, l02); bsplit(s[2*ks][3],   h03, l03);
                bsplit(s[2*ks+1][0], h10, l10); bsplit(s[2*ks+1][1], h11, l11);
                bsplit(s[2*ks+1][2], h12, l12); bsplit(s[2*ks+1][3], h13, l13);
                pah[0] = packbf(h00, h01); pah[1] = packbf(h02, h03);
                pah[2] = packbf(h10, h11); pah[3] = packbf(h12, h13);
                pal[0] = packbf(l00, l01); pal[1] = packbf(l02, l03);
                pal[2] = packbf(l10, l11); pal[3] = packbf(l12, l13);
            }
            // trans tiles: t0 = (l 0-7, d 0-7), t1 = (l 8-15, d 0-7),
            //              t2 = (l 0-7, d 8-15), t3 = (l 8-15, d 8-15)
            uint32_t vrow = (uint32_t)(ks * 16 + (lane & 7) + (((lane >> 3) & 1) << 3));
            uint32_t vcb  = (uint32_t)((lane >> 4) << 4);
#pragma unroll
            for (int dg = 0; dg < 8; dg++) {
                uint32_t addrV = sb + FL_VH + vrow * 272 + (uint32_t)(dg * 32) + vcb;
                uint32_t vhf[4], vlf[4];
                ldsm4t(addrV,                   vhf);
                ldsm4t(addrV + (FL_VL - FL_VH), vlf);
#pragma unroll
                for (int hf = 0; hf < 2; hf++) {
                    int dnt = dg * 2 + hf, o = hf * 2;
                    mma_bf16(O[dnt], pah, vhf[o], vhf[o + 1]);
                    mma_bf16(O[dnt], pah, vlf[o], vlf[o + 1]);
                    mma_bf16(O[dnt], pal, vhf[o], vhf[o + 1]);
                }
            }
        }
        __syncthreads();                // all warps done reading V
        if (it < 15) loadV(it + 1);     // overlap with next iter's QK
    }

    // ---- normalize + store split bf16 ----
    float inv0 = 1.0f / l0, inv1 = 1.0f / l1;
    size_t row0g = (size_t)((b << 10) + lq0) * 512 + hh * 128;
    size_t row1g = (size_t)((b << 10) + lq1) * 512 + hh * 128;
#pragma unroll
    for (int d = 0; d < 16; d++) {
        int col = d * 8 + (lane & 3) * 2;
        __nv_bfloat16 h0, lo0, h1, lo1;
        bsplit(O[d][0] * inv0, h0, lo0); bsplit(O[d][1] * inv0, h1, lo1);
        *(__nv_bfloat162*)&aoh[row0g + col] = __nv_bfloat162(h0, h1);
        *(__nv_bfloat162*)&aol[row0g + col] = __nv_bfloat162(lo0, lo1);
        bsplit(O[d][2] * inv1, h0, lo0); bsplit(O[d][3] * inv1, h1, lo1);
        *(__nv_bfloat162*)&aoh[row1g + col] = __nv_bfloat162(h0, h1);
        *(__nv_bfloat162*)&aol[row1g + col] = __nv_bfloat162(lo0, lo1);
    }
}

// ---------------------------------------------------------------------------
// x -> bf16 hi/lo split
// ---------------------------------------------------------------------------
__global__ __launch_bounds__(256) void splitx(const float* __restrict__ x,
                                              __nv_bfloat16* __restrict__ xh,
                                              __nv_bfloat16* __restrict__ xl, int n4)
{
    for (int i = blockIdx.x * 256 + threadIdx.x; i < n4; i += gridDim.x * 256) {
        float4 v = ((const float4*)x)[i];
        __nv_bfloat16 h0,l0,h1,l1,h2,l2,h3,l3;
        bsplit(v.x,h0,l0); bsplit(v.y,h1,l1); bsplit(v.z,h2,l2); bsplit(v.w,h3,l3);
        ((__nv_bfloat162*)xh)[i*2]   = __nv_bfloat162(h0,h1);
        ((__nv_bfloat162*)xh)[i*2+1] = __nv_bfloat162(h2,h3);
        ((__nv_bfloat162*)xl)[i*2]   = __nv_bfloat162(l0,l1);
        ((__nv_bfloat162*)xl)[i*2+1] = __nv_bfloat162(l2,l3);
    }
}

// ---------------------------------------------------------------------------
// Weight prep: transpose+split weight z. grid (16,16,4), block (32,8).
// ---------------------------------------------------------------------------
__global__ void wprep(const float* __restrict__ Wq, const float* __restrict__ Wk,
                      const float* __restrict__ Wv, const float* __restrict__ Wo,
                      __nv_bfloat16* __restrict__ wqh, __nv_bfloat16* __restrict__ wql,
                      __nv_bfloat16* __restrict__ wkh, __nv_bfloat16* __restrict__ wkl,
                      __nv_bfloat16* __restrict__ wvh, __nv_bfloat16* __restrict__ wvl,
                      __nv_bfloat16* __restrict__ woh, __nv_bfloat16* __restrict__ wol)
{
    const int zz = blockIdx.z;
    const float* W = zz == 0 ? Wq : zz == 1 ? Wk : zz == 2 ? Wv : Wo;
    __nv_bfloat16* th = zz == 0 ? wqh : zz == 1 ? wkh : zz == 2 ? wvh : woh;
    __nv_bfloat16* tl = zz == 0 ? wql : zz == 1 ? wkl : zz == 2 ? wvl : wol;
    __shared__ float t[32][33];
    int x = blockIdx.x * 32 + threadIdx.x;
    int y = blockIdx.y * 32 + threadIdx.y;
#pragma unroll
    for (int j = 0; j < 32; j += 8)
        t[threadIdx.y + j][threadIdx.x] = W[(size_t)(y + j) * 512 + x];
    __syncthreads();
    int x2 = blockIdx.y * 32 + threadIdx.x;
    int y2 = blockIdx.x * 32 + threadIdx.y;
#pragma unroll
    for (int j = 0; j < 32; j += 8) {
        float val = t[threadIdx.x][threadIdx.y + j];
        __nv_bfloat16 h, l;
        bsplit(val, h, l);
        size_t o = (size_t)(y2 + j) * 512 + x2;
        th[o] = h; tl[o] = l;
    }
}

// ---------------------------------------------------------------------------
// Padded [posW | posH]^T -> bf16 hi/lo
// ---------------------------------------------------------------------------
__global__ void posprep(const float* __restrict__ pew, const float* __restrict__ peh,
                        __nv_bfloat16* __restrict__ pbh, __nv_bfloat16* __restrict__ pbl)
{
    int i = blockIdx.x * 256 + threadIdx.x;
    if (i >= 128 * 128) return;
    int n = i >> 7, k = i & 127;
    float v = 0.f;
    if (n < NREL)                 v = pew[k * NREL + n];
    else if (n >= 64 && n < 127)  v = peh[k * NREL + (n - 64)];
    __nv_bfloat16 h, l;
    bsplit(v, h, l);
    pbh[i] = h; pbl[i] = l;
}

// ---------------------------------------------------------------------------
extern "C" void kernel_launch(void* const* d_in, const int* in_sizes, int n_in,
                              void* d_out, int out_size)
{
    const float* x   = (const float*)d_in[0];
    const float* Wq  = (const float*)d_in[1];
    const float* Wk  = (const float*)d_in[2];
    const float* Wv  = (const float*)d_in[3];
    const float* Wo  = (const float*)d_in[4];
    const float* pew = (const float*)d_in[5];
    const float* peh = (const float*)d_in[6];
    float* out = (float*)d_out;

    float* rwhp;
    __nv_bfloat16 *xh,*xl,*qh,*ql,*kh,*kl,*vh,*vl,*aoh,*aol,*pbh,*pbl;
    __nv_bfloat16 *wqh,*wql,*wkh,*wkl,*wvh,*wvl,*woh,*wol;
    cudaGetSymbolAddress((void**)&rwhp, g_rwh);
    cudaGetSymbolAddress((void**)&xh,  g_xh);  cudaGetSymbolAddress((void**)&xl,  g_xl);
    cudaGetSymbolAddress((void**)&qh,  g_qh);  cudaGetSymbolAddress((void**)&ql,  g_ql);
    cudaGetSymbolAddress((void**)&kh,  g_kh);  cudaGetSymbolAddress((void**)&kl,  g_kl);
    cudaGetSymbolAddress((void**)&vh,  g_vh);  cudaGetSymbolAddress((void**)&vl,  g_vl);
    cudaGetSymbolAddress((void**)&aoh, g_aoh); cudaGetSymbolAddress((void**)&aol, g_aol);
    cudaGetSymbolAddress((void**)&pbh, g_pbh); cudaGetSymbolAddress((void**)&pbl, g_pbl);
    cudaGetSymbolAddress((void**)&wqh, g_wqh); cudaGetSymbolAddress((void**)&wql, g_wql);
    cudaGetSymbolAddress((void**)&wkh, g_wkh); cudaGetSymbolAddress((void**)&wkl, g_wkl);
    cudaGetSymbolAddress((void**)&wvh, g_wvh); cudaGetSymbolAddress((void**)&wvl, g_wvl);
    cudaGetSymbolAddress((void**)&woh, g_woh); cudaGetSymbolAddress((void**)&wol, g_wol);

    cudaFuncSetAttribute(gemm_bs,  cudaFuncAttributeMaxDynamicSharedMemorySize, GEMM_SMEM);
    cudaFuncSetAttribute(gemm_qkv, cudaFuncAttributeMaxDynamicSharedMemorySize, GEMM_SMEM);
    cudaFuncSetAttribute(flash,    cudaFuncAttributeMaxDynamicSharedMemorySize, FLASH_SMEM);

    const float scale = 0.08838834764831845f;   // 1/sqrt(128)

    // #1: input split
    splitx<<<1024, 256>>>(x, xh, xl, 8192*512/4);
    // #2: weight transposes
    wprep<<<dim3(16, 16, 4), dim3(32, 8)>>>(Wq, Wk, Wv, Wo,
        wqh, wql, wkh, wkl, wvh, wvl, woh, wol);
    // #3: pos tables
    posprep<<<64, 256>>>(pew, peh, pbh, pbl);
    // #4: fused QKV projections
    gemm_qkv<<<dim3(12, 64), 256, GEMM_SMEM>>>(xh, xl,
        wqh, wql, wkh, wkl, wvh, wvl, qh, ql, kh, kl, vh, vl, scale);
    // #5: relpos as batched GEMM: RW|RH [z, l, 128] = q[z,l,:] @ [posW|posH]
    gemm_bs<<<dim3(1, 8, 32), 256, GEMM_SMEM>>>(
        qh, ql, 512, 524288LL, 128LL,
        pbh, pbl, 128, 0, 0,
        rwhp, 128, 524288LL, 131072LL,
        4, 1.0f);
    // #6: flash attention (profiled launch under -s 5)
    flash<<<dim3(8, 1, 32), 256, FLASH_SMEM>>>(qh, ql, kh, kl, vh, vl, rwhp, aoh, aol);
    // #7: output projection
    gemm_bs<<<dim3(4, 64, 1), 256, GEMM_SMEM>>>(
        aoh, aol, 512, 0, 0, woh, wol, 512, 0, 0,
        out, 512, 0, 0, 16, 1.0f);
}

// round 11
// speedup vs baseline: 3.3510x; 1.0611x over previous
#include <cuda_runtime.h>
#include <cuda_bf16.h>
#include <cstdint>

// Problem constants
#define BB     8
#define LL     1024
#define HEADS  4
#define KD     128
#define EMB    512
#define NREL   63

// ---------------------------------------------------------------------------
// Device-global scratch (no allocations allowed)
// ---------------------------------------------------------------------------
__device__ float          g_rwh[32*1024*128];        // fused RW|RH bias, pitch 128
__device__ __nv_bfloat16  g_xh [BB*LL*EMB], g_xl [BB*LL*EMB];
__device__ __nv_bfloat16  g_qh [BB*LL*EMB], g_ql [BB*LL*EMB];
__device__ __nv_bfloat16  g_kh [BB*LL*EMB], g_kl [BB*LL*EMB];
__device__ __nv_bfloat16  g_vh [BB*LL*EMB], g_vl [BB*LL*EMB];
__device__ __nv_bfloat16  g_aoh[BB*LL*EMB], g_aol[BB*LL*EMB];
__device__ __nv_bfloat16  g_wqh[EMB*EMB], g_wql[EMB*EMB];
__device__ __nv_bfloat16  g_wkh[EMB*EMB], g_wkl[EMB*EMB];
__device__ __nv_bfloat16  g_wvh[EMB*EMB], g_wvl[EMB*EMB];
__device__ __nv_bfloat16  g_woh[EMB*EMB], g_wol[EMB*EMB];
__device__ __nv_bfloat16  g_pbh[128*128], g_pbl[128*128];   // padded [posW|posH]^T

// ---------------------------------------------------------------------------
// PTX helpers
// ---------------------------------------------------------------------------
__device__ __forceinline__ uint32_t smem_u32(const void* p) {
    uint32_t a;
    asm("{ .reg .u64 t; cvta.to.shared.u64 t, %1; cvt.u32.u64 %0, t; }" : "=r"(a) : "l"(p));
    return a;
}
__device__ __forceinline__ void ldsm4(uint32_t addr, uint32_t* r) {
    asm volatile("ldmatrix.sync.aligned.m8n8.x4.shared.b16 {%0,%1,%2,%3}, [%4];"
                 : "=r"(r[0]), "=r"(r[1]), "=r"(r[2]), "=r"(r[3]) : "r"(addr));
}
__device__ __forceinline__ void ldsm4t(uint32_t addr, uint32_t* r) {
    asm volatile("ldmatrix.sync.aligned.m8n8.x4.trans.shared.b16 {%0,%1,%2,%3}, [%4];"
                 : "=r"(r[0]), "=r"(r[1]), "=r"(r[2]), "=r"(r[3]) : "r"(addr));
}
__device__ __forceinline__ void mma_bf16(float* d, const uint32_t* a, uint32_t b0, uint32_t b1) {
    asm volatile("mma.sync.aligned.m16n8k16.row.col.f32.bf16.bf16.f32 "
                 "{%0,%1,%2,%3}, {%4,%5,%6,%7}, {%8,%9}, {%0,%1,%2,%3};"
                 : "+f"(d[0]), "+f"(d[1]), "+f"(d[2]), "+f"(d[3])
                 : "r"(a[0]), "r"(a[1]), "r"(a[2]), "r"(a[3]), "r"(b0), "r"(b1));
}
#define CP_ASYNC(dst, src) asm volatile("cp.async.ca.shared.global [%0], [%1], 16;" :: "r"(dst), "l"(src))
#define CP_COMMIT()        asm volatile("cp.async.commit_group;" ::: "memory")
#define CP_WAIT1()         asm volatile("cp.async.wait_group 1;" ::: "memory")
#define CP_WAIT0()         asm volatile("cp.async.wait_group 0;" ::: "memory")

__device__ __forceinline__ void bsplit(float x, __nv_bfloat16& h, __nv_bfloat16& l) {
    h = __float2bfloat16_rn(x);
    l = __float2bfloat16_rn(x - __bfloat162float(h));
}
__device__ __forceinline__ uint32_t packbf(__nv_bfloat16 a, __nv_bfloat16 b) {
    __nv_bfloat162 t(a, b);
    return *(uint32_t*)&t;
}

// ---------------------------------------------------------------------------
// Shared GEMM machinery constants (2-stage: 80 KB -> 2 CTAs/SM)
// ---------------------------------------------------------------------------
#define STG_BYTES 40960
#define TILE_P    10240
#define GEMM_SMEM (2 * STG_BYTES)

// ---------------------------------------------------------------------------
// bf16-split pipelined mma GEMM (generic, fp32 out): C = (A@B^T)*scale
// ---------------------------------------------------------------------------
__global__ __launch_bounds__(256, 2) void gemm_bs(
    const __nv_bfloat16* __restrict__ Ahi, const __nv_bfloat16* __restrict__ Alo,
    int lda, long long strA1, long long strA2,
    const __nv_bfloat16* __restrict__ Bhi, const __nv_bfloat16* __restrict__ Blo,
    int ldb, long long strB1, long long strB2,
    float* __restrict__ Cf,
    int ldc, long long strC1, long long strC2,
    int kIters, float scale)
{
    extern __shared__ char smem[];
    const uint32_t sb0 = smem_u32(smem);
    const int tid  = threadIdx.x;
    const int lane = tid & 31;
    const int wid  = tid >> 5;
    const int wm   = wid >> 1;
    const int wn   = wid & 1;
    const int n0   = blockIdx.x * 128;
    const int m0   = blockIdx.y * 128;
    const int z    = blockIdx.z;

    const size_t offA = (size_t)(z >> 2) * strA1 + (size_t)(z & 3) * strA2;
    const size_t offB = (size_t)(z >> 2) * strB1 + (size_t)(z & 3) * strB2;
    const size_t offC = (size_t)(z >> 2) * strC1 + (size_t)(z & 3) * strC2;

    const __nv_bfloat16* aH = Ahi + offA + (size_t)m0 * lda;
    const __nv_bfloat16* aL = Alo + offA + (size_t)m0 * lda;
    const __nv_bfloat16* bH = Bhi + offB + (size_t)n0 * ldb;
    const __nv_bfloat16* bL = Blo + offB + (size_t)n0 * ldb;

    auto issue = [&](int c, int stg) {
        const uint32_t sb = sb0 + stg * STG_BYTES;
        const int k0 = c * 32;
#pragma unroll
        for (int i = 0; i < 2; i++) {
            int o  = tid + i * 256;
            int r  = o >> 2;
            int ch = o & 3;
            uint32_t d = sb + r * 80 + ch * 16;
            const __nv_bfloat16* s;
            s = aH + (size_t)r * lda + k0 + ch * 8; CP_ASYNC(d,            s);
            s = aL + (size_t)r * lda + k0 + ch * 8; CP_ASYNC(d + TILE_P,   s);
            s = bH + (size_t)r * ldb + k0 + ch * 8; CP_ASYNC(d + 2*TILE_P, s);
            s = bL + (size_t)r * ldb + k0 + ch * 8; CP_ASYNC(d + 3*TILE_P, s);
        }
        CP_COMMIT();
    };

    issue(0, 0);
    if (kIters > 1) issue(1, 1);

    float acc[2][8][4];
#pragma unroll
    for (int mt = 0; mt < 2; mt++)
#pragma unroll
        for (int nt = 0; nt < 8; nt++)
#pragma unroll
            for (int e = 0; e < 4; e++) acc[mt][nt][e] = 0.f;

    for (int c = 0; c < kIters; c++) {
        CP_WAIT1();
        __syncthreads();

        const uint32_t sb = sb0 + (c & 1) * STG_BYTES;
#pragma unroll
        for (int s = 0; s < 2; s++) {
            uint32_t ahf[2][4], alf[2][4];
#pragma unroll
            for (int mt = 0; mt < 2; mt++) {
                uint32_t addr = sb + (uint32_t)((wm * 32 + mt * 16 + (lane & 15)) * 80)
                                   + (uint32_t)((s * 2 + (lane >> 4)) << 4);
                ldsm4(addr,          ahf[mt]);
                ldsm4(addr + TILE_P, alf[mt]);
            }
#pragma unroll
            for (int ng = 0; ng < 4; ng++) {
                int row = wn * 64 + ng * 16 + ((lane >> 4) << 3) + (lane & 7);
                uint32_t addr = sb + 2 * TILE_P + (uint32_t)(row * 80)
                                   + (uint32_t)((s * 2 + ((lane >> 3) & 1)) << 4);
                uint32_t bhf[4], blf[4];
                ldsm4(addr,          bhf);
                ldsm4(addr + TILE_P, blf);
#pragma unroll
                for (int hf = 0; hf < 2; hf++) {
                    int nt = ng * 2 + hf, o = hf * 2;
#pragma unroll
                    for (int mt = 0; mt < 2; mt++) {
                        mma_bf16(acc[mt][nt], ahf[mt], bhf[o], bhf[o + 1]);
                        mma_bf16(acc[mt][nt], ahf[mt], blf[o], blf[o + 1]);
                        mma_bf16(acc[mt][nt], alf[mt], bhf[o], bhf[o + 1]);
                    }
                }
            }
        }
        __syncthreads();
        if (c + 2 < kIters) issue(c + 2, c & 1);
    }

    const int rr  = lane >> 2;
    const int cp2 = (lane & 3) * 2;
    float* Cfb = Cf + offC;
#pragma unroll
    for (int mt = 0; mt < 2; mt++) {
        int row0 = m0 + wm * 32 + mt * 16 + rr;
        int row1 = row0 + 8;
#pragma unroll
        for (int nt = 0; nt < 8; nt++) {
            int col = n0 + wn * 64 + nt * 8 + cp2;
            *(float2*)&Cfb[(size_t)row0 * ldc + col] =
                make_float2(acc[mt][nt][0] * scale, acc[mt][nt][1] * scale);
            *(float2*)&Cfb[(size_t)row1 * ldc + col] =
                make_float2(acc[mt][nt][2] * scale, acc[mt][nt][3] * scale);
        }
    }
}

// ---------------------------------------------------------------------------
// Fused QKV projection GEMM (split bf16 out). grid (12, 64).
// ---------------------------------------------------------------------------
__global__ __launch_bounds__(256, 2) void gemm_qkv(
    const __nv_bfloat16* __restrict__ xh, const __nv_bfloat16* __restrict__ xl,
    const __nv_bfloat16* __restrict__ wqh, const __nv_bfloat16* __restrict__ wql,
    const __nv_bfloat16* __restrict__ wkh, const __nv_bfloat16* __restrict__ wkl,
    const __nv_bfloat16* __restrict__ wvh, const __nv_bfloat16* __restrict__ wvl,
    __nv_bfloat16* __restrict__ qh, __nv_bfloat16* __restrict__ ql,
    __nv_bfloat16* __restrict__ kh, __nv_bfloat16* __restrict__ kl,
    __nv_bfloat16* __restrict__ vh, __nv_bfloat16* __restrict__ vl,
    float qscale)
{
    extern __shared__ char smem[];
    const uint32_t sb0 = smem_u32(smem);
    const int tid  = threadIdx.x;
    const int lane = tid & 31;
    const int wid  = tid >> 5;
    const int wm   = wid >> 1;
    const int wn   = wid & 1;
    const int sel  = blockIdx.x >> 2;
    const int n0   = (blockIdx.x & 3) * 128;
    const int m0   = blockIdx.y * 128;

    const __nv_bfloat16* Bhi = sel == 0 ? wqh : sel == 1 ? wkh : wvh;
    const __nv_bfloat16* Blo = sel == 0 ? wql : sel == 1 ? wkl : wvl;
    __nv_bfloat16* Chi = sel == 0 ? qh : sel == 1 ? kh : vh;
    __nv_bfloat16* Clo = sel == 0 ? ql : sel == 1 ? kl : vl;
    const float scale = sel == 0 ? qscale : 1.0f;

    const __nv_bfloat16* aH = xh  + (size_t)m0 * 512;
    const __nv_bfloat16* aL = xl  + (size_t)m0 * 512;
    const __nv_bfloat16* bH = Bhi + (size_t)n0 * 512;
    const __nv_bfloat16* bL = Blo + (size_t)n0 * 512;

    auto issue = [&](int c, int stg) {
        const uint32_t sb = sb0 + stg * STG_BYTES;
        const int k0 = c * 32;
#pragma unroll
        for (int i = 0; i < 2; i++) {
            int o  = tid + i * 256;
            int r  = o >> 2;
            int ch = o & 3;
            uint32_t d = sb + r * 80 + ch * 16;
            const __nv_bfloat16* s;
            s = aH + (size_t)r * 512 + k0 + ch * 8; CP_ASYNC(d,            s);
            s = aL + (size_t)r * 512 + k0 + ch * 8; CP_ASYNC(d + TILE_P,   s);
            s = bH + (size_t)r * 512 + k0 + ch * 8; CP_ASYNC(d + 2*TILE_P, s);
            s = bL + (size_t)r * 512 + k0 + ch * 8; CP_ASYNC(d + 3*TILE_P, s);
        }
        CP_COMMIT();
    };

    issue(0, 0);
    issue(1, 1);

    float acc[2][8][4];
#pragma unroll
    for (int mt = 0; mt < 2; mt++)
#pragma unroll
        for (int nt = 0; nt < 8; nt++)
#pragma unroll
            for (int e = 0; e < 4; e++) acc[mt][nt][e] = 0.f;

    for (int c = 0; c < 16; c++) {
        CP_WAIT1();
        __syncthreads();

        const uint32_t sb = sb0 + (c & 1) * STG_BYTES;
#pragma unroll
        for (int s = 0; s < 2; s++) {
            uint32_t ahf[2][4], alf[2][4];
#pragma unroll
            for (int mt = 0; mt < 2; mt++) {
                uint32_t addr = sb + (uint32_t)((wm * 32 + mt * 16 + (lane & 15)) * 80)
                                   + (uint32_t)((s * 2 + (lane >> 4)) << 4);
                ldsm4(addr,          ahf[mt]);
                ldsm4(addr + TILE_P, alf[mt]);
            }
#pragma unroll
            for (int ng = 0; ng < 4; ng++) {
                int row = wn * 64 + ng * 16 + ((lane >> 4) << 3) + (lane & 7);
                uint32_t addr = sb + 2 * TILE_P + (uint32_t)(row * 80)
                                   + (uint32_t)((s * 2 + ((lane >> 3) & 1)) << 4);
                uint32_t bhf[4], blf[4];
                ldsm4(addr,          bhf);
                ldsm4(addr + TILE_P, blf);
#pragma unroll
                for (int hf = 0; hf < 2; hf++) {
                    int nt = ng * 2 + hf, o = hf * 2;
#pragma unroll
                    for (int mt = 0; mt < 2; mt++) {
                        mma_bf16(acc[mt][nt], ahf[mt], bhf[o], bhf[o + 1]);
                        mma_bf16(acc[mt][nt], ahf[mt], blf[o], blf[o + 1]);
                        mma_bf16(acc[mt][nt], alf[mt], bhf[o], bhf[o + 1]);
                    }
                }
            }
        }
        __syncthreads();
        if (c + 2 < 16) issue(c + 2, c & 1);
    }

    const int rr  = lane >> 2;
    const int cp2 = (lane & 3) * 2;
#pragma unroll
    for (int mt = 0; mt < 2; mt++) {
        int row0 = m0 + wm * 32 + mt * 16 + rr;
        int row1 = row0 + 8;
#pragma unroll
        for (int nt = 0; nt < 8; nt++) {
            int col = n0 + wn * 64 + nt * 8 + cp2;
            __nv_bfloat16 h0, l0, h1, l1;
            bsplit(acc[mt][nt][0] * scale, h0, l0); bsplit(acc[mt][nt][1] * scale, h1, l1);
            *(__nv_bfloat162*)&Chi[(size_t)row0 * 512 + col] = __nv_bfloat162(h0, h1);
            *(__nv_bfloat162*)&Clo[(size_t)row0 * 512 + col] = __nv_bfloat162(l0, l1);
            bsplit(acc[mt][nt][2] * scale, h0, l0); bsplit(acc[mt][nt][3] * scale, h1, l1);
            *(__nv_bfloat162*)&Chi[(size_t)row1 * 512 + col] = __nv_bfloat162(h0, h1);
            *(__nv_bfloat162*)&Clo[(size_t)row1 * 512 + col] = __nv_bfloat162(l0, l1);
        }
    }
}

// ---------------------------------------------------------------------------
// Fused flash attention, pipelined loads.
// Bias: RW values preloaded in REGISTERS (loop-invariant per row);
// only 2 RH values per row per iteration come from smem (rhS, pitch 68).
// ---------------------------------------------------------------------------
#define FL_QH 0
#define FL_QL 34816
#define FL_KH 69632
#define FL_KL 87040
#define FL_VH 104448
#define FL_VL 121856
#define FL_RH 139264                      // float[128][68]
#define FLASH_SMEM (139264 + 34816)       // 174080

__global__ __launch_bounds__(256) void flash(
    const __nv_bfloat16* __restrict__ qh, const __nv_bfloat16* __restrict__ ql,
    const __nv_bfloat16* __restrict__ kh, const __nv_bfloat16* __restrict__ kl,
    const __nv_bfloat16* __restrict__ vh, const __nv_bfloat16* __restrict__ vl,
    const float* __restrict__ rwh,
    __nv_bfloat16* __restrict__ aoh, __nv_bfloat16* __restrict__ aol)
{
    extern __shared__ char smem[];
    const uint32_t sb = smem_u32(smem);
    float* rhS = (float*)(smem + FL_RH);

    const int tid  = threadIdx.x;
    const int lane = tid & 31;
    const int w    = tid >> 5;
    const int z    = blockIdx.z;
    const int b    = z >> 2;
    const int hh   = z & 3;
    const int qbase = blockIdx.x * 128;

    auto loadK = [&](int it) {
        const int kb = it * 64;
#pragma unroll
        for (int t = 0; t < 4; t++) {
            int idx = tid + t * 256;
            int r = idx >> 4, c = idx & 15;
            size_t g = (size_t)((b << 10) + kb + r) * 512 + hh * 128 + c * 8;
            CP_ASYNC(sb + FL_KH + r * 272 + c * 16, kh + g);
            CP_ASYNC(sb + FL_KL + r * 272 + c * 16, kl + g);
        }
        CP_COMMIT();
    };
    auto loadV = [&](int it) {
        const int kb = it * 64;
#pragma unroll
        for (int t = 0; t < 4; t++) {
            int idx = tid + t * 256;
            int r = idx >> 4, c = idx & 15;
            size_t g = (size_t)((b << 10) + kb + r) * 512 + hh * 128 + c * 8;
            CP_ASYNC(sb + FL_VH + r * 272 + c * 16, vh + g);
            CP_ASYNC(sb + FL_VL + r * 272 + c * 16, vl + g);
        }
        CP_COMMIT();
    };

    // Q group
#pragma unroll
    for (int t = 0; t < 8; t++) {
        int idx = tid + t * 256;
        int r = idx >> 4, c = idx & 15;
        size_t g = (size_t)((b << 10) + qbase + r) * 512 + hh * 128 + c * 8;
        CP_ASYNC(sb + FL_QH + r * 272 + c * 16, qh + g);
        CP_ASYNC(sb + FL_QL + r * 272 + c * 16, ql + g);
    }
    CP_COMMIT();
    loadK(0);
    loadV(0);

    // rhS: RH half of the fused bias table (cols 64..127) -> pitch 68
    {
        const float4* bsrc = (const float4*)(rwh + ((size_t)z * 1024 + qbase) * 128);
        for (int i = tid; i < 128 * 16; i += 256) {
            int r = i >> 4, c4 = i & 15;
            *(float4*)&rhS[r * 68 + c4 * 4] = bsrc[r * 32 + 16 + c4];
        }
    }

    const int cp  = (lane & 3) * 2;
    const int r0 = w * 16 + (lane >> 2);
    const int r1 = r0 + 8;
    const int lq0 = qbase + r0, lq1 = qbase + r1;
    const int xq0 = lq0 & 31, yq0 = lq0 >> 5;
    const int xq1 = lq1 & 31, yq1 = lq1 >> 5;
    const float L2E = 1.4426950408889634f;

    // RW bias values: loop-invariant per row -> registers (direct gmem read).
    float rw0[8], rw1[8];
    {
        const float* brow0 = rwh + ((size_t)z * 1024 + lq0) * 128;
        const float* brow1 = rwh + ((size_t)z * 1024 + lq1) * 128;
#pragma unroll
        for (int i = 0; i < 4; i++)
#pragma unroll
            for (int e = 0; e < 2; e++) {
                rw0[i * 2 + e] = brow0[8 * i + cp + e - xq0 + 31];
                rw1[i * 2 + e] = brow1[8 * i + cp + e - xq1 + 31];
            }
    }

    float m0 = -1e30f, m1 = -1e30f, l0 = 0.f, l1 = 0.f;
    float O[16][4];
#pragma unroll
    for (int d = 0; d < 16; d++)
#pragma unroll
        for (int e = 0; e < 4; e++) O[d][e] = 0.f;

    for (int it = 0; it < 16; it++) {
        CP_WAIT1();                     // Q + K(it) ready (V(it) may be in flight)
        __syncthreads();

        // ---- S = Q K^T ----
        float s[8][4];
#pragma unroll
        for (int nt = 0; nt < 8; nt++)
#pragma unroll
            for (int e = 0; e < 4; e++) s[nt][e] = 0.f;

#pragma unroll
        for (int ks = 0; ks < 8; ks++) {
            uint32_t qhf[4], qlf[4];
            uint32_t addrA = sb + FL_QH + (uint32_t)((w * 16 + (lane & 15)) * 272)
                               + (uint32_t)(ks * 32 + (lane >> 4) * 16);
            ldsm4(addrA,                   qhf);
            ldsm4(addrA + (FL_QL - FL_QH), qlf);
            uint32_t bhf[4][4], blf[4][4];
#pragma unroll
            for (int ng = 0; ng < 4; ng++) {
                int row = ng * 16 + ((lane >> 4) << 3) + (lane & 7);
                uint32_t addrB = sb + FL_KH + (uint32_t)(row * 272)
                                   + (uint32_t)(ks * 32 + ((lane >> 3) & 1) * 16);
                ldsm4(addrB,                   bhf[ng]);
                ldsm4(addrB + (FL_KL - FL_KH), blf[ng]);
            }
#pragma unroll
            for (int nt = 0; nt < 8; nt++) {
                int ng = nt >> 1, o = (nt & 1) * 2;
                mma_bf16(s[nt], qhf, bhf[ng][o], bhf[ng][o + 1]);
                mma_bf16(s[nt], qhf, blf[ng][o], blf[ng][o + 1]);
                mma_bf16(s[nt], qlf, bhf[ng][o], bhf[ng][o + 1]);
            }
        }
        __syncthreads();                // all warps done reading K
        if (it < 15) loadK(it + 1);     // overlap with softmax + PV

        // ---- bias + online softmax (RH: 4 LDS per thread per iter) ----
        const int j = it * 2;
        float rh0a = rhS[r0 * 68 + j - yq0 + 31];
        float rh0b = rhS[r0 * 68 + j + 1 - yq0 + 31];
        float rh1a = rhS[r1 * 68 + j - yq1 + 31];
        float rh1b = rhS[r1 * 68 + j + 1 - yq1 + 31];

        float mx0 = m0, mx1 = m1;
#pragma unroll
        for (int nt = 0; nt < 8; nt++) {
            const float rh0 = (nt < 4) ? rh0a : rh0b;
            const float rh1 = (nt < 4) ? rh1a : rh1b;
            const int i2 = (nt & 3) * 2;
            s[nt][0] += rw0[i2]     + rh0;
            s[nt][1] += rw0[i2 + 1] + rh0;
            s[nt][2] += rw1[i2]     + rh1;
            s[nt][3] += rw1[i2 + 1] + rh1;
            mx0 = fmaxf(mx0, fmaxf(s[nt][0], s[nt][1]));
            mx1 = fmaxf(mx1, fmaxf(s[nt][2], s[nt][3]));
        }
        mx0 = fmaxf(mx0, __shfl_xor_sync(0xffffffffu, mx0, 1));
        mx0 = fmaxf(mx0, __shfl_xor_sync(0xffffffffu, mx0, 2));
        mx1 = fmaxf(mx1, __shfl_xor_sync(0xffffffffu, mx1, 1));
        mx1 = fmaxf(mx1, __shfl_xor_sync(0xffffffffu, mx1, 2));

        float a0 = exp2f((m0 - mx0) * L2E);
        float a1 = exp2f((m1 - mx1) * L2E);
        m0 = mx0; m1 = mx1;

        float s0 = 0.f, s1 = 0.f;
#pragma unroll
        for (int nt = 0; nt < 8; nt++) {
            s[nt][0] = exp2f((s[nt][0] - m0) * L2E);
            s[nt][1] = exp2f((s[nt][1] - m0) * L2E);
            s[nt][2] = exp2f((s[nt][2] - m1) * L2E);
            s[nt][3] = exp2f((s[nt][3] - m1) * L2E);
            s0 += s[nt][0] + s[nt][1];
            s1 += s[nt][2] + s[nt][3];
        }
        s0 += __shfl_xor_sync(0xffffffffu, s0, 1);
        s0 += __shfl_xor_sync(0xffffffffu, s0, 2);
        s1 += __shfl_xor_sync(0xffffffffu, s1, 1);
        s1 += __shfl_xor_sync(0xffffffffu, s1, 2);
        l0 = l0 * a0 + s0;
        l1 = l1 * a1 + s1;

#pragma unroll
        for (int d = 0; d < 16; d++) {
            O[d][0] *= a0; O[d][1] *= a0;
            O[d][2] *= a1; O[d][3] *= a1;
        }

        if (it < 15) { CP_WAIT1(); } else { CP_WAIT0(); }   // V(it) ready
        __syncthreads();

        // ---- O += P V (V row-major [l][d], B fragments via ldmatrix.trans) ----
#pragma unroll
        for (int ks = 0; ks < 4; ks++) {
            uint32_t pah[4], pal[4];
            {
                __nv_bfloat16 h00,l00,h01,l01,h02,l02,h03,l03;
                __nv_bfloat16 h10,l10,h11,l11,h12,l12,h13,l13;
                bsplit(s[2*ks][0],   h00, l00); bsplit(s[2*ks][1],   h01, l01);
                bsplit(s[2*ks][2],   h02, l02); bsplit(s[2*ks][3],   h03, l03);
                bsplit(s[2*ks+1][0], h10, l10); bsplit(s[2*ks+1][1], h11, l11);
                bsplit(s[2*ks+1][2], h12, l12); bsplit(s[2*ks+1][3], h13, l13);
                pah[0] = packbf(h00, h01); pah[1] = packbf(h02, h03);
                pah[2] = packbf(h10, h11); pah[3] = packbf(h12, h13);
                pal[0] = packbf(l00, l01); pal[1] = packbf(l02, l03);
                pal[2] = packbf(l10, l11); pal[3] = packbf(l12, l13);
            }
            uint32_t vrow = (uint32_t)(ks * 16 + (lane & 7) + (((lane >> 3) & 1) << 3));
            uint32_t vcb  = (uint32_t)((lane >> 4) << 4);
#pragma unroll
            for (int dg = 0; dg < 8; dg++) {
                uint32_t addrV = sb + FL_VH + vrow * 272 + (uint32_t)(dg * 32) + vcb;
                uint32_t vhf[4], vlf[4];
                ldsm4t(addrV,                   vhf);
                ldsm4t(addrV + (FL_VL - FL_VH), vlf);
#pragma unroll
                for (int hf = 0; hf < 2; hf++) {
                    int dnt = dg * 2 + hf, o = hf * 2;
                    mma_bf16(O[dnt], pah, vhf[o], vhf[o + 1]);
                    mma_bf16(O[dnt], pah, vlf[o], vlf[o + 1]);
                    mma_bf16(O[dnt], pal, vhf[o], vhf[o + 1]);
                }
            }
        }
        __syncthreads();                // all warps done reading V
        if (it < 15) loadV(it + 1);     // overlap with next iter's QK
    }

    // ---- normalize + store split bf16 ----
    float inv0 = 1.0f / l0, inv1 = 1.0f / l1;
    size_t row0g = (size_t)((b << 10) + lq0) * 512 + hh * 128;
    size_t row1g = (size_t)((b << 10) + lq1) * 512 + hh * 128;
#pragma unroll
    for (int d = 0; d < 16; d++) {
        int col = d * 8 + cp;
        __nv_bfloat16 h0, lo0, h1, lo1;
        bsplit(O[d][0] * inv0, h0, lo0); bsplit(O[d][1] * inv0, h1, lo1);
        *(__nv_bfloat162*)&aoh[row0g + col] = __nv_bfloat162(h0, h1);
        *(__nv_bfloat162*)&aol[row0g + col] = __nv_bfloat162(lo0, lo1);
        bsplit(O[d][2] * inv1, h0, lo0); bsplit(O[d][3] * inv1, h1, lo1);
        *(__nv_bfloat162*)&aoh[row1g + col] = __nv_bfloat162(h0, h1);
        *(__nv_bfloat162*)&aol[row1g + col] = __nv_bfloat162(lo0, lo1);
    }
}

// ---------------------------------------------------------------------------
// x -> bf16 hi/lo split
// ---------------------------------------------------------------------------
__global__ __launch_bounds__(256) void splitx(const float* __restrict__ x,
                                              __nv_bfloat16* __restrict__ xh,
                                              __nv_bfloat16* __restrict__ xl, int n4)
{
    for (int i = blockIdx.x * 256 + threadIdx.x; i < n4; i += gridDim.x * 256) {
        float4 v = ((const float4*)x)[i];
        __nv_bfloat16 h0,l0,h1,l1,h2,l2,h3,l3;
        bsplit(v.x,h0,l0); bsplit(v.y,h1,l1); bsplit(v.z,h2,l2); bsplit(v.w,h3,l3);
        ((__nv_bfloat162*)xh)[i*2]   = __nv_bfloat162(h0,h1);
        ((__nv_bfloat162*)xh)[i*2+1] = __nv_bfloat162(h2,h3);
        ((__nv_bfloat162*)xl)[i*2]   = __nv_bfloat162(l0,l1);
        ((__nv_bfloat162*)xl)[i*2+1] = __nv_bfloat162(l2,l3);
    }
}

// ---------------------------------------------------------------------------
// Weight prep: transpose+split weight z. grid (16,16,4), block (32,8).
// ---------------------------------------------------------------------------
__global__ void wprep(const float* __restrict__ Wq, const float* __restrict__ Wk,
                      const float* __restrict__ Wv, const float* __restrict__ Wo,
                      __nv_bfloat16* __restrict__ wqh, __nv_bfloat16* __restrict__ wql,
                      __nv_bfloat16* __restrict__ wkh, __nv_bfloat16* __restrict__ wkl,
                      __nv_bfloat16* __restrict__ wvh, __nv_bfloat16* __restrict__ wvl,
                      __nv_bfloat16* __restrict__ woh, __nv_bfloat16* __restrict__ wol)
{
    const int zz = blockIdx.z;
    const float* W = zz == 0 ? Wq : zz == 1 ? Wk : zz == 2 ? Wv : Wo;
    __nv_bfloat16* th = zz == 0 ? wqh : zz == 1 ? wkh : zz == 2 ? wvh : woh;
    __nv_bfloat16* tl = zz == 0 ? wql : zz == 1 ? wkl : zz == 2 ? wvl : wol;
    __shared__ float t[32][33];
    int x = blockIdx.x * 32 + threadIdx.x;
    int y = blockIdx.y * 32 + threadIdx.y;
#pragma unroll
    for (int j = 0; j < 32; j += 8)
        t[threadIdx.y + j][threadIdx.x] = W[(size_t)(y + j) * 512 + x];
    __syncthreads();
    int x2 = blockIdx.y * 32 + threadIdx.x;
    int y2 = blockIdx.x * 32 + threadIdx.y;
#pragma unroll
    for (int j = 0; j < 32; j += 8) {
        float val = t[threadIdx.x][threadIdx.y + j];
        __nv_bfloat16 h, l;
        bsplit(val, h, l);
        size_t o = (size_t)(y2 + j) * 512 + x2;
        th[o] = h; tl[o] = l;
    }
}

// ---------------------------------------------------------------------------
// Padded [posW | posH]^T -> bf16 hi/lo
// ---------------------------------------------------------------------------
__global__ void posprep(const float* __restrict__ pew, const float* __restrict__ peh,
                        __nv_bfloat16* __restrict__ pbh, __nv_bfloat16* __restrict__ pbl)
{
    int i = blockIdx.x * 256 + threadIdx.x;
    if (i >= 128 * 128) return;
    int n = i >> 7, k = i & 127;
    float v = 0.f;
    if (n < NREL)                 v = pew[k * NREL + n];
    else if (n >= 64 && n < 127)  v = peh[k * NREL + (n - 64)];
    __nv_bfloat16 h, l;
    bsplit(v, h, l);
    pbh[i] = h; pbl[i] = l;
}

// ---------------------------------------------------------------------------
extern "C" void kernel_launch(void* const* d_in, const int* in_sizes, int n_in,
                              void* d_out, int out_size)
{
    const float* x   = (const float*)d_in[0];
    const float* Wq  = (const float*)d_in[1];
    const float* Wk  = (const float*)d_in[2];
    const float* Wv  = (const float*)d_in[3];
    const float* Wo  = (const float*)d_in[4];
    const float* pew = (const float*)d_in[5];
    const float* peh = (const float*)d_in[6];
    float* out = (float*)d_out;

    float* rwhp;
    __nv_bfloat16 *xh,*xl,*qh,*ql,*kh,*kl,*vh,*vl,*aoh,*aol,*pbh,*pbl;
    __nv_bfloat16 *wqh,*wql,*wkh,*wkl,*wvh,*wvl,*woh,*wol;
    cudaGetSymbolAddress((void**)&rwhp, g_rwh);
    cudaGetSymbolAddress((void**)&xh,  g_xh);  cudaGetSymbolAddress((void**)&xl,  g_xl);
    cudaGetSymbolAddress((void**)&qh,  g_qh);  cudaGetSymbolAddress((void**)&ql,  g_ql);
    cudaGetSymbolAddress((void**)&kh,  g_kh);  cudaGetSymbolAddress((void**)&kl,  g_kl);
    cudaGetSymbolAddress((void**)&vh,  g_vh);  cudaGetSymbolAddress((void**)&vl,  g_vl);
    cudaGetSymbolAddress((void**)&aoh, g_aoh); cudaGetSymbolAddress((void**)&aol, g_aol);
    cudaGetSymbolAddress((void**)&pbh, g_pbh); cudaGetSymbolAddress((void**)&pbl, g_pbl);
    cudaGetSymbolAddress((void**)&wqh, g_wqh); cudaGetSymbolAddress((void**)&wql, g_wql);
    cudaGetSymbolAddress((void**)&wkh, g_wkh); cudaGetSymbolAddress((void**)&wkl, g_wkl);
    cudaGetSymbolAddress((void**)&wvh, g_wvh); cudaGetSymbolAddress((void**)&wvl, g_wvl);
    cudaGetSymbolAddress((void**)&woh, g_woh); cudaGetSymbolAddress((void**)&wol, g_wol);

    cudaFuncSetAttribute(gemm_bs,  cudaFuncAttributeMaxDynamicSharedMemorySize, GEMM_SMEM);
    cudaFuncSetAttribute(gemm_qkv, cudaFuncAttributeMaxDynamicSharedMemorySize, GEMM_SMEM);
    cudaFuncSetAttribute(flash,    cudaFuncAttributeMaxDynamicSharedMemorySize, FLASH_SMEM);

    const float scale = 0.08838834764831845f;   // 1/sqrt(128)

    // #1: input split
    splitx<<<1024, 256>>>(x, xh, xl, 8192*512/4);
    // #2: weight transposes
    wprep<<<dim3(16, 16, 4), dim3(32, 8)>>>(Wq, Wk, Wv, Wo,
        wqh, wql, wkh, wkl, wvh, wvl, woh, wol);
    // #3: pos tables
    posprep<<<64, 256>>>(pew, peh, pbh, pbl);
    // #4: fused QKV projections
    gemm_qkv<<<dim3(12, 64), 256, GEMM_SMEM>>>(xh, xl,
        wqh, wql, wkh, wkl, wvh, wvl, qh, ql, kh, kl, vh, vl, scale);
    // #5: relpos as batched GEMM: RW|RH [z, l, 128] = q[z,l,:] @ [posW|posH]
    gemm_bs<<<dim3(1, 8, 32), 256, GEMM_SMEM>>>(
        qh, ql, 512, 524288LL, 128LL,
        pbh, pbl, 128, 0, 0,
        rwhp, 128, 524288LL, 131072LL,
        4, 1.0f);
    // #6: flash attention (profiled launch under -s 5)
    flash<<<dim3(8, 1, 32), 256, FLASH_SMEM>>>(qh, ql, kh, kl, vh, vl, rwhp, aoh, aol);
    // #7: output projection
    gemm_bs<<<dim3(4, 64, 1), 256, GEMM_SMEM>>>(
        aoh, aol, 512, 0, 0, woh, wol, 512, 0, 0,
        out, 512, 0, 0, 16, 1.0f);
}